// round 4
// baseline (speedup 1.0000x reference)
#include <cuda_runtime.h>
#include <math.h>

#define Bq   8
#define Nseq 512
#define Edim 256
#define Hh   8
#define DKd  32
#define SCALE 0.17677669529663687f   // 1/sqrt(32)

typedef unsigned long long ull;

// ---------------- scratch (device globals) ------------------------------------
__device__ float g_q[Bq*Hh*Nseq*DKd];
__device__ float g_k[Bq*Hh*Nseq*DKd];
__device__ float g_v[Bq*Hh*Nseq*DKd];
__device__ float g_x[Bq*Nseq*3*Edim];          // concat attn outputs (B,N,768)
__device__ float g_h1[Bq*Nseq*Edim];
__device__ float g_wcat[3*Edim*Edim];          // [Wo@Ws1_bar] stacked (768x256)
__device__ float g_bfull[Edim];
__device__ float g_zero[Edim];
__device__ float g_conv[(size_t)Bq*Hh*Nseq*Nseq];  // conv*SCALE with code in 2 LSBs

// ---------------- packed f32x2 helpers ----------------------------------------
__device__ __forceinline__ ull pk2(float lo, float hi) {
    ull r;
    asm("mov.b64 %0, {%1, %2};" : "=l"(r)
        : "r"(__float_as_uint(lo)), "r"(__float_as_uint(hi)));
    return r;
}
__device__ __forceinline__ void fma2(ull& d, ull a, ull b) {
    asm("fma.rn.f32x2 %0, %1, %2, %3;" : "=l"(d) : "l"(a), "l"(b), "l"(d));
}
__device__ __forceinline__ float2 upk(ull v) {
    unsigned int lo, hi;
    asm("mov.b64 {%0, %1}, %2;" : "=r"(lo), "=r"(hi) : "l"(v));
    return make_float2(__uint_as_float(lo), __uint_as_float(hi));
}

// ---------------- conv precompute: conv*SCALE + region code in LSBs -----------
// code: 0 = in-all-bars (forced or d<0.3), 1 = d<0.7, 2 = else, 3 = masked
__global__ __launch_bounds__(256) void conv_kernel(
    const float* __restrict__ dist, const int* __restrict__ mask,
    const float* __restrict__ cw1, const float* __restrict__ cb1,
    const float* __restrict__ cw2, const float* __restrict__ cb2,
    float* __restrict__ convp)
{
    __shared__ float scw1[8], scb1[8], scw2[64], scb2[8];
    int tid = threadIdx.x;
    if (tid < 8)  { scw1[tid] = cw1[tid]; scb1[tid] = cb1[tid]; scb2[tid] = cb2[tid]; }
    if (tid < 64) scw2[tid] = cw2[tid];
    __syncthreads();

    const int bi = blockIdx.x;           // b*512 + i
    const int b = bi >> 9, i = bi & 511;
    const float* drow = dist + (size_t)bi * Nseq;
    const int*   mrow = mask + (size_t)bi * Nseq;

    for (int j = tid; j < Nseq; j += 256) {
        float d = drow[j];
        int   m = mrow[j];
        float rl[8];
        #pragma unroll
        for (int t = 0; t < 8; t++)
            rl[t] = fmaxf(fmaf(d, scw1[t], scb1[t]), 0.f);
        unsigned code = (m == 0) ? 3u
                      : (i == 0 || j == 0) ? 0u
                      : (d < 0.3f) ? 0u : (d < 0.7f) ? 1u : 2u;
        #pragma unroll
        for (int h = 0; h < 8; h++) {
            float c = scb2[h];
            #pragma unroll
            for (int t = 0; t < 8; t++)
                c = fmaf(scw2[h*8 + t], rl[t], c);
            c *= SCALE;
            unsigned u = (__float_as_uint(c) & ~3u) | code;
            convp[(((size_t)(b*Hh + h) * Nseq + i) * Nseq) + j] = __uint_as_float(u);
        }
    }
}

// ---------------- 128x64-tile fp32x2 GEMM, double-buffered, z-batched ---------
__global__ __launch_bounds__(256) void gemm128(
    const float* __restrict__ A0, const float* __restrict__ A1, const float* __restrict__ A2,
    const float* __restrict__ W0, const float* __restrict__ W1, const float* __restrict__ W2,
    const float* __restrict__ bias0, const float* __restrict__ bias1, const float* __restrict__ bias2,
    float* __restrict__ C0, float* __restrict__ C1, float* __restrict__ C2,
    int Kd, int ldw, int ldc, int do_relu, int headsplit)
{
    const int z = blockIdx.z;
    const float* A    = (z == 0) ? A0 : (z == 1) ? A1 : A2;
    const float* W    = (z == 0) ? W0 : (z == 1) ? W1 : W2;
    const float* bias = (z == 0) ? bias0 : (z == 1) ? bias1 : bias2;
    float*       C    = (z == 0) ? C0 : (z == 1) ? C1 : C2;

    __shared__ float As[2][16][136];
    __shared__ float Ws[2][16][68];

    const int m0 = blockIdx.x << 7;
    const int n0 = blockIdx.y << 6;
    const int tid = threadIdx.x;
    const int tx = tid & 15, ty = tid >> 4;

    const int ar = tid >> 1;
    const int ac = (tid & 1) << 3;
    const int wr = tid >> 4;
    const int wc = (tid & 15) << 2;

    const float* Aptr = A + (size_t)(m0 + ar) * Kd + ac;
    const float* Wptr = W + (size_t)wr * ldw + n0 + wc;

    float4 a0p = *(const float4*)(Aptr);
    float4 a1p = *(const float4*)(Aptr + 4);
    float4 wp  = *(const float4*)(Wptr);

    ull acc[8][2] = {};

    As[0][ac+0][ar] = a0p.x; As[0][ac+1][ar] = a0p.y;
    As[0][ac+2][ar] = a0p.z; As[0][ac+3][ar] = a0p.w;
    As[0][ac+4][ar] = a1p.x; As[0][ac+5][ar] = a1p.y;
    As[0][ac+6][ar] = a1p.z; As[0][ac+7][ar] = a1p.w;
    *(float4*)&Ws[0][wr][wc] = wp;
    __syncthreads();

    const int nk = Kd >> 4;
    for (int kt = 0; kt < nk; kt++) {
        const int cur = kt & 1, nxt = cur ^ 1;
        if (kt + 1 < nk) {
            a0p = *(const float4*)(Aptr + (kt+1)*16);
            a1p = *(const float4*)(Aptr + (kt+1)*16 + 4);
            wp  = *(const float4*)(Wptr + (size_t)(kt+1)*16*ldw);
        }
        #pragma unroll
        for (int kk = 0; kk < 16; kk++) {
            float4 aA = *(const float4*)&As[cur][kk][ty << 3];
            float4 aB = *(const float4*)&As[cur][kk][(ty << 3) + 4];
            double2 wv = *(const double2*)&Ws[cur][kk][tx << 2];
            ull w01 = __double_as_longlong(wv.x);
            ull w23 = __double_as_longlong(wv.y);
            float a[8] = {aA.x, aA.y, aA.z, aA.w, aB.x, aB.y, aB.z, aB.w};
            #pragma unroll
            for (int i = 0; i < 8; i++) {
                ull ad = pk2(a[i], a[i]);
                fma2(acc[i][0], ad, w01);
                fma2(acc[i][1], ad, w23);
            }
        }
        if (kt + 1 < nk) {
            As[nxt][ac+0][ar] = a0p.x; As[nxt][ac+1][ar] = a0p.y;
            As[nxt][ac+2][ar] = a0p.z; As[nxt][ac+3][ar] = a0p.w;
            As[nxt][ac+4][ar] = a1p.x; As[nxt][ac+5][ar] = a1p.y;
            As[nxt][ac+6][ar] = a1p.z; As[nxt][ac+7][ar] = a1p.w;
            *(float4*)&Ws[nxt][wr][wc] = wp;
        }
        __syncthreads();
    }

    const int col0 = n0 + (tx << 2);
    float4 b4 = *(const float4*)&bias[col0];
    #pragma unroll
    for (int i = 0; i < 8; i++) {
        int m = m0 + (ty << 3) + i;
        float2 u0 = upk(acc[i][0]);
        float2 u1 = upk(acc[i][1]);
        float4 r;
        r.x = u0.x + b4.x; r.y = u0.y + b4.y;
        r.z = u1.x + b4.z; r.w = u1.y + b4.w;
        if (do_relu) {
            r.x = fmaxf(r.x, 0.f); r.y = fmaxf(r.y, 0.f);
            r.z = fmaxf(r.z, 0.f); r.w = fmaxf(r.w, 0.f);
        }
        if (headsplit) {
            int b = m >> 9, n = m & 511;
            int h = col0 >> 5, d = col0 & 31;
            *(float4*)&C[(((size_t)(b*Hh + h))*Nseq + n)*DKd + d] = r;
        } else {
            *(float4*)&C[(size_t)m * ldc + col0] = r;
        }
    }
}

// ---------------- bias fold ---------------------------------------------------
__global__ void bias_fold(const float* __restrict__ bo, const float* __restrict__ Ws1,
                          const float* __restrict__ bs1, float* __restrict__ bfull)
{
    int n = threadIdx.x;
    float s = bs1[n];
    #pragma unroll 8
    for (int r = 0; r < 3*Edim; r++)
        s += bo[r & (Edim-1)] * Ws1[(size_t)r * Edim + n];
    bfull[n] = s;
}

// ---------------- fused multi-bar attention -----------------------------------
// dynamic smem layout (bytes):
//   QsD  [64][32] ull     @ 0        (16384)
//   Kst  [32][68] float   @ 16384    (8704)
//   Vt   [32][68] float   @ 25088    (8704)
//   E2   [64][68] float   @ 33792    (17408)
//   E1   [64][68] float   @ 51200    (17408)
//   E0   [64][68] float   @ 68608    (17408)   total 86016
#define ATTN_SMEM 86016

__global__ __launch_bounds__(256) void attn_kernel(
    const float* __restrict__ Q, const float* __restrict__ K, const float* __restrict__ V,
    const float* __restrict__ convp, float* __restrict__ xcat)
{
    extern __shared__ char smraw[];
    ull   (*QsD)[32] = (ull(*)[32])(smraw);
    float (*Kst)[68] = (float(*)[68])(smraw + 16384);
    float (*Vt)[68]  = (float(*)[68])(smraw + 25088);
    float (*E2)[68]  = (float(*)[68])(smraw + 33792);
    float (*E1)[68]  = (float(*)[68])(smraw + 51200);
    float (*E0)[68]  = (float(*)[68])(smraw + 68608);

    const int qt = blockIdx.x;
    const int bh = blockIdx.y;
    const int b = bh >> 3, h = bh & 7;
    const int q0 = qt << 6;
    const int tid = threadIdx.x;
    const int tx = tid & 15, ty = tid >> 4;

    const size_t headbase = ((size_t)bh) * Nseq * DKd;

    // Q tile, pre-duplicated into f32x2 pairs
    const float* Qb = Q + headbase + (size_t)q0 * DKd;
    for (int t = tid; t < 64*32; t += 256) {
        float v = Qb[t];
        QsD[t >> 5][t & 31] = pk2(v, v);
    }

    // accumulators: o2[bar][i][0] -> d=tx,  o2[bar][i][1] -> d=tx+16
    ull o2[3][4][2] = {};
    float lsum[3][4] = {};

    const float* cbase = convp + ((size_t)bh * Nseq + q0) * Nseq;

    for (int kt = 0; kt < 8; kt++) {
        const int k0 = kt << 6;
        const float* Kb = K + headbase + (size_t)k0 * DKd;
        const float* Vb = V + headbase + (size_t)k0 * DKd;
        __syncthreads();
        for (int t = tid; t < 64*32; t += 256) {
            Kst[t & 31][t >> 5] = Kb[t];
            Vt[t & 31][t >> 5]  = Vb[t];
        }
        __syncthreads();

        // ---- S = Q K^T, packed j-pairs; zero repack ----
        ull s2[4][2] = {};
        #pragma unroll
        for (int d = 0; d < 32; d++) {
            double2 kd = *(const double2*)&Kst[d][tx << 2];
            ull k01 = __double_as_longlong(kd.x);
            ull k23 = __double_as_longlong(kd.y);
            #pragma unroll
            for (int i = 0; i < 4; i++) {
                ull ad = QsD[ty*4 + i][d];
                fma2(s2[i][0], ad, k01);
                fma2(s2[i][1], ad, k23);
            }
        }

        // ---- conv(packed code) -> e2/e1/e0, staged once ----
        #pragma unroll
        for (int i = 0; i < 4; i++) {
            const int row = ty*4 + i;
            float4 c4 = *(const float4*)&cbase[(size_t)row * Nseq + k0 + (tx << 2)];
            float2 su0 = upk(s2[i][0]);
            float2 su1 = upk(s2[i][1]);
            float sj[4] = {su0.x, su0.y, su1.x, su1.y};
            float cj[4] = {c4.x, c4.y, c4.z, c4.w};
            float e2v[4], e1v[4], e0v[4];
            float l2 = 0.f, l1 = 0.f, l0 = 0.f;
            #pragma unroll
            for (int j = 0; j < 4; j++) {
                unsigned u = __float_as_uint(cj[j]);
                unsigned code = u & 3u;
                float ev = __expf(sj[j] * cj[j]);
                ev = (code == 3u) ? 0.f : ev;
                float ev1 = (code < 2u) ? ev : 0.f;
                float ev0 = (code == 0u) ? ev : 0.f;
                e2v[j] = ev; e1v[j] = ev1; e0v[j] = ev0;
                l2 += ev; l1 += ev1; l0 += ev0;
            }
            lsum[2][i] += l2; lsum[1][i] += l1; lsum[0][i] += l0;
            *(float4*)&E2[row][tx << 2] = make_float4(e2v[0], e2v[1], e2v[2], e2v[3]);
            *(float4*)&E1[row][tx << 2] = make_float4(e1v[0], e1v[1], e1v[2], e1v[3]);
            *(float4*)&E0[row][tx << 2] = make_float4(e0v[0], e0v[1], e0v[2], e0v[3]);
        }
        __syncthreads();

        // ---- PV: all bars, pure packed FMA, zero ALU ----
        #pragma unroll
        for (int jg = 0; jg < 16; jg++) {
            double2 vad = *(const double2*)&Vt[tx][jg << 2];
            double2 vbd = *(const double2*)&Vt[tx + 16][jg << 2];
            ull va01 = __double_as_longlong(vad.x);
            ull va23 = __double_as_longlong(vad.y);
            ull vb01 = __double_as_longlong(vbd.x);
            ull vb23 = __double_as_longlong(vbd.y);
            #pragma unroll
            for (int i = 0; i < 4; i++) {
                const int row = ty*4 + i;
                double2 e2d = *(const double2*)&E2[row][jg << 2];
                double2 e1d = *(const double2*)&E1[row][jg << 2];
                double2 e0d = *(const double2*)&E0[row][jg << 2];
                ull e201 = __double_as_longlong(e2d.x), e223 = __double_as_longlong(e2d.y);
                ull e101 = __double_as_longlong(e1d.x), e123 = __double_as_longlong(e1d.y);
                ull e001 = __double_as_longlong(e0d.x), e023 = __double_as_longlong(e0d.y);
                fma2(o2[2][i][0], e201, va01); fma2(o2[2][i][0], e223, va23);
                fma2(o2[2][i][1], e201, vb01); fma2(o2[2][i][1], e223, vb23);
                fma2(o2[1][i][0], e101, va01); fma2(o2[1][i][0], e123, va23);
                fma2(o2[1][i][1], e101, vb01); fma2(o2[1][i][1], e123, vb23);
                fma2(o2[0][i][0], e001, va01); fma2(o2[0][i][0], e023, va23);
                fma2(o2[0][i][1], e001, vb01); fma2(o2[0][i][1], e023, vb23);
            }
        }
    }

    // ---- reduce row sums over 16 tx lanes (within warp halves) ----
    #pragma unroll
    for (int bar = 0; bar < 3; bar++)
        #pragma unroll
        for (int i = 0; i < 4; i++) {
            float v = lsum[bar][i];
            #pragma unroll
            for (int off = 1; off < 16; off <<= 1)
                v += __shfl_xor_sync(0xffffffffu, v, off);
            lsum[bar][i] = v;
        }

    // ---- normalize + write concat layout (B,N, bar*256 + h*32 + d) ----
    #pragma unroll
    for (int bar = 0; bar < 3; bar++)
        #pragma unroll
        for (int i = 0; i < 4; i++) {
            int qi = q0 + ty*4 + i;
            float rl = 1.f / lsum[bar][i];
            float2 u0 = upk(o2[bar][i][0]);
            float2 u1 = upk(o2[bar][i][1]);
            size_t base = ((size_t)b*Nseq + qi) * (3*Edim) + bar*Edim + h*DKd;
            xcat[base + tx]      = (u0.x + u0.y) * rl;
            xcat[base + tx + 16] = (u1.x + u1.y) * rl;
        }
}

// ---------------- host launcher ----------------------------------------------
extern "C" void kernel_launch(void* const* d_in, const int* in_sizes, int n_in,
                              void* d_out, int out_size)
{
    const float* query = (const float*)d_in[0];
    const float* key   = (const float*)d_in[1];
    const float* value = (const float*)d_in[2];
    const float* dist  = (const float*)d_in[3];
    const int*   mask  = (const int*)d_in[4];
    const float* Wq = (const float*)d_in[5];
    const float* bq = (const float*)d_in[6];
    const float* Wk = (const float*)d_in[7];
    const float* bk = (const float*)d_in[8];
    const float* Wv = (const float*)d_in[9];
    const float* bv = (const float*)d_in[10];
    const float* Wo = (const float*)d_in[11];
    const float* bo = (const float*)d_in[12];
    const float* cw1 = (const float*)d_in[13];
    const float* cb1 = (const float*)d_in[14];
    const float* cw2 = (const float*)d_in[15];
    const float* cb2 = (const float*)d_in[16];
    const float* Ws1 = (const float*)d_in[17];
    const float* bs1 = (const float*)d_in[18];
    const float* Ws2 = (const float*)d_in[19];
    const float* bs2 = (const float*)d_in[20];
    float* out = (float*)d_out;

    float *q_p, *k_p, *v_p, *x_p, *h1_p, *wcat_p, *bfull_p, *zero_p, *conv_p;
    cudaGetSymbolAddress((void**)&q_p,    g_q);
    cudaGetSymbolAddress((void**)&k_p,    g_k);
    cudaGetSymbolAddress((void**)&v_p,    g_v);
    cudaGetSymbolAddress((void**)&x_p,    g_x);
    cudaGetSymbolAddress((void**)&h1_p,   g_h1);
    cudaGetSymbolAddress((void**)&wcat_p, g_wcat);
    cudaGetSymbolAddress((void**)&bfull_p,g_bfull);
    cudaGetSymbolAddress((void**)&zero_p, g_zero);
    cudaGetSymbolAddress((void**)&conv_p, g_conv);

    static int smem_set = 0;
    if (!smem_set) {
        cudaFuncSetAttribute(attn_kernel,
                             cudaFuncAttributeMaxDynamicSharedMemorySize, ATTN_SMEM);
        smem_set = 1;
    }

    const int M = Bq * Nseq;          // 4096
    dim3 blk(256);

    // conv precompute (runs alongside nothing else, but cheap)
    conv_kernel<<<Bq * Nseq, blk>>>(dist, mask, cw1, cb1, cw2, cb2, conv_p);

    // Wcat = [Wo @ Ws1_bar] and folded bias
    {
        dim3 grid(Edim / 128, Edim / 64, 3);
        gemm128<<<grid, blk>>>(Wo, Wo, Wo,
                               Ws1, Ws1 + Edim*Edim, Ws1 + 2*Edim*Edim,
                               zero_p, zero_p, zero_p,
                               wcat_p, wcat_p + Edim*Edim, wcat_p + 2*Edim*Edim,
                               Edim, Edim, Edim, 0, 0);
        bias_fold<<<1, Edim>>>(bo, Ws1, bs1, bfull_p);
    }

    // QKV projections -> (B,H,N,DK), z-batched
    {
        dim3 grid(M / 128, Edim / 64, 3);
        gemm128<<<grid, blk>>>(query, key, value,
                               Wq, Wk, Wv,
                               bq, bk, bv,
                               q_p, k_p, v_p,
                               Edim, Edim, 0, 0, 1);
    }

    // fused multi-bar attention -> concat g_x (B,N,768)
    {
        dim3 grid(Nseq / 64, Bq * Hh);
        attn_kernel<<<grid, blk, ATTN_SMEM>>>(q_p, k_p, v_p, conv_p, x_p);
    }

    // h1 = relu(xcat @ Wcat + bfull)
    {
        dim3 grid(M / 128, Edim / 64, 1);
        gemm128<<<grid, blk>>>(x_p, x_p, x_p, wcat_p, wcat_p, wcat_p,
                               bfull_p, bfull_p, bfull_p,
                               h1_p, h1_p, h1_p, 3*Edim, Edim, Edim, 1, 0);
    }

    // out = h1 @ Ws2 + bs2
    {
        dim3 grid(M / 128, Edim / 64, 1);
        gemm128<<<grid, blk>>>(h1_p, h1_p, h1_p, Ws2, Ws2, Ws2, bs2, bs2, bs2,
                               out, out, out, Edim, Edim, Edim, 0, 0);
    }
}

// round 6
// speedup vs baseline: 1.2347x; 1.2347x over previous
#include <cuda_runtime.h>
#include <math.h>

#define Bq   8
#define Nseq 512
#define Edim 256
#define Hh   8
#define DKd  32
#define SCALE 0.17677669529663687f   // 1/sqrt(32)

typedef unsigned long long ull;

// ---------------- scratch (device globals) ------------------------------------
__device__ float g_q[Bq*Hh*Nseq*DKd];
__device__ float g_k[Bq*Hh*Nseq*DKd];
__device__ float g_v[Bq*Hh*Nseq*DKd];
__device__ float g_x[Bq*Nseq*3*Edim];          // concat attn outputs (B,N,768)
__device__ float g_h1[Bq*Nseq*Edim];
__device__ float g_wcat[3*Edim*Edim];          // [Wo@Ws1_bar] stacked (768x256)
__device__ float g_bfull[Edim];
__device__ float g_zero[Edim];
__device__ float g_conv[(size_t)Bq*Hh*Nseq*Nseq];  // conv*SCALE with code in 2 LSBs

// ---------------- packed f32x2 helpers (GEMM) ----------------------------------
__device__ __forceinline__ ull pk2(float lo, float hi) {
    ull r;
    asm("mov.b64 %0, {%1, %2};" : "=l"(r)
        : "r"(__float_as_uint(lo)), "r"(__float_as_uint(hi)));
    return r;
}
__device__ __forceinline__ void fma2(ull& d, ull a, ull b) {
    asm("fma.rn.f32x2 %0, %1, %2, %3;" : "=l"(d) : "l"(a), "l"(b), "l"(d));
}
__device__ __forceinline__ float2 upk(ull v) {
    unsigned int lo, hi;
    asm("mov.b64 {%0, %1}, %2;" : "=r"(lo), "=r"(hi) : "l"(v));
    return make_float2(__uint_as_float(lo), __uint_as_float(hi));
}

// ---------------- tf32 helpers --------------------------------------------------
__device__ __forceinline__ float tf32_of(float f) {
    unsigned u;
    asm("cvt.rna.tf32.f32 %0, %1;" : "=r"(u) : "f"(f));
    return __uint_as_float(u);
}
__device__ __forceinline__ void mma_tf32(float* d, const unsigned* a,
                                         unsigned b0, unsigned b1) {
    asm volatile(
        "mma.sync.aligned.m16n8k8.row.col.f32.tf32.tf32.f32 "
        "{%0,%1,%2,%3}, {%4,%5,%6,%7}, {%8,%9}, {%0,%1,%2,%3};"
        : "+f"(d[0]), "+f"(d[1]), "+f"(d[2]), "+f"(d[3])
        : "r"(a[0]), "r"(a[1]), "r"(a[2]), "r"(a[3]), "r"(b0), "r"(b1));
}

// fast exp for tiny arguments (scores ~1e-3); exact-0 preserved; rare fallback
__device__ __forceinline__ float fexp(float x) {
    float e = fmaf(x, 0.041666667f, 0.16666667f);
    e = fmaf(e, x, 0.5f);
    e = fmaf(e, x, 1.0f);
    e = fmaf(e, x, 1.0f);
    if (fabsf(x) > 0.25f) e = __expf(x);
    return e;
}

// ---------------- conv precompute: conv*SCALE + region code in LSBs -----------
// code: 0 = in-all-bars (forced or d<0.3), 1 = d<0.7, 2 = else, 3 = masked
__global__ __launch_bounds__(256) void conv_kernel(
    const float* __restrict__ dist, const int* __restrict__ mask,
    const float* __restrict__ cw1, const float* __restrict__ cb1,
    const float* __restrict__ cw2, const float* __restrict__ cb2,
    float* __restrict__ convp)
{
    __shared__ float scw1[8], scb1[8], scw2[64], scb2[8];
    int tid = threadIdx.x;
    if (tid < 8)  { scw1[tid] = cw1[tid]; scb1[tid] = cb1[tid]; scb2[tid] = cb2[tid]; }
    if (tid < 64) scw2[tid] = cw2[tid];
    __syncthreads();

    const int bi = blockIdx.x;           // b*512 + i
    const int b = bi >> 9, i = bi & 511;
    const float* drow = dist + (size_t)bi * Nseq;
    const int*   mrow = mask + (size_t)bi * Nseq;

    for (int j = tid; j < Nseq; j += 256) {
        float d = drow[j];
        int   m = mrow[j];
        float rl[8];
        #pragma unroll
        for (int t = 0; t < 8; t++)
            rl[t] = fmaxf(fmaf(d, scw1[t], scb1[t]), 0.f);
        unsigned code = (m == 0) ? 3u
                      : (i == 0 || j == 0) ? 0u
                      : (d < 0.3f) ? 0u : (d < 0.7f) ? 1u : 2u;
        #pragma unroll
        for (int h = 0; h < 8; h++) {
            float c = scb2[h];
            #pragma unroll
            for (int t = 0; t < 8; t++)
                c = fmaf(scw2[h*8 + t], rl[t], c);
            c *= SCALE;
            unsigned u = (__float_as_uint(c) & ~3u) | code;
            convp[(((size_t)(b*Hh + h) * Nseq + i) * Nseq) + j] = __uint_as_float(u);
        }
    }
}

// ---------------- 128x64-tile fp32x2 GEMM, double-buffered, z-batched ---------
__global__ __launch_bounds__(256) void gemm128(
    const float* __restrict__ A0, const float* __restrict__ A1, const float* __restrict__ A2,
    const float* __restrict__ W0, const float* __restrict__ W1, const float* __restrict__ W2,
    const float* __restrict__ bias0, const float* __restrict__ bias1, const float* __restrict__ bias2,
    float* __restrict__ C0, float* __restrict__ C1, float* __restrict__ C2,
    int Kd, int ldw, int ldc, int do_relu, int headsplit)
{
    const int z = blockIdx.z;
    const float* A    = (z == 0) ? A0 : (z == 1) ? A1 : A2;
    const float* W    = (z == 0) ? W0 : (z == 1) ? W1 : W2;
    const float* bias = (z == 0) ? bias0 : (z == 1) ? bias1 : bias2;
    float*       C    = (z == 0) ? C0 : (z == 1) ? C1 : C2;

    __shared__ float As[2][16][136];
    __shared__ float Ws[2][16][68];

    const int m0 = blockIdx.x << 7;
    const int n0 = blockIdx.y << 6;
    const int tid = threadIdx.x;
    const int tx = tid & 15, ty = tid >> 4;

    const int ar = tid >> 1;
    const int ac = (tid & 1) << 3;
    const int wr = tid >> 4;
    const int wc = (tid & 15) << 2;

    const float* Aptr = A + (size_t)(m0 + ar) * Kd + ac;
    const float* Wptr = W + (size_t)wr * ldw + n0 + wc;

    float4 a0p = *(const float4*)(Aptr);
    float4 a1p = *(const float4*)(Aptr + 4);
    float4 wp  = *(const float4*)(Wptr);

    ull acc[8][2] = {};

    As[0][ac+0][ar] = a0p.x; As[0][ac+1][ar] = a0p.y;
    As[0][ac+2][ar] = a0p.z; As[0][ac+3][ar] = a0p.w;
    As[0][ac+4][ar] = a1p.x; As[0][ac+5][ar] = a1p.y;
    As[0][ac+6][ar] = a1p.z; As[0][ac+7][ar] = a1p.w;
    *(float4*)&Ws[0][wr][wc] = wp;
    __syncthreads();

    const int nk = Kd >> 4;
    for (int kt = 0; kt < nk; kt++) {
        const int cur = kt & 1, nxt = cur ^ 1;
        if (kt + 1 < nk) {
            a0p = *(const float4*)(Aptr + (kt+1)*16);
            a1p = *(const float4*)(Aptr + (kt+1)*16 + 4);
            wp  = *(const float4*)(Wptr + (size_t)(kt+1)*16*ldw);
        }
        #pragma unroll
        for (int kk = 0; kk < 16; kk++) {
            float4 aA = *(const float4*)&As[cur][kk][ty << 3];
            float4 aB = *(const float4*)&As[cur][kk][(ty << 3) + 4];
            double2 wv = *(const double2*)&Ws[cur][kk][tx << 2];
            ull w01 = __double_as_longlong(wv.x);
            ull w23 = __double_as_longlong(wv.y);
            float a[8] = {aA.x, aA.y, aA.z, aA.w, aB.x, aB.y, aB.z, aB.w};
            #pragma unroll
            for (int i = 0; i < 8; i++) {
                ull ad = pk2(a[i], a[i]);
                fma2(acc[i][0], ad, w01);
                fma2(acc[i][1], ad, w23);
            }
        }
        if (kt + 1 < nk) {
            As[nxt][ac+0][ar] = a0p.x; As[nxt][ac+1][ar] = a0p.y;
            As[nxt][ac+2][ar] = a0p.z; As[nxt][ac+3][ar] = a0p.w;
            As[nxt][ac+4][ar] = a1p.x; As[nxt][ac+5][ar] = a1p.y;
            As[nxt][ac+6][ar] = a1p.z; As[nxt][ac+7][ar] = a1p.w;
            *(float4*)&Ws[nxt][wr][wc] = wp;
        }
        __syncthreads();
    }

    const int col0 = n0 + (tx << 2);
    float4 b4 = *(const float4*)&bias[col0];
    #pragma unroll
    for (int i = 0; i < 8; i++) {
        int m = m0 + (ty << 3) + i;
        float2 u0 = upk(acc[i][0]);
        float2 u1 = upk(acc[i][1]);
        float4 r;
        r.x = u0.x + b4.x; r.y = u0.y + b4.y;
        r.z = u1.x + b4.z; r.w = u1.y + b4.w;
        if (do_relu) {
            r.x = fmaxf(r.x, 0.f); r.y = fmaxf(r.y, 0.f);
            r.z = fmaxf(r.z, 0.f); r.w = fmaxf(r.w, 0.f);
        }
        if (headsplit) {
            int b = m >> 9, n = m & 511;
            int h = col0 >> 5, d = col0 & 31;
            *(float4*)&C[(((size_t)(b*Hh + h))*Nseq + n)*DKd + d] = r;
        } else {
            *(float4*)&C[(size_t)m * ldc + col0] = r;
        }
    }
}

// ---------------- bias fold ---------------------------------------------------
__global__ void bias_fold(const float* __restrict__ bo, const float* __restrict__ Ws1,
                          const float* __restrict__ bs1, float* __restrict__ bfull)
{
    int n = threadIdx.x;
    float s = bs1[n];
    #pragma unroll 8
    for (int r = 0; r < 3*Edim; r++)
        s += bo[r & (Edim-1)] * Ws1[(size_t)r * Edim + n];
    bfull[n] = s;
}

// ---------------- tf32 mma attention ------------------------------------------
// CTA = (qtile 64 rows, b*H+h). 128 threads / 4 warps; warp owns 16 q-rows.
// dynamic smem (float offsets):
//   Qs [64][36] @0        (2304)   32 d-cols used
//   Ks [64][36] @2304     (2304)   32 d-cols used
//   Vt [32][68] @4608     (2176)   d-major, 64 j-cols
//   E0 [64][68] @6784     (4352)
//   E1 [64][68] @11136    (4352)
//   E2 [64][68] @15488    (4352)   total 19840 floats = 79360 bytes
#define ATTN_SMEM 79360

__global__ __launch_bounds__(128) void attn_mma(
    const float* __restrict__ Q, const float* __restrict__ K, const float* __restrict__ V,
    const float* __restrict__ convp, float* __restrict__ xcat)
{
    extern __shared__ float sm[];
    float (*Qs)[36] = (float(*)[36])(sm);
    float (*Ks)[36] = (float(*)[36])(sm + 2304);
    float (*Vt)[68] = (float(*)[68])(sm + 4608);
    float (*E0)[68] = (float(*)[68])(sm + 6784);
    float (*E1)[68] = (float(*)[68])(sm + 11136);
    float (*E2)[68] = (float(*)[68])(sm + 15488);

    const int qt = blockIdx.x;
    const int bh = blockIdx.y;
    const int b = bh >> 3, h = bh & 7;
    const int q0 = qt << 6;
    const int tid = threadIdx.x;
    const int warp = tid >> 5, lane = tid & 31;
    const int g = lane >> 2, r4 = lane & 3;
    const int mrow = warp << 4;                 // warp's q-stripe base (0,16,32,48)

    const size_t headbase = (size_t)bh * Nseq * DKd;

    // ---- stage Q (cvt to tf32) ----
    const float* Qb = Q + headbase + (size_t)q0 * DKd;
    for (int t = tid; t < 64*32; t += 128)
        Qs[t >> 5][t & 31] = tf32_of(Qb[t]);
    __syncthreads();

    // ---- load Q A-fragments once: 4 ksteps x 4 regs ----
    unsigned qa[4][4];
    #pragma unroll
    for (int ks = 0; ks < 4; ks++) {
        qa[ks][0] = __float_as_uint(Qs[mrow + g    ][ks*8 + r4    ]);
        qa[ks][1] = __float_as_uint(Qs[mrow + g + 8][ks*8 + r4    ]);
        qa[ks][2] = __float_as_uint(Qs[mrow + g    ][ks*8 + r4 + 4]);
        qa[ks][3] = __float_as_uint(Qs[mrow + g + 8][ks*8 + r4 + 4]);
    }

    float o[3][4][4] = {};       // [bar][d-ntile][frag reg]
    float lsum[3][2] = {};       // [bar][row g / row g+8]

    const float* cbase = convp + ((size_t)bh * Nseq + q0 + mrow) * Nseq;

    for (int kt = 0; kt < 8; kt++) {
        const int k0 = kt << 6;
        const float* Kb = K + headbase + (size_t)k0 * DKd;
        const float* Vb = V + headbase + (size_t)k0 * DKd;
        __syncthreads();                        // prev PV done
        for (int t = tid; t < 64*32; t += 128) {
            Ks[t >> 5][t & 31] = tf32_of(Kb[t]);
            Vt[t & 31][t >> 5] = tf32_of(Vb[t]);
        }
        __syncthreads();

        // ---- S = Q K^T : 8 n-tiles (key), 4 k-steps (d) ----
        float s[8][4];
        #pragma unroll
        for (int nt = 0; nt < 8; nt++)
            #pragma unroll
            for (int r = 0; r < 4; r++) s[nt][r] = 0.f;
        #pragma unroll
        for (int ks = 0; ks < 4; ks++) {
            #pragma unroll
            for (int nt = 0; nt < 8; nt++) {
                unsigned b0 = __float_as_uint(Ks[nt*8 + g][ks*8 + r4    ]);
                unsigned b1 = __float_as_uint(Ks[nt*8 + g][ks*8 + r4 + 4]);
                mma_tf32(s[nt], qa[ks], b0, b1);
            }
        }

        // ---- exp once, split by bar code, stage E0/E1/E2 (tf32) ----
        #pragma unroll
        for (int nt = 0; nt < 8; nt++) {
            #pragma unroll
            for (int rr = 0; rr < 2; rr++) {
                const int trow = mrow + g + rr*8;        // tile row
                const float2 c2 = *(const float2*)&cbase[(size_t)(g + rr*8) * Nseq
                                                         + k0 + nt*8 + 2*r4];
                float sx = s[nt][rr*2 + 0], sy = s[nt][rr*2 + 1];
                unsigned cx = __float_as_uint(c2.x) & 3u;
                unsigned cy = __float_as_uint(c2.y) & 3u;
                float ex = fexp(sx * c2.x);
                float ey = fexp(sy * c2.y);
                ex = (cx == 3u) ? 0.f : ex;
                ey = (cy == 3u) ? 0.f : ey;
                float ex1 = (cx < 2u) ? ex : 0.f;
                float ey1 = (cy < 2u) ? ey : 0.f;
                float ex0 = (cx == 0u) ? ex : 0.f;
                float ey0 = (cy == 0u) ? ey : 0.f;
                lsum[2][rr] += ex + ey;
                lsum[1][rr] += ex1 + ey1;
                lsum[0][rr] += ex0 + ey0;
                const int col = nt*8 + 2*r4;
                *(float2*)&E2[trow][col] = make_float2(tf32_of(ex),  tf32_of(ey));
                *(float2*)&E1[trow][col] = make_float2(tf32_of(ex1), tf32_of(ey1));
                *(float2*)&E0[trow][col] = make_float2(tf32_of(ex0), tf32_of(ey0));
            }
        }
        __syncthreads();

        // ---- PV: O_bar += E_bar @ V ; 8 key-steps, 4 d-ntiles, 3 bars ----
        #pragma unroll
        for (int ks = 0; ks < 8; ks++) {
            unsigned vb[4][2];
            #pragma unroll
            for (int nt = 0; nt < 4; nt++) {
                vb[nt][0] = __float_as_uint(Vt[nt*8 + g][ks*8 + r4    ]);
                vb[nt][1] = __float_as_uint(Vt[nt*8 + g][ks*8 + r4 + 4]);
            }
            unsigned a[4];
            // bar 2
            a[0] = __float_as_uint(E2[mrow + g    ][ks*8 + r4    ]);
            a[1] = __float_as_uint(E2[mrow + g + 8][ks*8 + r4    ]);
            a[2] = __float_as_uint(E2[mrow + g    ][ks*8 + r4 + 4]);
            a[3] = __float_as_uint(E2[mrow + g + 8][ks*8 + r4 + 4]);
            #pragma unroll
            for (int nt = 0; nt < 4; nt++) mma_tf32(o[2][nt], a, vb[nt][0], vb[nt][1]);
            // bar 1
            a[0] = __float_as_uint(E1[mrow + g    ][ks*8 + r4    ]);
            a[1] = __float_as_uint(E1[mrow + g + 8][ks*8 + r4    ]);
            a[2] = __float_as_uint(E1[mrow + g    ][ks*8 + r4 + 4]);
            a[3] = __float_as_uint(E1[mrow + g + 8][ks*8 + r4 + 4]);
            #pragma unroll
            for (int nt = 0; nt < 4; nt++) mma_tf32(o[1][nt], a, vb[nt][0], vb[nt][1]);
            // bar 0
            a[0] = __float_as_uint(E0[mrow + g    ][ks*8 + r4    ]);
            a[1] = __float_as_uint(E0[mrow + g + 8][ks*8 + r4    ]);
            a[2] = __float_as_uint(E0[mrow + g    ][ks*8 + r4 + 4]);
            a[3] = __float_as_uint(E0[mrow + g + 8][ks*8 + r4 + 4]);
            #pragma unroll
            for (int nt = 0; nt < 4; nt++) mma_tf32(o[0][nt], a, vb[nt][0], vb[nt][1]);
        }
    }

    // ---- reduce lsum across the 4 lanes of each row-quad ----
    #pragma unroll
    for (int bar = 0; bar < 3; bar++)
        #pragma unroll
        for (int rr = 0; rr < 2; rr++) {
            float v = lsum[bar][rr];
            v += __shfl_xor_sync(0xffffffffu, v, 1);
            v += __shfl_xor_sync(0xffffffffu, v, 2);
            lsum[bar][rr] = v;
        }

    // ---- normalize + write concat layout (B,N, bar*256 + h*32 + d) ----
    const int rowA = q0 + mrow + g;
    const int rowB = rowA + 8;
    #pragma unroll
    for (int bar = 0; bar < 3; bar++) {
        const float rlA = 1.f / lsum[bar][0];
        const float rlB = 1.f / lsum[bar][1];
        #pragma unroll
        for (int nt = 0; nt < 4; nt++) {
            const int col = bar*Edim + h*DKd + nt*8 + 2*r4;
            size_t baseA = ((size_t)b*Nseq + rowA) * (3*Edim) + col;
            size_t baseB = ((size_t)b*Nseq + rowB) * (3*Edim) + col;
            *(float2*)&xcat[baseA] = make_float2(o[bar][nt][0]*rlA, o[bar][nt][1]*rlA);
            *(float2*)&xcat[baseB] = make_float2(o[bar][nt][2]*rlB, o[bar][nt][3]*rlB);
        }
    }
}

// ---------------- host launcher ----------------------------------------------
extern "C" void kernel_launch(void* const* d_in, const int* in_sizes, int n_in,
                              void* d_out, int out_size)
{
    const float* query = (const float*)d_in[0];
    const float* key   = (const float*)d_in[1];
    const float* value = (const float*)d_in[2];
    const float* dist  = (const float*)d_in[3];
    const int*   mask  = (const int*)d_in[4];
    const float* Wq = (const float*)d_in[5];
    const float* bq = (const float*)d_in[6];
    const float* Wk = (const float*)d_in[7];
    const float* bk = (const float*)d_in[8];
    const float* Wv = (const float*)d_in[9];
    const float* bv = (const float*)d_in[10];
    const float* Wo = (const float*)d_in[11];
    const float* bo = (const float*)d_in[12];
    const float* cw1 = (const float*)d_in[13];
    const float* cb1 = (const float*)d_in[14];
    const float* cw2 = (const float*)d_in[15];
    const float* cb2 = (const float*)d_in[16];
    const float* Ws1 = (const float*)d_in[17];
    const float* bs1 = (const float*)d_in[18];
    const float* Ws2 = (const float*)d_in[19];
    const float* bs2 = (const float*)d_in[20];
    float* out = (float*)d_out;

    float *q_p, *k_p, *v_p, *x_p, *h1_p, *wcat_p, *bfull_p, *zero_p, *conv_p;
    cudaGetSymbolAddress((void**)&q_p,    g_q);
    cudaGetSymbolAddress((void**)&k_p,    g_k);
    cudaGetSymbolAddress((void**)&v_p,    g_v);
    cudaGetSymbolAddress((void**)&x_p,    g_x);
    cudaGetSymbolAddress((void**)&h1_p,   g_h1);
    cudaGetSymbolAddress((void**)&wcat_p, g_wcat);
    cudaGetSymbolAddress((void**)&bfull_p,g_bfull);
    cudaGetSymbolAddress((void**)&zero_p, g_zero);
    cudaGetSymbolAddress((void**)&conv_p, g_conv);

    cudaFuncSetAttribute(attn_mma,
                         cudaFuncAttributeMaxDynamicSharedMemorySize, ATTN_SMEM);

    const int M = Bq * Nseq;          // 4096
    dim3 blk(256);

    // conv precompute
    conv_kernel<<<Bq * Nseq, blk>>>(dist, mask, cw1, cb1, cw2, cb2, conv_p);

    // Wcat = [Wo @ Ws1_bar] and folded bias
    {
        dim3 grid(Edim / 128, Edim / 64, 3);
        gemm128<<<grid, blk>>>(Wo, Wo, Wo,
                               Ws1, Ws1 + Edim*Edim, Ws1 + 2*Edim*Edim,
                               zero_p, zero_p, zero_p,
                               wcat_p, wcat_p + Edim*Edim, wcat_p + 2*Edim*Edim,
                               Edim, Edim, Edim, 0, 0);
        bias_fold<<<1, Edim>>>(bo, Ws1, bs1, bfull_p);
    }

    // QKV projections -> (B,H,N,DK), z-batched
    {
        dim3 grid(M / 128, Edim / 64, 3);
        gemm128<<<grid, blk>>>(query, key, value,
                               Wq, Wk, Wv,
                               bq, bk, bv,
                               q_p, k_p, v_p,
                               Edim, Edim, 0, 0, 1);
    }

    // tf32 mma attention -> concat g_x (B,N,768)
    {
        dim3 grid(Nseq / 64, Bq * Hh);
        attn_mma<<<grid, 128, ATTN_SMEM>>>(q_p, k_p, v_p, conv_p, x_p);
    }

    // h1 = relu(xcat @ Wcat + bfull)
    {
        dim3 grid(M / 128, Edim / 64, 1);
        gemm128<<<grid, blk>>>(x_p, x_p, x_p, wcat_p, wcat_p, wcat_p,
                               bfull_p, bfull_p, bfull_p,
                               h1_p, h1_p, h1_p, 3*Edim, Edim, Edim, 1, 0);
    }

    // out = h1 @ Ws2 + bs2
    {
        dim3 grid(M / 128, Edim / 64, 1);
        gemm128<<<grid, blk>>>(h1_p, h1_p, h1_p, Ws2, Ws2, Ws2, bs2, bs2, bs2,
                               out, out, out, Edim, Edim, Edim, 0, 0);
    }
}

// round 7
// speedup vs baseline: 1.2893x; 1.0442x over previous
#include <cuda_runtime.h>
#include <math.h>

#define Bq   8
#define Nseq 512
#define Edim 256
#define Hh   8
#define DKd  32
#define SCALE 0.17677669529663687f   // 1/sqrt(32)

typedef unsigned long long ull;

// ---------------- scratch (device globals) ------------------------------------
__device__ float g_q[Bq*Hh*Nseq*DKd];
__device__ float g_k[Bq*Hh*Nseq*DKd];
__device__ float g_v[Bq*Hh*Nseq*DKd];
__device__ float g_x[Bq*Nseq*3*Edim];          // concat attn outputs (B,N,768)
__device__ float g_h1[Bq*Nseq*Edim];
__device__ float g_wcat[3*Edim*Edim];          // [Wo@Ws1_bar] stacked (768x256)
__device__ float g_bfull[Edim];
__device__ float g_zero[Edim];
__device__ float g_conv[(size_t)Bq*Hh*Nseq*Nseq];  // conv*SCALE with code in 2 LSBs

// ---------------- packed f32x2 helpers (GEMM) ----------------------------------
__device__ __forceinline__ ull pk2(float lo, float hi) {
    ull r;
    asm("mov.b64 %0, {%1, %2};" : "=l"(r)
        : "r"(__float_as_uint(lo)), "r"(__float_as_uint(hi)));
    return r;
}
__device__ __forceinline__ void fma2(ull& d, ull a, ull b) {
    asm("fma.rn.f32x2 %0, %1, %2, %3;" : "=l"(d) : "l"(a), "l"(b), "l"(d));
}
__device__ __forceinline__ float2 upk(ull v) {
    unsigned int lo, hi;
    asm("mov.b64 {%0, %1}, %2;" : "=r"(lo), "=r"(hi) : "l"(v));
    return make_float2(__uint_as_float(lo), __uint_as_float(hi));
}

// ---------------- tf32 helpers --------------------------------------------------
__device__ __forceinline__ float tf32_of(float f) {
    unsigned u;
    asm("cvt.rna.tf32.f32 %0, %1;" : "=r"(u) : "f"(f));
    return __uint_as_float(u);
}
__device__ __forceinline__ void mma_tf32(float* d, const unsigned* a,
                                         unsigned b0, unsigned b1) {
    asm volatile(
        "mma.sync.aligned.m16n8k8.row.col.f32.tf32.tf32.f32 "
        "{%0,%1,%2,%3}, {%4,%5,%6,%7}, {%8,%9}, {%0,%1,%2,%3};"
        : "+f"(d[0]), "+f"(d[1]), "+f"(d[2]), "+f"(d[3])
        : "r"(a[0]), "r"(a[1]), "r"(a[2]), "r"(a[3]), "r"(b0), "r"(b1));
}

// fast exp for tiny arguments (scores ~1e-3); exact-0 preserved; rare fallback
__device__ __forceinline__ float fexp(float x) {
    float e = fmaf(x, 0.041666667f, 0.16666667f);
    e = fmaf(e, x, 0.5f);
    e = fmaf(e, x, 1.0f);
    e = fmaf(e, x, 1.0f);
    if (fabsf(x) > 0.25f) e = __expf(x);
    return e;
}

// ---------------- conv precompute: conv*SCALE + region code in LSBs -----------
// code: 0 = in-all-bars (forced or d<0.3), 1 = d<0.7, 2 = else, 3 = masked
__global__ __launch_bounds__(256) void conv_kernel(
    const float* __restrict__ dist, const int* __restrict__ mask,
    const float* __restrict__ cw1, const float* __restrict__ cb1,
    const float* __restrict__ cw2, const float* __restrict__ cb2,
    float* __restrict__ convp)
{
    __shared__ float scw1[8], scb1[8], scw2[64], scb2[8];
    int tid = threadIdx.x;
    if (tid < 8)  { scw1[tid] = cw1[tid]; scb1[tid] = cb1[tid]; scb2[tid] = cb2[tid]; }
    if (tid < 64) scw2[tid] = cw2[tid];
    __syncthreads();

    const int bi = blockIdx.x;           // b*512 + i
    const int b = bi >> 9, i = bi & 511;
    const float* drow = dist + (size_t)bi * Nseq;
    const int*   mrow = mask + (size_t)bi * Nseq;

    for (int j = tid; j < Nseq; j += 256) {
        float d = drow[j];
        int   m = mrow[j];
        float rl[8];
        #pragma unroll
        for (int t = 0; t < 8; t++)
            rl[t] = fmaxf(fmaf(d, scw1[t], scb1[t]), 0.f);
        unsigned code = (m == 0) ? 3u
                      : (i == 0 || j == 0) ? 0u
                      : (d < 0.3f) ? 0u : (d < 0.7f) ? 1u : 2u;
        #pragma unroll
        for (int h = 0; h < 8; h++) {
            float c = scb2[h];
            #pragma unroll
            for (int t = 0; t < 8; t++)
                c = fmaf(scw2[h*8 + t], rl[t], c);
            c *= SCALE;
            unsigned u = (__float_as_uint(c) & ~3u) | code;
            convp[(((size_t)(b*Hh + h) * Nseq + i) * Nseq) + j] = __uint_as_float(u);
        }
    }
}

// ---------------- 128x64-tile fp32x2 GEMM, double-buffered, z-batched ---------
__global__ __launch_bounds__(256) void gemm128(
    const float* __restrict__ A0, const float* __restrict__ A1, const float* __restrict__ A2,
    const float* __restrict__ W0, const float* __restrict__ W1, const float* __restrict__ W2,
    const float* __restrict__ bias0, const float* __restrict__ bias1, const float* __restrict__ bias2,
    float* __restrict__ C0, float* __restrict__ C1, float* __restrict__ C2,
    int Kd, int ldw, int ldc, int do_relu, int headsplit)
{
    const int z = blockIdx.z;
    const float* A    = (z == 0) ? A0 : (z == 1) ? A1 : A2;
    const float* W    = (z == 0) ? W0 : (z == 1) ? W1 : W2;
    const float* bias = (z == 0) ? bias0 : (z == 1) ? bias1 : bias2;
    float*       C    = (z == 0) ? C0 : (z == 1) ? C1 : C2;

    __shared__ float As[2][16][136];
    __shared__ float Ws[2][16][68];

    const int m0 = blockIdx.x << 7;
    const int n0 = blockIdx.y << 6;
    const int tid = threadIdx.x;
    const int tx = tid & 15, ty = tid >> 4;

    const int ar = tid >> 1;
    const int ac = (tid & 1) << 3;
    const int wr = tid >> 4;
    const int wc = (tid & 15) << 2;

    const float* Aptr = A + (size_t)(m0 + ar) * Kd + ac;
    const float* Wptr = W + (size_t)wr * ldw + n0 + wc;

    float4 a0p = *(const float4*)(Aptr);
    float4 a1p = *(const float4*)(Aptr + 4);
    float4 wp  = *(const float4*)(Wptr);

    ull acc[8][2] = {};

    As[0][ac+0][ar] = a0p.x; As[0][ac+1][ar] = a0p.y;
    As[0][ac+2][ar] = a0p.z; As[0][ac+3][ar] = a0p.w;
    As[0][ac+4][ar] = a1p.x; As[0][ac+5][ar] = a1p.y;
    As[0][ac+6][ar] = a1p.z; As[0][ac+7][ar] = a1p.w;
    *(float4*)&Ws[0][wr][wc] = wp;
    __syncthreads();

    const int nk = Kd >> 4;
    for (int kt = 0; kt < nk; kt++) {
        const int cur = kt & 1, nxt = cur ^ 1;
        if (kt + 1 < nk) {
            a0p = *(const float4*)(Aptr + (kt+1)*16);
            a1p = *(const float4*)(Aptr + (kt+1)*16 + 4);
            wp  = *(const float4*)(Wptr + (size_t)(kt+1)*16*ldw);
        }
        #pragma unroll
        for (int kk = 0; kk < 16; kk++) {
            float4 aA = *(const float4*)&As[cur][kk][ty << 3];
            float4 aB = *(const float4*)&As[cur][kk][(ty << 3) + 4];
            double2 wv = *(const double2*)&Ws[cur][kk][tx << 2];
            ull w01 = __double_as_longlong(wv.x);
            ull w23 = __double_as_longlong(wv.y);
            float a[8] = {aA.x, aA.y, aA.z, aA.w, aB.x, aB.y, aB.z, aB.w};
            #pragma unroll
            for (int i = 0; i < 8; i++) {
                ull ad = pk2(a[i], a[i]);
                fma2(acc[i][0], ad, w01);
                fma2(acc[i][1], ad, w23);
            }
        }
        if (kt + 1 < nk) {
            As[nxt][ac+0][ar] = a0p.x; As[nxt][ac+1][ar] = a0p.y;
            As[nxt][ac+2][ar] = a0p.z; As[nxt][ac+3][ar] = a0p.w;
            As[nxt][ac+4][ar] = a1p.x; As[nxt][ac+5][ar] = a1p.y;
            As[nxt][ac+6][ar] = a1p.z; As[nxt][ac+7][ar] = a1p.w;
            *(float4*)&Ws[nxt][wr][wc] = wp;
        }
        __syncthreads();
    }

    const int col0 = n0 + (tx << 2);
    float4 b4 = *(const float4*)&bias[col0];
    #pragma unroll
    for (int i = 0; i < 8; i++) {
        int m = m0 + (ty << 3) + i;
        float2 u0 = upk(acc[i][0]);
        float2 u1 = upk(acc[i][1]);
        float4 r;
        r.x = u0.x + b4.x; r.y = u0.y + b4.y;
        r.z = u1.x + b4.z; r.w = u1.y + b4.w;
        if (do_relu) {
            r.x = fmaxf(r.x, 0.f); r.y = fmaxf(r.y, 0.f);
            r.z = fmaxf(r.z, 0.f); r.w = fmaxf(r.w, 0.f);
        }
        if (headsplit) {
            int b = m >> 9, n = m & 511;
            int h = col0 >> 5, d = col0 & 31;
            *(float4*)&C[(((size_t)(b*Hh + h))*Nseq + n)*DKd + d] = r;
        } else {
            *(float4*)&C[(size_t)m * ldc + col0] = r;
        }
    }
}

// ---------------- bias fold ---------------------------------------------------
__global__ void bias_fold(const float* __restrict__ bo, const float* __restrict__ Ws1,
                          const float* __restrict__ bs1, float* __restrict__ bfull)
{
    int n = threadIdx.x;
    float s = bs1[n];
    #pragma unroll 8
    for (int r = 0; r < 3*Edim; r++)
        s += bo[r & (Edim-1)] * Ws1[(size_t)r * Edim + n];
    bfull[n] = s;
}

// ---------------- tf32 mma attention, key-split warp groups -------------------
// CTA = (64 q rows, b*H+h), 256 threads / 8 warps.
// wg = warp/4 owns keys [wg*32, wg*32+32); mwarp = warp%4 owns q-rows [mwarp*16,+16).
// dynamic smem (float offsets):
//   Qs  [64][36]        @0       (2304)
//   Ks  [64][36]        @2304    (2304)   Ks[key][d]
//   Vt  [32][68]        @4608    (2176)   Vt[d][key]
//   E3  rowstride 272   @6784    (17408)  [row][key][{e2,e1,e0,pad}]
//   lsA [3][64]         @24192   (192)
//   lsB [3][64]         @24384   (192)    total 24576 floats = 98304 B
#define ATTN_SMEM 98304

__global__ __launch_bounds__(256) void attn_mma(
    const float* __restrict__ Q, const float* __restrict__ K, const float* __restrict__ V,
    const float* __restrict__ convp, float* __restrict__ xcat)
{
    extern __shared__ float sm[];
    float (*Qs)[36] = (float(*)[36])(sm);
    float (*Ks)[36] = (float(*)[36])(sm + 2304);
    float (*Vt)[68] = (float(*)[68])(sm + 4608);
    float*  E3      = sm + 6784;         // row stride 272 floats
    float*  lsA     = sm + 24192;
    float*  lsB     = sm + 24384;

    const int qt = blockIdx.x;
    const int bh = blockIdx.y;
    const int b = bh >> 3, h = bh & 7;
    const int q0 = qt << 6;
    const int tid = threadIdx.x;
    const int warp = tid >> 5, lane = tid & 31;
    const int g = lane >> 2, r4 = lane & 3;
    const int wg = warp >> 2;                    // key half
    const int mwarp = warp & 3;
    const int mrow = mwarp << 4;                 // q-stripe base
    const int keybase = wg << 5;

    const size_t headbase = (size_t)bh * Nseq * DKd;

    // ---- stage Q (cvt to tf32) ----
    const float* Qb = Q + headbase + (size_t)q0 * DKd;
    for (int t = tid; t < 64*32; t += 256)
        Qs[t >> 5][t & 31] = tf32_of(Qb[t]);
    __syncthreads();

    // ---- Q A-fragments: 4 ksteps (d) x 4 regs ----
    unsigned qa[4][4];
    #pragma unroll
    for (int ks = 0; ks < 4; ks++) {
        qa[ks][0] = __float_as_uint(Qs[mrow + g    ][ks*8 + r4    ]);
        qa[ks][1] = __float_as_uint(Qs[mrow + g + 8][ks*8 + r4    ]);
        qa[ks][2] = __float_as_uint(Qs[mrow + g    ][ks*8 + r4 + 4]);
        qa[ks][3] = __float_as_uint(Qs[mrow + g + 8][ks*8 + r4 + 4]);
    }

    float o[3][4][4] = {};       // [bar][d-ntile][frag reg] (partial: this wg's keys)
    float lsum[3][2] = {};

    const float* cbase = convp + ((size_t)bh * Nseq + q0 + mrow) * Nseq;

    for (int kt = 0; kt < 8; kt++) {
        const int k0 = kt << 6;
        const float* Kb = K + headbase + (size_t)k0 * DKd;
        const float* Vb = V + headbase + (size_t)k0 * DKd;
        __syncthreads();                        // prev PV / E3 reads done
        for (int t = tid; t < 64*32; t += 256) {
            Ks[t >> 5][t & 31] = tf32_of(Kb[t]);
            Vt[t & 31][t >> 5] = tf32_of(Vb[t]);
        }
        __syncthreads();

        // ---- S = Q K^T for this wg's 4 key n-tiles ----
        float s[4][4] = {};
        #pragma unroll
        for (int ks = 0; ks < 4; ks++) {
            #pragma unroll
            for (int nt = 0; nt < 4; nt++) {
                unsigned b0 = __float_as_uint(Ks[keybase + nt*8 + g][ks*8 + r4    ]);
                unsigned b1 = __float_as_uint(Ks[keybase + nt*8 + g][ks*8 + r4 + 4]);
                mma_tf32(s[nt], qa[ks], b0, b1);
            }
        }

        // ---- exp once, split by bar code, stage E3 interleaved (tf32) ----
        #pragma unroll
        for (int nt = 0; nt < 4; nt++) {
            #pragma unroll
            for (int rr = 0; rr < 2; rr++) {
                const int trow = mrow + g + rr*8;
                const int col = keybase + nt*8 + 2*r4;
                const float2 c2 = *(const float2*)&cbase[(size_t)(g + rr*8) * Nseq
                                                         + k0 + col];
                float sx = s[nt][rr*2 + 0], sy = s[nt][rr*2 + 1];
                unsigned cx = __float_as_uint(c2.x) & 3u;
                unsigned cy = __float_as_uint(c2.y) & 3u;
                float ex = fexp(sx * c2.x);
                float ey = fexp(sy * c2.y);
                ex = (cx == 3u) ? 0.f : ex;
                ey = (cy == 3u) ? 0.f : ey;
                float ex1 = (cx < 2u) ? ex : 0.f;
                float ey1 = (cy < 2u) ? ey : 0.f;
                float ex0 = (cx == 0u) ? ex : 0.f;
                float ey0 = (cy == 0u) ? ey : 0.f;
                lsum[2][rr] += ex + ey;
                lsum[1][rr] += ex1 + ey1;
                lsum[0][rr] += ex0 + ey0;
                *(float4*)&E3[trow*272 + col*4] =
                    make_float4(tf32_of(ex),  tf32_of(ex1), tf32_of(ex0), 0.f);
                *(float4*)&E3[trow*272 + (col+1)*4] =
                    make_float4(tf32_of(ey),  tf32_of(ey1), tf32_of(ey0), 0.f);
            }
        }
        __syncthreads();

        // ---- PV over this wg's 4 key k-steps; one LDS.128 = 3 bars ----
        #pragma unroll
        for (int ks = 0; ks < 4; ks++) {
            const int kk = keybase + ks*8;
            unsigned vb[4][2];
            #pragma unroll
            for (int nt = 0; nt < 4; nt++) {
                vb[nt][0] = __float_as_uint(Vt[nt*8 + g][kk + r4    ]);
                vb[nt][1] = __float_as_uint(Vt[nt*8 + g][kk + r4 + 4]);
            }
            float4 f00 = *(const float4*)&E3[(mrow + g    )*272 + (kk + r4    )*4];
            float4 f10 = *(const float4*)&E3[(mrow + g + 8)*272 + (kk + r4    )*4];
            float4 f01 = *(const float4*)&E3[(mrow + g    )*272 + (kk + r4 + 4)*4];
            float4 f11 = *(const float4*)&E3[(mrow + g + 8)*272 + (kk + r4 + 4)*4];
            unsigned a[4];
            // bar 2 (x), bar 1 (y), bar 0 (z)
            a[0]=__float_as_uint(f00.x); a[1]=__float_as_uint(f10.x);
            a[2]=__float_as_uint(f01.x); a[3]=__float_as_uint(f11.x);
            #pragma unroll
            for (int nt = 0; nt < 4; nt++) mma_tf32(o[2][nt], a, vb[nt][0], vb[nt][1]);
            a[0]=__float_as_uint(f00.y); a[1]=__float_as_uint(f10.y);
            a[2]=__float_as_uint(f01.y); a[3]=__float_as_uint(f11.y);
            #pragma unroll
            for (int nt = 0; nt < 4; nt++) mma_tf32(o[1][nt], a, vb[nt][0], vb[nt][1]);
            a[0]=__float_as_uint(f00.z); a[1]=__float_as_uint(f10.z);
            a[2]=__float_as_uint(f01.z); a[3]=__float_as_uint(f11.z);
            #pragma unroll
            for (int nt = 0; nt < 4; nt++) mma_tf32(o[0][nt], a, vb[nt][0], vb[nt][1]);
        }
    }

    // ---- lane-reduce lsum within quad, publish per-wg row sums ----
    float* lsX = wg ? lsB : lsA;
    #pragma unroll
    for (int bar = 0; bar < 3; bar++)
        #pragma unroll
        for (int rr = 0; rr < 2; rr++) {
            float v = lsum[bar][rr];
            v += __shfl_xor_sync(0xffffffffu, v, 1);
            v += __shfl_xor_sync(0xffffffffu, v, 2);
            if (r4 == 0) lsX[bar*64 + mrow + g + rr*8] = v;
        }

    // wg1 dumps partial O into E3 region
    if (wg == 1) {
        const int idx = tid - 128;     // 0..127
        #pragma unroll
        for (int bar = 0; bar < 3; bar++)
            #pragma unroll
            for (int nt = 0; nt < 4; nt++)
                *(float4*)&E3[(idx*12 + bar*4 + nt)*4] =
                    make_float4(o[bar][nt][0], o[bar][nt][1], o[bar][nt][2], o[bar][nt][3]);
    }
    __syncthreads();

    // wg0 combines, normalizes, writes concat layout (B,N, bar*256 + h*32 + d)
    if (wg == 0) {
        const int idx = tid;           // 0..127
        const int rowA = q0 + mrow + g;
        const int rowB = rowA + 8;
        #pragma unroll
        for (int bar = 0; bar < 3; bar++) {
            const float rlA = 1.f / (lsA[bar*64 + mrow + g    ] + lsB[bar*64 + mrow + g    ]);
            const float rlB = 1.f / (lsA[bar*64 + mrow + g + 8] + lsB[bar*64 + mrow + g + 8]);
            #pragma unroll
            for (int nt = 0; nt < 4; nt++) {
                float4 p = *(const float4*)&E3[(idx*12 + bar*4 + nt)*4];
                const int col = bar*Edim + h*DKd + nt*8 + 2*r4;
                size_t baseA = ((size_t)b*Nseq + rowA) * (3*Edim) + col;
                size_t baseB = ((size_t)b*Nseq + rowB) * (3*Edim) + col;
                *(float2*)&xcat[baseA] = make_float2((o[bar][nt][0] + p.x)*rlA,
                                                     (o[bar][nt][1] + p.y)*rlA);
                *(float2*)&xcat[baseB] = make_float2((o[bar][nt][2] + p.z)*rlB,
                                                     (o[bar][nt][3] + p.w)*rlB);
            }
        }
    }
}

// ---------------- host launcher ----------------------------------------------
extern "C" void kernel_launch(void* const* d_in, const int* in_sizes, int n_in,
                              void* d_out, int out_size)
{
    const float* query = (const float*)d_in[0];
    const float* key   = (const float*)d_in[1];
    const float* value = (const float*)d_in[2];
    const float* dist  = (const float*)d_in[3];
    const int*   mask  = (const int*)d_in[4];
    const float* Wq = (const float*)d_in[5];
    const float* bq = (const float*)d_in[6];
    const float* Wk = (const float*)d_in[7];
    const float* bk = (const float*)d_in[8];
    const float* Wv = (const float*)d_in[9];
    const float* bv = (const float*)d_in[10];
    const float* Wo = (const float*)d_in[11];
    const float* bo = (const float*)d_in[12];
    const float* cw1 = (const float*)d_in[13];
    const float* cb1 = (const float*)d_in[14];
    const float* cw2 = (const float*)d_in[15];
    const float* cb2 = (const float*)d_in[16];
    const float* Ws1 = (const float*)d_in[17];
    const float* bs1 = (const float*)d_in[18];
    const float* Ws2 = (const float*)d_in[19];
    const float* bs2 = (const float*)d_in[20];
    float* out = (float*)d_out;

    float *q_p, *k_p, *v_p, *x_p, *h1_p, *wcat_p, *bfull_p, *zero_p, *conv_p;
    cudaGetSymbolAddress((void**)&q_p,    g_q);
    cudaGetSymbolAddress((void**)&k_p,    g_k);
    cudaGetSymbolAddress((void**)&v_p,    g_v);
    cudaGetSymbolAddress((void**)&x_p,    g_x);
    cudaGetSymbolAddress((void**)&h1_p,   g_h1);
    cudaGetSymbolAddress((void**)&wcat_p, g_wcat);
    cudaGetSymbolAddress((void**)&bfull_p,g_bfull);
    cudaGetSymbolAddress((void**)&zero_p, g_zero);
    cudaGetSymbolAddress((void**)&conv_p, g_conv);

    cudaFuncSetAttribute(attn_mma,
                         cudaFuncAttributeMaxDynamicSharedMemorySize, ATTN_SMEM);

    const int M = Bq * Nseq;          // 4096
    dim3 blk(256);

    // conv precompute
    conv_kernel<<<Bq * Nseq, blk>>>(dist, mask, cw1, cb1, cw2, cb2, conv_p);

    // Wcat = [Wo @ Ws1_bar] and folded bias
    {
        dim3 grid(Edim / 128, Edim / 64, 3);
        gemm128<<<grid, blk>>>(Wo, Wo, Wo,
                               Ws1, Ws1 + Edim*Edim, Ws1 + 2*Edim*Edim,
                               zero_p, zero_p, zero_p,
                               wcat_p, wcat_p + Edim*Edim, wcat_p + 2*Edim*Edim,
                               Edim, Edim, Edim, 0, 0);
        bias_fold<<<1, Edim>>>(bo, Ws1, bs1, bfull_p);
    }

    // QKV projections -> (B,H,N,DK), z-batched
    {
        dim3 grid(M / 128, Edim / 64, 3);
        gemm128<<<grid, blk>>>(query, key, value,
                               Wq, Wk, Wv,
                               bq, bk, bv,
                               q_p, k_p, v_p,
                               Edim, Edim, 0, 0, 1);
    }

    // tf32 mma attention -> concat g_x (B,N,768)
    {
        dim3 grid(Nseq / 64, Bq * Hh);
        attn_mma<<<grid, 256, ATTN_SMEM>>>(q_p, k_p, v_p, conv_p, x_p);
    }

    // h1 = relu(xcat @ Wcat + bfull)
    {
        dim3 grid(M / 128, Edim / 64, 1);
        gemm128<<<grid, blk>>>(x_p, x_p, x_p, wcat_p, wcat_p, wcat_p,
                               bfull_p, bfull_p, bfull_p,
                               h1_p, h1_p, h1_p, 3*Edim, Edim, Edim, 1, 0);
    }

    // out = h1 @ Ws2 + bs2
    {
        dim3 grid(M / 128, Edim / 64, 1);
        gemm128<<<grid, blk>>>(h1_p, h1_p, h1_p, Ws2, Ws2, Ws2, bs2, bs2, bs2,
                               out, out, out, Edim, Edim, Edim, 0, 0);
    }
}

// round 8
// speedup vs baseline: 1.3292x; 1.0309x over previous
#include <cuda_runtime.h>
#include <math.h>

#define Bq   8
#define Nseq 512
#define Edim 256
#define Hh   8
#define DKd  32
#define SCALE 0.17677669529663687f   // 1/sqrt(32)

typedef unsigned long long ull;

// ---------------- scratch (device globals) ------------------------------------
__device__ float g_q[Bq*Hh*Nseq*DKd];
__device__ float g_k[Bq*Hh*Nseq*DKd];
__device__ float g_v[Bq*Hh*Nseq*DKd];
__device__ float g_x[Bq*Nseq*3*Edim];          // concat attn outputs (B,N,768)
__device__ float g_h1[Bq*Nseq*Edim];
__device__ float g_wcat[3*Edim*Edim];          // [Wo@Ws1_bar] stacked (768x256)
__device__ float g_bfull[Edim];
__device__ float g_zero[Edim];
__device__ float g_conv[(size_t)Bq*Hh*Nseq*Nseq];  // conv*SCALE with code in 2 LSBs

// ---------------- packed f32x2 helpers (GEMM) ----------------------------------
__device__ __forceinline__ ull pk2(float lo, float hi) {
    ull r;
    asm("mov.b64 %0, {%1, %2};" : "=l"(r)
        : "r"(__float_as_uint(lo)), "r"(__float_as_uint(hi)));
    return r;
}
__device__ __forceinline__ void fma2(ull& d, ull a, ull b) {
    asm("fma.rn.f32x2 %0, %1, %2, %3;" : "=l"(d) : "l"(a), "l"(b), "l"(d));
}
__device__ __forceinline__ float2 upk(ull v) {
    unsigned int lo, hi;
    asm("mov.b64 {%0, %1}, %2;" : "=r"(lo), "=r"(hi) : "l"(v));
    return make_float2(__uint_as_float(lo), __uint_as_float(hi));
}

// ---------------- tf32 helpers --------------------------------------------------
__device__ __forceinline__ float tf32_of(float f) {
    unsigned u;
    asm("cvt.rna.tf32.f32 %0, %1;" : "=r"(u) : "f"(f));
    return __uint_as_float(u);
}
__device__ __forceinline__ void mma_tf32(float* d, const unsigned* a,
                                         unsigned b0, unsigned b1) {
    asm volatile(
        "mma.sync.aligned.m16n8k8.row.col.f32.tf32.tf32.f32 "
        "{%0,%1,%2,%3}, {%4,%5,%6,%7}, {%8,%9}, {%0,%1,%2,%3};"
        : "+f"(d[0]), "+f"(d[1]), "+f"(d[2]), "+f"(d[3])
        : "r"(a[0]), "r"(a[1]), "r"(a[2]), "r"(a[3]), "r"(b0), "r"(b1));
}

// fast exp for tiny arguments (scores ~1e-3); exact-0 preserved; rare fallback
__device__ __forceinline__ float fexp(float x) {
    float e = fmaf(x, 0.041666667f, 0.16666667f);
    e = fmaf(e, x, 0.5f);
    e = fmaf(e, x, 1.0f);
    e = fmaf(e, x, 1.0f);
    if (fabsf(x) > 0.25f) e = __expf(x);
    return e;
}

// ---------------- conv precompute: conv*SCALE + region code in LSBs -----------
// code: 0 = in-all-bars (forced or d<0.3), 1 = d<0.7, 2 = else, 3 = masked
__global__ __launch_bounds__(256) void conv_kernel(
    const float* __restrict__ dist, const int* __restrict__ mask,
    const float* __restrict__ cw1, const float* __restrict__ cb1,
    const float* __restrict__ cw2, const float* __restrict__ cb2,
    float* __restrict__ convp)
{
    __shared__ float scw1[8], scb1[8], scw2[64], scb2[8];
    int tid = threadIdx.x;
    if (tid < 8)  { scw1[tid] = cw1[tid]; scb1[tid] = cb1[tid]; scb2[tid] = cb2[tid]; }
    if (tid < 64) scw2[tid] = cw2[tid];
    __syncthreads();

    const int bi = blockIdx.x;           // b*512 + i
    const int b = bi >> 9, i = bi & 511;
    const float* drow = dist + (size_t)bi * Nseq;
    const int*   mrow = mask + (size_t)bi * Nseq;

    for (int j = tid; j < Nseq; j += 256) {
        float d = drow[j];
        int   m = mrow[j];
        float rl[8];
        #pragma unroll
        for (int t = 0; t < 8; t++)
            rl[t] = fmaxf(fmaf(d, scw1[t], scb1[t]), 0.f);
        unsigned code = (m == 0) ? 3u
                      : (i == 0 || j == 0) ? 0u
                      : (d < 0.3f) ? 0u : (d < 0.7f) ? 1u : 2u;
        #pragma unroll
        for (int h = 0; h < 8; h++) {
            float c = scb2[h];
            #pragma unroll
            for (int t = 0; t < 8; t++)
                c = fmaf(scw2[h*8 + t], rl[t], c);
            c *= SCALE;
            unsigned u = (__float_as_uint(c) & ~3u) | code;
            convp[(((size_t)(b*Hh + h) * Nseq + i) * Nseq) + j] = __uint_as_float(u);
        }
    }
}

// ---------------- 128x64-tile fp32x2 GEMM, double-buffered, z-batched ---------
__global__ __launch_bounds__(256) void gemm128(
    const float* __restrict__ A0, const float* __restrict__ A1, const float* __restrict__ A2,
    const float* __restrict__ W0, const float* __restrict__ W1, const float* __restrict__ W2,
    const float* __restrict__ bias0, const float* __restrict__ bias1, const float* __restrict__ bias2,
    float* __restrict__ C0, float* __restrict__ C1, float* __restrict__ C2,
    int Kd, int ldw, int ldc, int do_relu, int headsplit)
{
    const int z = blockIdx.z;
    const float* A    = (z == 0) ? A0 : (z == 1) ? A1 : A2;
    const float* W    = (z == 0) ? W0 : (z == 1) ? W1 : W2;
    const float* bias = (z == 0) ? bias0 : (z == 1) ? bias1 : bias2;
    float*       C    = (z == 0) ? C0 : (z == 1) ? C1 : C2;

    __shared__ float As[2][16][136];
    __shared__ float Ws[2][16][68];

    const int m0 = blockIdx.x << 7;
    const int n0 = blockIdx.y << 6;
    const int tid = threadIdx.x;
    const int tx = tid & 15, ty = tid >> 4;

    const int ar = tid >> 1;
    const int ac = (tid & 1) << 3;
    const int wr = tid >> 4;
    const int wc = (tid & 15) << 2;

    const float* Aptr = A + (size_t)(m0 + ar) * Kd + ac;
    const float* Wptr = W + (size_t)wr * ldw + n0 + wc;

    float4 a0p = *(const float4*)(Aptr);
    float4 a1p = *(const float4*)(Aptr + 4);
    float4 wp  = *(const float4*)(Wptr);

    ull acc[8][2] = {};

    As[0][ac+0][ar] = a0p.x; As[0][ac+1][ar] = a0p.y;
    As[0][ac+2][ar] = a0p.z; As[0][ac+3][ar] = a0p.w;
    As[0][ac+4][ar] = a1p.x; As[0][ac+5][ar] = a1p.y;
    As[0][ac+6][ar] = a1p.z; As[0][ac+7][ar] = a1p.w;
    *(float4*)&Ws[0][wr][wc] = wp;
    __syncthreads();

    const int nk = Kd >> 4;
    for (int kt = 0; kt < nk; kt++) {
        const int cur = kt & 1, nxt = cur ^ 1;
        if (kt + 1 < nk) {
            a0p = *(const float4*)(Aptr + (kt+1)*16);
            a1p = *(const float4*)(Aptr + (kt+1)*16 + 4);
            wp  = *(const float4*)(Wptr + (size_t)(kt+1)*16*ldw);
        }
        #pragma unroll
        for (int kk = 0; kk < 16; kk++) {
            float4 aA = *(const float4*)&As[cur][kk][ty << 3];
            float4 aB = *(const float4*)&As[cur][kk][(ty << 3) + 4];
            double2 wv = *(const double2*)&Ws[cur][kk][tx << 2];
            ull w01 = __double_as_longlong(wv.x);
            ull w23 = __double_as_longlong(wv.y);
            float a[8] = {aA.x, aA.y, aA.z, aA.w, aB.x, aB.y, aB.z, aB.w};
            #pragma unroll
            for (int i = 0; i < 8; i++) {
                ull ad = pk2(a[i], a[i]);
                fma2(acc[i][0], ad, w01);
                fma2(acc[i][1], ad, w23);
            }
        }
        if (kt + 1 < nk) {
            As[nxt][ac+0][ar] = a0p.x; As[nxt][ac+1][ar] = a0p.y;
            As[nxt][ac+2][ar] = a0p.z; As[nxt][ac+3][ar] = a0p.w;
            As[nxt][ac+4][ar] = a1p.x; As[nxt][ac+5][ar] = a1p.y;
            As[nxt][ac+6][ar] = a1p.z; As[nxt][ac+7][ar] = a1p.w;
            *(float4*)&Ws[nxt][wr][wc] = wp;
        }
        __syncthreads();
    }

    const int col0 = n0 + (tx << 2);
    float4 b4 = *(const float4*)&bias[col0];
    #pragma unroll
    for (int i = 0; i < 8; i++) {
        int m = m0 + (ty << 3) + i;
        float2 u0 = upk(acc[i][0]);
        float2 u1 = upk(acc[i][1]);
        float4 r;
        r.x = u0.x + b4.x; r.y = u0.y + b4.y;
        r.z = u1.x + b4.z; r.w = u1.y + b4.w;
        if (do_relu) {
            r.x = fmaxf(r.x, 0.f); r.y = fmaxf(r.y, 0.f);
            r.z = fmaxf(r.z, 0.f); r.w = fmaxf(r.w, 0.f);
        }
        if (headsplit) {
            int b = m >> 9, n = m & 511;
            int h = col0 >> 5, d = col0 & 31;
            *(float4*)&C[(((size_t)(b*Hh + h))*Nseq + n)*DKd + d] = r;
        } else {
            *(float4*)&C[(size_t)m * ldc + col0] = r;
        }
    }
}

// ---------------- bias fold ---------------------------------------------------
__global__ void bias_fold(const float* __restrict__ bo, const float* __restrict__ Ws1,
                          const float* __restrict__ bs1, float* __restrict__ bfull)
{
    int n = threadIdx.x;
    float s = bs1[n];
    #pragma unroll 8
    for (int r = 0; r < 3*Edim; r++)
        s += bo[r & (Edim-1)] * Ws1[(size_t)r * Edim + n];
    bfull[n] = s;
}

// ---------------- tf32 mma attention, key-split warp groups -------------------
// CTA = (64 q rows, b*H+h), 256 threads / 8 warps.
// wg = warp/4 owns keys [wg*32, wg*32+32); mwarp = warp%4 owns q-rows [mwarp*16,+16).
// dynamic smem (float offsets):
//   Qs  [64][36]        @0       (2304)
//   Ks  [64][36]        @2304    (2304)   Ks[key][d]
//   Vt  [32][68]        @4608    (2176)   Vt[d][key]
//   E3  rowstride 272   @6784    (17408)  [row][key][{e2,e1,e0,pad}]
//   lsA [3][64]         @24192   (192)
//   lsB [3][64]         @24384   (192)    total 24576 floats = 98304 B
#define ATTN_SMEM 98304

__global__ __launch_bounds__(256) void attn_mma(
    const float* __restrict__ Q, const float* __restrict__ K, const float* __restrict__ V,
    const float* __restrict__ convp, float* __restrict__ xcat)
{
    extern __shared__ float sm[];
    float (*Qs)[36] = (float(*)[36])(sm);
    float (*Ks)[36] = (float(*)[36])(sm + 2304);
    float (*Vt)[68] = (float(*)[68])(sm + 4608);
    float*  E3      = sm + 6784;         // row stride 272 floats
    float*  lsA     = sm + 24192;
    float*  lsB     = sm + 24384;

    const int qt = blockIdx.x;
    const int bh = blockIdx.y;
    const int b = bh >> 3, h = bh & 7;
    const int q0 = qt << 6;
    const int tid = threadIdx.x;
    const int warp = tid >> 5, lane = tid & 31;
    const int g = lane >> 2, r4 = lane & 3;
    const int wg = warp >> 2;                    // key half
    const int mwarp = warp & 3;
    const int mrow = mwarp << 4;                 // q-stripe base
    const int keybase = wg << 5;

    const size_t headbase = (size_t)bh * Nseq * DKd;

    // ---- stage Q (cvt to tf32) ----
    const float* Qb = Q + headbase + (size_t)q0 * DKd;
    for (int t = tid; t < 64*32; t += 256)
        Qs[t >> 5][t & 31] = tf32_of(Qb[t]);
    __syncthreads();

    // ---- Q A-fragments: 4 ksteps (d) x 4 regs ----
    unsigned qa[4][4];
    #pragma unroll
    for (int ks = 0; ks < 4; ks++) {
        qa[ks][0] = __float_as_uint(Qs[mrow + g    ][ks*8 + r4    ]);
        qa[ks][1] = __float_as_uint(Qs[mrow + g + 8][ks*8 + r4    ]);
        qa[ks][2] = __float_as_uint(Qs[mrow + g    ][ks*8 + r4 + 4]);
        qa[ks][3] = __float_as_uint(Qs[mrow + g + 8][ks*8 + r4 + 4]);
    }

    float o[3][4][4] = {};       // [bar][d-ntile][frag reg] (partial: this wg's keys)
    float lsum[3][2] = {};

    const float* cbase = convp + ((size_t)bh * Nseq + q0 + mrow) * Nseq;

    for (int kt = 0; kt < 8; kt++) {
        const int k0 = kt << 6;
        const float* Kb = K + headbase + (size_t)k0 * DKd;
        const float* Vb = V + headbase + (size_t)k0 * DKd;
        __syncthreads();                        // prev PV / E3 reads done
        for (int t = tid; t < 64*32; t += 256) {
            Ks[t >> 5][t & 31] = tf32_of(Kb[t]);
            Vt[t & 31][t >> 5] = tf32_of(Vb[t]);
        }
        __syncthreads();

        // ---- S = Q K^T for this wg's 4 key n-tiles ----
        float s[4][4] = {};
        #pragma unroll
        for (int ks = 0; ks < 4; ks++) {
            #pragma unroll
            for (int nt = 0; nt < 4; nt++) {
                unsigned b0 = __float_as_uint(Ks[keybase + nt*8 + g][ks*8 + r4    ]);
                unsigned b1 = __float_as_uint(Ks[keybase + nt*8 + g][ks*8 + r4 + 4]);
                mma_tf32(s[nt], qa[ks], b0, b1);
            }
        }

        // ---- exp once, split by bar code, stage E3 interleaved (tf32) ----
        #pragma unroll
        for (int nt = 0; nt < 4; nt++) {
            #pragma unroll
            for (int rr = 0; rr < 2; rr++) {
                const int trow = mrow + g + rr*8;
                const int col = keybase + nt*8 + 2*r4;
                const float2 c2 = *(const float2*)&cbase[(size_t)(g + rr*8) * Nseq
                                                         + k0 + col];
                float sx = s[nt][rr*2 + 0], sy = s[nt][rr*2 + 1];
                unsigned cx = __float_as_uint(c2.x) & 3u;
                unsigned cy = __float_as_uint(c2.y) & 3u;
                float ex = fexp(sx * c2.x);
                float ey = fexp(sy * c2.y);
                ex = (cx == 3u) ? 0.f : ex;
                ey = (cy == 3u) ? 0.f : ey;
                float ex1 = (cx < 2u) ? ex : 0.f;
                float ey1 = (cy < 2u) ? ey : 0.f;
                float ex0 = (cx == 0u) ? ex : 0.f;
                float ey0 = (cy == 0u) ? ey : 0.f;
                lsum[2][rr] += ex + ey;
                lsum[1][rr] += ex1 + ey1;
                lsum[0][rr] += ex0 + ey0;
                *(float4*)&E3[trow*272 + col*4] =
                    make_float4(tf32_of(ex),  tf32_of(ex1), tf32_of(ex0), 0.f);
                *(float4*)&E3[trow*272 + (col+1)*4] =
                    make_float4(tf32_of(ey),  tf32_of(ey1), tf32_of(ey0), 0.f);
            }
        }
        __syncthreads();

        // ---- PV over this wg's 4 key k-steps; one LDS.128 = 3 bars ----
        #pragma unroll
        for (int ks = 0; ks < 4; ks++) {
            const int kk = keybase + ks*8;
            unsigned vb[4][2];
            #pragma unroll
            for (int nt = 0; nt < 4; nt++) {
                vb[nt][0] = __float_as_uint(Vt[nt*8 + g][kk + r4    ]);
                vb[nt][1] = __float_as_uint(Vt[nt*8 + g][kk + r4 + 4]);
            }
            float4 f00 = *(const float4*)&E3[(mrow + g    )*272 + (kk + r4    )*4];
            float4 f10 = *(const float4*)&E3[(mrow + g + 8)*272 + (kk + r4    )*4];
            float4 f01 = *(const float4*)&E3[(mrow + g    )*272 + (kk + r4 + 4)*4];
            float4 f11 = *(const float4*)&E3[(mrow + g + 8)*272 + (kk + r4 + 4)*4];
            unsigned a[4];
            // bar 2 (x), bar 1 (y), bar 0 (z)
            a[0]=__float_as_uint(f00.x); a[1]=__float_as_uint(f10.x);
            a[2]=__float_as_uint(f01.x); a[3]=__float_as_uint(f11.x);
            #pragma unroll
            for (int nt = 0; nt < 4; nt++) mma_tf32(o[2][nt], a, vb[nt][0], vb[nt][1]);
            a[0]=__float_as_uint(f00.y); a[1]=__float_as_uint(f10.y);
            a[2]=__float_as_uint(f01.y); a[3]=__float_as_uint(f11.y);
            #pragma unroll
            for (int nt = 0; nt < 4; nt++) mma_tf32(o[1][nt], a, vb[nt][0], vb[nt][1]);
            a[0]=__float_as_uint(f00.z); a[1]=__float_as_uint(f10.z);
            a[2]=__float_as_uint(f01.z); a[3]=__float_as_uint(f11.z);
            #pragma unroll
            for (int nt = 0; nt < 4; nt++) mma_tf32(o[0][nt], a, vb[nt][0], vb[nt][1]);
        }
    }

    // ---- lane-reduce lsum within quad, publish per-wg row sums ----
    float* lsX = wg ? lsB : lsA;
    #pragma unroll
    for (int bar = 0; bar < 3; bar++)
        #pragma unroll
        for (int rr = 0; rr < 2; rr++) {
            float v = lsum[bar][rr];
            v += __shfl_xor_sync(0xffffffffu, v, 1);
            v += __shfl_xor_sync(0xffffffffu, v, 2);
            if (r4 == 0) lsX[bar*64 + mrow + g + rr*8] = v;
        }

    // wg1 dumps partial O into E3 region
    if (wg == 1) {
        const int idx = tid - 128;     // 0..127
        #pragma unroll
        for (int bar = 0; bar < 3; bar++)
            #pragma unroll
            for (int nt = 0; nt < 4; nt++)
                *(float4*)&E3[(idx*12 + bar*4 + nt)*4] =
                    make_float4(o[bar][nt][0], o[bar][nt][1], o[bar][nt][2], o[bar][nt][3]);
    }
    __syncthreads();

    // wg0 combines, normalizes, writes concat layout (B,N, bar*256 + h*32 + d)
    if (wg == 0) {
        const int idx = tid;           // 0..127
        const int rowA = q0 + mrow + g;
        const int rowB = rowA + 8;
        #pragma unroll
        for (int bar = 0; bar < 3; bar++) {
            const float rlA = 1.f / (lsA[bar*64 + mrow + g    ] + lsB[bar*64 + mrow + g    ]);
            const float rlB = 1.f / (lsA[bar*64 + mrow + g + 8] + lsB[bar*64 + mrow + g + 8]);
            #pragma unroll
            for (int nt = 0; nt < 4; nt++) {
                float4 p = *(const float4*)&E3[(idx*12 + bar*4 + nt)*4];
                const int col = bar*Edim + h*DKd + nt*8 + 2*r4;
                size_t baseA = ((size_t)b*Nseq + rowA) * (3*Edim) + col;
                size_t baseB = ((size_t)b*Nseq + rowB) * (3*Edim) + col;
                *(float2*)&xcat[baseA] = make_float2((o[bar][nt][0] + p.x)*rlA,
                                                     (o[bar][nt][1] + p.y)*rlA);
                *(float2*)&xcat[baseB] = make_float2((o[bar][nt][2] + p.z)*rlB,
                                                     (o[bar][nt][3] + p.w)*rlB);
            }
        }
    }
}

// ---------------- host launcher ----------------------------------------------
extern "C" void kernel_launch(void* const* d_in, const int* in_sizes, int n_in,
                              void* d_out, int out_size)
{
    const float* query = (const float*)d_in[0];
    const float* key   = (const float*)d_in[1];
    const float* value = (const float*)d_in[2];
    const float* dist  = (const float*)d_in[3];
    const int*   mask  = (const int*)d_in[4];
    const float* Wq = (const float*)d_in[5];
    const float* bq = (const float*)d_in[6];
    const float* Wk = (const float*)d_in[7];
    const float* bk = (const float*)d_in[8];
    const float* Wv = (const float*)d_in[9];
    const float* bv = (const float*)d_in[10];
    const float* Wo = (const float*)d_in[11];
    const float* bo = (const float*)d_in[12];
    const float* cw1 = (const float*)d_in[13];
    const float* cb1 = (const float*)d_in[14];
    const float* cw2 = (const float*)d_in[15];
    const float* cb2 = (const float*)d_in[16];
    const float* Ws1 = (const float*)d_in[17];
    const float* bs1 = (const float*)d_in[18];
    const float* Ws2 = (const float*)d_in[19];
    const float* bs2 = (const float*)d_in[20];
    float* out = (float*)d_out;

    float *q_p, *k_p, *v_p, *x_p, *h1_p, *wcat_p, *bfull_p, *zero_p, *conv_p;
    cudaGetSymbolAddress((void**)&q_p,    g_q);
    cudaGetSymbolAddress((void**)&k_p,    g_k);
    cudaGetSymbolAddress((void**)&v_p,    g_v);
    cudaGetSymbolAddress((void**)&x_p,    g_x);
    cudaGetSymbolAddress((void**)&h1_p,   g_h1);
    cudaGetSymbolAddress((void**)&wcat_p, g_wcat);
    cudaGetSymbolAddress((void**)&bfull_p,g_bfull);
    cudaGetSymbolAddress((void**)&zero_p, g_zero);
    cudaGetSymbolAddress((void**)&conv_p, g_conv);

    cudaFuncSetAttribute(attn_mma,
                         cudaFuncAttributeMaxDynamicSharedMemorySize, ATTN_SMEM);

    const int M = Bq * Nseq;          // 4096
    dim3 blk(256);

    // conv precompute
    conv_kernel<<<Bq * Nseq, blk>>>(dist, mask, cw1, cb1, cw2, cb2, conv_p);

    // Wcat = [Wo @ Ws1_bar] and folded bias
    {
        dim3 grid(Edim / 128, Edim / 64, 3);
        gemm128<<<grid, blk>>>(Wo, Wo, Wo,
                               Ws1, Ws1 + Edim*Edim, Ws1 + 2*Edim*Edim,
                               zero_p, zero_p, zero_p,
                               wcat_p, wcat_p + Edim*Edim, wcat_p + 2*Edim*Edim,
                               Edim, Edim, Edim, 0, 0);
        bias_fold<<<1, Edim>>>(bo, Ws1, bs1, bfull_p);
    }

    // QKV projections -> (B,H,N,DK), z-batched
    {
        dim3 grid(M / 128, Edim / 64, 3);
        gemm128<<<grid, blk>>>(query, key, value,
                               Wq, Wk, Wv,
                               bq, bk, bv,
                               q_p, k_p, v_p,
                               Edim, Edim, 0, 0, 1);
    }

    // tf32 mma attention -> concat g_x (B,N,768)
    {
        dim3 grid(Nseq / 64, Bq * Hh);
        attn_mma<<<grid, 256, ATTN_SMEM>>>(q_p, k_p, v_p, conv_p, x_p);
    }

    // h1 = relu(xcat @ Wcat + bfull)
    {
        dim3 grid(M / 128, Edim / 64, 1);
        gemm128<<<grid, blk>>>(x_p, x_p, x_p, wcat_p, wcat_p, wcat_p,
                               bfull_p, bfull_p, bfull_p,
                               h1_p, h1_p, h1_p, 3*Edim, Edim, Edim, 1, 0);
    }

    // out = h1 @ Ws2 + bs2
    {
        dim3 grid(M / 128, Edim / 64, 1);
        gemm128<<<grid, blk>>>(h1_p, h1_p, h1_p, Ws2, Ws2, Ws2, bs2, bs2, bs2,
                               out, out, out, Edim, Edim, Edim, 0, 0);
    }
}

// round 9
// speedup vs baseline: 1.5570x; 1.1714x over previous
#include <cuda_runtime.h>
#include <math.h>

#define Bq   8
#define Nseq 512
#define Edim 256
#define Hh   8
#define DKd  32
#define SCALE 0.17677669529663687f   // 1/sqrt(32)

typedef unsigned long long ull;

// ---------------- scratch (device globals) ------------------------------------
__device__ float g_q[Bq*Hh*Nseq*DKd];
__device__ float g_k[Bq*Hh*Nseq*DKd];
__device__ float g_v[Bq*Hh*Nseq*DKd];
__device__ float g_x[Bq*Nseq*3*Edim];
__device__ float g_h1[Bq*Nseq*Edim];
__device__ float g_wcat[3*Edim*Edim];
__device__ float g_bfull[Edim];
__device__ float g_zero[Edim];
__device__ float g_conv[(size_t)Bq*Hh*Nseq*Nseq];  // conv*SCALE, code in 2 LSBs

// ---------------- tf32 helpers --------------------------------------------------
__device__ __forceinline__ float tf32_of(float f) {
    unsigned u;
    asm("cvt.rna.tf32.f32 %0, %1;" : "=r"(u) : "f"(f));
    return __uint_as_float(u);
}
__device__ __forceinline__ void mma_tf32(float* d, const unsigned* a,
                                         unsigned b0, unsigned b1) {
    asm volatile(
        "mma.sync.aligned.m16n8k8.row.col.f32.tf32.tf32.f32 "
        "{%0,%1,%2,%3}, {%4,%5,%6,%7}, {%8,%9}, {%0,%1,%2,%3};"
        : "+f"(d[0]), "+f"(d[1]), "+f"(d[2]), "+f"(d[3])
        : "r"(a[0]), "r"(a[1]), "r"(a[2]), "r"(a[3]), "r"(b0), "r"(b1));
}
__device__ __forceinline__ float fexp(float x) {
    float e = fmaf(x, 0.041666667f, 0.16666667f);
    e = fmaf(e, x, 0.5f);
    e = fmaf(e, x, 1.0f);
    e = fmaf(e, x, 1.0f);
    if (fabsf(x) > 0.25f) e = __expf(x);
    return e;
}

// ---------------- conv precompute (unchanged, known-good) ----------------------
__global__ __launch_bounds__(256) void conv_kernel(
    const float* __restrict__ dist, const int* __restrict__ mask,
    const float* __restrict__ cw1, const float* __restrict__ cb1,
    const float* __restrict__ cw2, const float* __restrict__ cb2,
    float* __restrict__ convp)
{
    __shared__ float scw1[8], scb1[8], scw2[64], scb2[8];
    int tid = threadIdx.x;
    if (tid < 8)  { scw1[tid] = cw1[tid]; scb1[tid] = cb1[tid]; scb2[tid] = cb2[tid]; }
    if (tid < 64) scw2[tid] = cw2[tid];
    __syncthreads();

    const int bi = blockIdx.x;
    const int b = bi >> 9, i = bi & 511;
    const float* drow = dist + (size_t)bi * Nseq;
    const int*   mrow = mask + (size_t)bi * Nseq;

    for (int j = tid; j < Nseq; j += 256) {
        float d = drow[j];
        int   m = mrow[j];
        float rl[8];
        #pragma unroll
        for (int t = 0; t < 8; t++)
            rl[t] = fmaxf(fmaf(d, scw1[t], scb1[t]), 0.f);
        unsigned code = (m == 0) ? 3u
                      : (i == 0 || j == 0) ? 0u
                      : (d < 0.3f) ? 0u : (d < 0.7f) ? 1u : 2u;
        #pragma unroll
        for (int h = 0; h < 8; h++) {
            float c = scb2[h];
            #pragma unroll
            for (int t = 0; t < 8; t++)
                c = fmaf(scw2[h*8 + t], rl[t], c);
            c *= SCALE;
            unsigned u = (__float_as_uint(c) & ~3u) | code;
            convp[(((size_t)(b*Hh + h) * Nseq + i) * Nseq) + j] = __uint_as_float(u);
        }
    }
}

// ---------------- tf32 mma GEMM: 128x64 CTA tile, double-buffered, z-batched ---
// 256 threads / 8 warps; warp tile 32x32 (2 m16 x 4 n8).
__global__ __launch_bounds__(256) void gemm_tc(
    const float* __restrict__ A0, const float* __restrict__ A1, const float* __restrict__ A2,
    const float* __restrict__ W0, const float* __restrict__ W1, const float* __restrict__ W2,
    const float* __restrict__ bias0, const float* __restrict__ bias1, const float* __restrict__ bias2,
    float* __restrict__ C0, float* __restrict__ C1, float* __restrict__ C2,
    int Kd, int ldw, int ldc, int do_relu, int headsplit)
{
    const int z = blockIdx.z;
    const float* A    = (z == 0) ? A0 : (z == 1) ? A1 : A2;
    const float* W    = (z == 0) ? W0 : (z == 1) ? W1 : W2;
    const float* bias = (z == 0) ? bias0 : (z == 1) ? bias1 : bias2;
    float*       C    = (z == 0) ? C0 : (z == 1) ? C1 : C2;

    __shared__ float As[2][16][136];   // k-major A tile (tf32 bits)
    __shared__ float Ws[2][16][72];    // W tile (tf32 bits)

    const int m0 = blockIdx.x << 7;
    const int n0 = blockIdx.y << 6;
    const int tid = threadIdx.x;
    const int warp = tid >> 5, lane = tid & 31;
    const int g = lane >> 2, r4 = lane & 3;
    const int mb = (warp & 3) << 5;    // warp m-base within CTA
    const int nb = (warp >> 2) << 5;   // warp n-base within CTA

    const int ar = tid >> 1;
    const int ac = (tid & 1) << 3;
    const int wr = tid >> 4;
    const int wc = (tid & 15) << 2;

    const float* Aptr = A + (size_t)(m0 + ar) * Kd + ac;
    const float* Wptr = W + (size_t)wr * ldw + n0 + wc;

    float4 a0p = *(const float4*)(Aptr);
    float4 a1p = *(const float4*)(Aptr + 4);
    float4 wp  = *(const float4*)(Wptr);

    float c[2][4][4] = {};

    // store stage 0 (tf32-converted)
    As[0][ac+0][ar] = tf32_of(a0p.x); As[0][ac+1][ar] = tf32_of(a0p.y);
    As[0][ac+2][ar] = tf32_of(a0p.z); As[0][ac+3][ar] = tf32_of(a0p.w);
    As[0][ac+4][ar] = tf32_of(a1p.x); As[0][ac+5][ar] = tf32_of(a1p.y);
    As[0][ac+6][ar] = tf32_of(a1p.z); As[0][ac+7][ar] = tf32_of(a1p.w);
    Ws[0][wr][wc+0] = tf32_of(wp.x);  Ws[0][wr][wc+1] = tf32_of(wp.y);
    Ws[0][wr][wc+2] = tf32_of(wp.z);  Ws[0][wr][wc+3] = tf32_of(wp.w);
    __syncthreads();

    const int nk = Kd >> 4;
    for (int kt = 0; kt < nk; kt++) {
        const int cur = kt & 1, nxt = cur ^ 1;
        if (kt + 1 < nk) {
            a0p = *(const float4*)(Aptr + (kt+1)*16);
            a1p = *(const float4*)(Aptr + (kt+1)*16 + 4);
            wp  = *(const float4*)(Wptr + (size_t)(kt+1)*16*ldw);
        }
        #pragma unroll
        for (int ks = 0; ks < 2; ks++) {
            unsigned af[2][4], bf[4][2];
            #pragma unroll
            for (int mt = 0; mt < 2; mt++) {
                const int row = mb + mt*16 + g;
                af[mt][0] = __float_as_uint(As[cur][ks*8 + r4    ][row    ]);
                af[mt][1] = __float_as_uint(As[cur][ks*8 + r4    ][row + 8]);
                af[mt][2] = __float_as_uint(As[cur][ks*8 + r4 + 4][row    ]);
                af[mt][3] = __float_as_uint(As[cur][ks*8 + r4 + 4][row + 8]);
            }
            #pragma unroll
            for (int nt = 0; nt < 4; nt++) {
                const int col = nb + nt*8 + g;
                bf[nt][0] = __float_as_uint(Ws[cur][ks*8 + r4    ][col]);
                bf[nt][1] = __float_as_uint(Ws[cur][ks*8 + r4 + 4][col]);
            }
            #pragma unroll
            for (int mt = 0; mt < 2; mt++)
                #pragma unroll
                for (int nt = 0; nt < 4; nt++)
                    mma_tf32(c[mt][nt], af[mt], bf[nt][0], bf[nt][1]);
        }
        if (kt + 1 < nk) {
            As[nxt][ac+0][ar] = tf32_of(a0p.x); As[nxt][ac+1][ar] = tf32_of(a0p.y);
            As[nxt][ac+2][ar] = tf32_of(a0p.z); As[nxt][ac+3][ar] = tf32_of(a0p.w);
            As[nxt][ac+4][ar] = tf32_of(a1p.x); As[nxt][ac+5][ar] = tf32_of(a1p.y);
            As[nxt][ac+6][ar] = tf32_of(a1p.z); As[nxt][ac+7][ar] = tf32_of(a1p.w);
            Ws[nxt][wr][wc+0] = tf32_of(wp.x);  Ws[nxt][wr][wc+1] = tf32_of(wp.y);
            Ws[nxt][wr][wc+2] = tf32_of(wp.z);  Ws[nxt][wr][wc+3] = tf32_of(wp.w);
        }
        __syncthreads();
    }

    // ---- epilogue ----
    #pragma unroll
    for (int nt = 0; nt < 4; nt++) {
        const int col0 = n0 + nb + nt*8 + 2*r4;
        const float2 bb = *(const float2*)&bias[col0];
        #pragma unroll
        for (int mt = 0; mt < 2; mt++) {
            const int row0 = m0 + mb + mt*16 + g;
            float2 v0 = make_float2(c[mt][nt][0] + bb.x, c[mt][nt][1] + bb.y);
            float2 v1 = make_float2(c[mt][nt][2] + bb.x, c[mt][nt][3] + bb.y);
            if (do_relu) {
                v0.x = fmaxf(v0.x, 0.f); v0.y = fmaxf(v0.y, 0.f);
                v1.x = fmaxf(v1.x, 0.f); v1.y = fmaxf(v1.y, 0.f);
            }
            if (headsplit) {
                const int h = col0 >> 5, d = col0 & 31;
                int b = row0 >> 9, n = row0 & 511;
                *(float2*)&C[(((size_t)(b*Hh + h))*Nseq + n)*DKd + d] = v0;
                b = (row0+8) >> 9; n = (row0+8) & 511;
                *(float2*)&C[(((size_t)(b*Hh + h))*Nseq + n)*DKd + d] = v1;
            } else {
                *(float2*)&C[(size_t)row0 * ldc + col0] = v0;
                *(float2*)&C[(size_t)(row0+8) * ldc + col0] = v1;
            }
        }
    }
}

// ---------------- bias fold ---------------------------------------------------
__global__ void bias_fold(const float* __restrict__ bo, const float* __restrict__ Ws1,
                          const float* __restrict__ bs1, float* __restrict__ bfull)
{
    int n = threadIdx.x;
    float s = bs1[n];
    #pragma unroll 8
    for (int r = 0; r < 3*Edim; r++)
        s += bo[r & (Edim-1)] * Ws1[(size_t)r * Edim + n];
    bfull[n] = s;
}

// ---------------- tf32 mma attention (unchanged, known-good) -------------------
#define ATTN_SMEM 98304

__global__ __launch_bounds__(256) void attn_mma(
    const float* __restrict__ Q, const float* __restrict__ K, const float* __restrict__ V,
    const float* __restrict__ convp, float* __restrict__ xcat)
{
    extern __shared__ float sm[];
    float (*Qs)[36] = (float(*)[36])(sm);
    float (*Ks)[36] = (float(*)[36])(sm + 2304);
    float (*Vt)[68] = (float(*)[68])(sm + 4608);
    float*  E3      = sm + 6784;
    float*  lsA     = sm + 24192;
    float*  lsB     = sm + 24384;

    const int qt = blockIdx.x;
    const int bh = blockIdx.y;
    const int b = bh >> 3, h = bh & 7;
    const int q0 = qt << 6;
    const int tid = threadIdx.x;
    const int warp = tid >> 5, lane = tid & 31;
    const int g = lane >> 2, r4 = lane & 3;
    const int wg = warp >> 2;
    const int mwarp = warp & 3;
    const int mrow = mwarp << 4;
    const int keybase = wg << 5;

    const size_t headbase = (size_t)bh * Nseq * DKd;

    const float* Qb = Q + headbase + (size_t)q0 * DKd;
    for (int t = tid; t < 64*32; t += 256)
        Qs[t >> 5][t & 31] = tf32_of(Qb[t]);
    __syncthreads();

    unsigned qa[4][4];
    #pragma unroll
    for (int ks = 0; ks < 4; ks++) {
        qa[ks][0] = __float_as_uint(Qs[mrow + g    ][ks*8 + r4    ]);
        qa[ks][1] = __float_as_uint(Qs[mrow + g + 8][ks*8 + r4    ]);
        qa[ks][2] = __float_as_uint(Qs[mrow + g    ][ks*8 + r4 + 4]);
        qa[ks][3] = __float_as_uint(Qs[mrow + g + 8][ks*8 + r4 + 4]);
    }

    float o[3][4][4] = {};
    float lsum[3][2] = {};

    const float* cbase = convp + ((size_t)bh * Nseq + q0 + mrow) * Nseq;

    for (int kt = 0; kt < 8; kt++) {
        const int k0 = kt << 6;
        const float* Kb = K + headbase + (size_t)k0 * DKd;
        const float* Vb = V + headbase + (size_t)k0 * DKd;
        __syncthreads();
        for (int t = tid; t < 64*32; t += 256) {
            Ks[t >> 5][t & 31] = tf32_of(Kb[t]);
            Vt[t & 31][t >> 5] = tf32_of(Vb[t]);
        }
        __syncthreads();

        float s[4][4] = {};
        #pragma unroll
        for (int ks = 0; ks < 4; ks++) {
            #pragma unroll
            for (int nt = 0; nt < 4; nt++) {
                unsigned b0 = __float_as_uint(Ks[keybase + nt*8 + g][ks*8 + r4    ]);
                unsigned b1 = __float_as_uint(Ks[keybase + nt*8 + g][ks*8 + r4 + 4]);
                mma_tf32(s[nt], qa[ks], b0, b1);
            }
        }

        #pragma unroll
        for (int nt = 0; nt < 4; nt++) {
            #pragma unroll
            for (int rr = 0; rr < 2; rr++) {
                const int trow = mrow + g + rr*8;
                const int col = keybase + nt*8 + 2*r4;
                const float2 c2 = *(const float2*)&cbase[(size_t)(g + rr*8) * Nseq
                                                         + k0 + col];
                float sx = s[nt][rr*2 + 0], sy = s[nt][rr*2 + 1];
                unsigned cx = __float_as_uint(c2.x) & 3u;
                unsigned cy = __float_as_uint(c2.y) & 3u;
                float ex = fexp(sx * c2.x);
                float ey = fexp(sy * c2.y);
                ex = (cx == 3u) ? 0.f : ex;
                ey = (cy == 3u) ? 0.f : ey;
                float ex1 = (cx < 2u) ? ex : 0.f;
                float ey1 = (cy < 2u) ? ey : 0.f;
                float ex0 = (cx == 0u) ? ex : 0.f;
                float ey0 = (cy == 0u) ? ey : 0.f;
                lsum[2][rr] += ex + ey;
                lsum[1][rr] += ex1 + ey1;
                lsum[0][rr] += ex0 + ey0;
                *(float4*)&E3[trow*272 + col*4] =
                    make_float4(tf32_of(ex),  tf32_of(ex1), tf32_of(ex0), 0.f);
                *(float4*)&E3[trow*272 + (col+1)*4] =
                    make_float4(tf32_of(ey),  tf32_of(ey1), tf32_of(ey0), 0.f);
            }
        }
        __syncthreads();

        #pragma unroll
        for (int ks = 0; ks < 4; ks++) {
            const int kk = keybase + ks*8;
            unsigned vb[4][2];
            #pragma unroll
            for (int nt = 0; nt < 4; nt++) {
                vb[nt][0] = __float_as_uint(Vt[nt*8 + g][kk + r4    ]);
                vb[nt][1] = __float_as_uint(Vt[nt*8 + g][kk + r4 + 4]);
            }
            float4 f00 = *(const float4*)&E3[(mrow + g    )*272 + (kk + r4    )*4];
            float4 f10 = *(const float4*)&E3[(mrow + g + 8)*272 + (kk + r4    )*4];
            float4 f01 = *(const float4*)&E3[(mrow + g    )*272 + (kk + r4 + 4)*4];
            float4 f11 = *(const float4*)&E3[(mrow + g + 8)*272 + (kk + r4 + 4)*4];
            unsigned a[4];
            a[0]=__float_as_uint(f00.x); a[1]=__float_as_uint(f10.x);
            a[2]=__float_as_uint(f01.x); a[3]=__float_as_uint(f11.x);
            #pragma unroll
            for (int nt = 0; nt < 4; nt++) mma_tf32(o[2][nt], a, vb[nt][0], vb[nt][1]);
            a[0]=__float_as_uint(f00.y); a[1]=__float_as_uint(f10.y);
            a[2]=__float_as_uint(f01.y); a[3]=__float_as_uint(f11.y);
            #pragma unroll
            for (int nt = 0; nt < 4; nt++) mma_tf32(o[1][nt], a, vb[nt][0], vb[nt][1]);
            a[0]=__float_as_uint(f00.z); a[1]=__float_as_uint(f10.z);
            a[2]=__float_as_uint(f01.z); a[3]=__float_as_uint(f11.z);
            #pragma unroll
            for (int nt = 0; nt < 4; nt++) mma_tf32(o[0][nt], a, vb[nt][0], vb[nt][1]);
        }
    }

    float* lsX = wg ? lsB : lsA;
    #pragma unroll
    for (int bar = 0; bar < 3; bar++)
        #pragma unroll
        for (int rr = 0; rr < 2; rr++) {
            float v = lsum[bar][rr];
            v += __shfl_xor_sync(0xffffffffu, v, 1);
            v += __shfl_xor_sync(0xffffffffu, v, 2);
            if (r4 == 0) lsX[bar*64 + mrow + g + rr*8] = v;
        }

    if (wg == 1) {
        const int idx = tid - 128;
        #pragma unroll
        for (int bar = 0; bar < 3; bar++)
            #pragma unroll
            for (int nt = 0; nt < 4; nt++)
                *(float4*)&E3[(idx*12 + bar*4 + nt)*4] =
                    make_float4(o[bar][nt][0], o[bar][nt][1], o[bar][nt][2], o[bar][nt][3]);
    }
    __syncthreads();

    if (wg == 0) {
        const int idx = tid;
        const int rowA = q0 + mrow + g;
        const int rowB = rowA + 8;
        #pragma unroll
        for (int bar = 0; bar < 3; bar++) {
            const float rlA = 1.f / (lsA[bar*64 + mrow + g    ] + lsB[bar*64 + mrow + g    ]);
            const float rlB = 1.f / (lsA[bar*64 + mrow + g + 8] + lsB[bar*64 + mrow + g + 8]);
            #pragma unroll
            for (int nt = 0; nt < 4; nt++) {
                float4 p = *(const float4*)&E3[(idx*12 + bar*4 + nt)*4];
                const int col = bar*Edim + h*DKd + nt*8 + 2*r4;
                size_t baseA = ((size_t)b*Nseq + rowA) * (3*Edim) + col;
                size_t baseB = ((size_t)b*Nseq + rowB) * (3*Edim) + col;
                *(float2*)&xcat[baseA] = make_float2((o[bar][nt][0] + p.x)*rlA,
                                                     (o[bar][nt][1] + p.y)*rlA);
                *(float2*)&xcat[baseB] = make_float2((o[bar][nt][2] + p.z)*rlB,
                                                     (o[bar][nt][3] + p.w)*rlB);
            }
        }
    }
}

// ---------------- host launcher ----------------------------------------------
extern "C" void kernel_launch(void* const* d_in, const int* in_sizes, int n_in,
                              void* d_out, int out_size)
{
    const float* query = (const float*)d_in[0];
    const float* key   = (const float*)d_in[1];
    const float* value = (const float*)d_in[2];
    const float* dist  = (const float*)d_in[3];
    const int*   mask  = (const int*)d_in[4];
    const float* Wq = (const float*)d_in[5];
    const float* bq = (const float*)d_in[6];
    const float* Wk = (const float*)d_in[7];
    const float* bk = (const float*)d_in[8];
    const float* Wv = (const float*)d_in[9];
    const float* bv = (const float*)d_in[10];
    const float* Wo = (const float*)d_in[11];
    const float* bo = (const float*)d_in[12];
    const float* cw1 = (const float*)d_in[13];
    const float* cb1 = (const float*)d_in[14];
    const float* cw2 = (const float*)d_in[15];
    const float* cb2 = (const float*)d_in[16];
    const float* Ws1 = (const float*)d_in[17];
    const float* bs1 = (const float*)d_in[18];
    const float* Ws2 = (const float*)d_in[19];
    const float* bs2 = (const float*)d_in[20];
    float* out = (float*)d_out;

    float *q_p, *k_p, *v_p, *x_p, *h1_p, *wcat_p, *bfull_p, *zero_p, *conv_p;
    cudaGetSymbolAddress((void**)&q_p,    g_q);
    cudaGetSymbolAddress((void**)&k_p,    g_k);
    cudaGetSymbolAddress((void**)&v_p,    g_v);
    cudaGetSymbolAddress((void**)&x_p,    g_x);
    cudaGetSymbolAddress((void**)&h1_p,   g_h1);
    cudaGetSymbolAddress((void**)&wcat_p, g_wcat);
    cudaGetSymbolAddress((void**)&bfull_p,g_bfull);
    cudaGetSymbolAddress((void**)&zero_p, g_zero);
    cudaGetSymbolAddress((void**)&conv_p, g_conv);

    cudaFuncSetAttribute(attn_mma,
                         cudaFuncAttributeMaxDynamicSharedMemorySize, ATTN_SMEM);

    const int M = Bq * Nseq;          // 4096
    dim3 blk(256);

    // conv precompute
    conv_kernel<<<Bq * Nseq, blk>>>(dist, mask, cw1, cb1, cw2, cb2, conv_p);

    // Wcat = [Wo @ Ws1_bar] and folded bias
    {
        dim3 grid(Edim / 128, Edim / 64, 3);
        gemm_tc<<<grid, blk>>>(Wo, Wo, Wo,
                               Ws1, Ws1 + Edim*Edim, Ws1 + 2*Edim*Edim,
                               zero_p, zero_p, zero_p,
                               wcat_p, wcat_p + Edim*Edim, wcat_p + 2*Edim*Edim,
                               Edim, Edim, Edim, 0, 0);
        bias_fold<<<1, Edim>>>(bo, Ws1, bs1, bfull_p);
    }

    // QKV projections -> (B,H,N,DK), z-batched
    {
        dim3 grid(M / 128, Edim / 64, 3);
        gemm_tc<<<grid, blk>>>(query, key, value,
                               Wq, Wk, Wv,
                               bq, bk, bv,
                               q_p, k_p, v_p,
                               Edim, Edim, 0, 0, 1);
    }

    // tf32 mma attention -> concat g_x (B,N,768)
    {
        dim3 grid(Nseq / 64, Bq * Hh);
        attn_mma<<<grid, 256, ATTN_SMEM>>>(q_p, k_p, v_p, conv_p, x_p);
    }

    // h1 = relu(xcat @ Wcat + bfull)
    {
        dim3 grid(M / 128, Edim / 64, 1);
        gemm_tc<<<grid, blk>>>(x_p, x_p, x_p, wcat_p, wcat_p, wcat_p,
                               bfull_p, bfull_p, bfull_p,
                               h1_p, h1_p, h1_p, 3*Edim, Edim, Edim, 1, 0);
    }

    // out = h1 @ Ws2 + bs2
    {
        dim3 grid(M / 128, Edim / 64, 1);
        gemm_tc<<<grid, blk>>>(h1_p, h1_p, h1_p, Ws2, Ws2, Ws2, bs2, bs2, bs2,
                               out, out, out, Edim, Edim, Edim, 0, 0);
    }
}

// round 10
// speedup vs baseline: 1.6188x; 1.0397x over previous
#include <cuda_runtime.h>
#include <math.h>

#define Bq   8
#define Nseq 512
#define Edim 256
#define Hh   8
#define DKd  32
#define SCALE 0.17677669529663687f   // 1/sqrt(32)

typedef unsigned long long ull;

// ---------------- scratch (device globals) ------------------------------------
__device__ float g_q[Bq*Hh*Nseq*DKd];
__device__ float g_k[Bq*Hh*Nseq*DKd];
__device__ float g_v[Bq*Hh*Nseq*DKd];
__device__ float g_x[Bq*Nseq*3*Edim];
__device__ float g_h1[Bq*Nseq*Edim];
__device__ float g_wcat[3*Edim*Edim];
__device__ float g_bfull[Edim];
__device__ float g_zero[Edim];
__device__ float g_conv[(size_t)Bq*Hh*Nseq*Nseq];  // conv*SCALE, code in 2 LSBs
__device__ float g_tblA[Hh*256];                    // lerp slope  (×SCALE)
__device__ float g_tblB[Hh*256];                    // lerp offset (×SCALE)

// ---------------- tf32 helpers --------------------------------------------------
__device__ __forceinline__ float tf32_of(float f) {
    unsigned u;
    asm("cvt.rna.tf32.f32 %0, %1;" : "=r"(u) : "f"(f));
    return __uint_as_float(u);
}
__device__ __forceinline__ void mma_tf32(float* d, const unsigned* a,
                                         unsigned b0, unsigned b1) {
    asm volatile(
        "mma.sync.aligned.m16n8k8.row.col.f32.tf32.tf32.f32 "
        "{%0,%1,%2,%3}, {%4,%5,%6,%7}, {%8,%9}, {%0,%1,%2,%3};"
        : "+f"(d[0]), "+f"(d[1]), "+f"(d[2]), "+f"(d[3])
        : "r"(a[0]), "r"(a[1]), "r"(a[2]), "r"(a[3]), "r"(b0), "r"(b1));
}
__device__ __forceinline__ float fexp(float x) {
    float e = fmaf(x, 0.041666667f, 0.16666667f);
    e = fmaf(e, x, 0.5f);
    e = fmaf(e, x, 1.0f);
    e = fmaf(e, x, 1.0f);
    if (fabsf(x) > 0.25f) e = __expf(x);
    return e;
}

// ---------------- lerp table build: 256 bins x 8 heads -------------------------
__global__ void tbl_kernel(const float* __restrict__ cw1, const float* __restrict__ cb1,
                           const float* __restrict__ cw2, const float* __restrict__ cb2,
                           float* __restrict__ tblA, float* __restrict__ tblB)
{
    const int i = threadIdx.x;              // bin 0..255
    const float d0 = i * (1.0f/256.0f);
    const float d1 = (i+1) * (1.0f/256.0f);
    #pragma unroll
    for (int h = 0; h < 8; h++) {
        float f0 = cb2[h], f1 = cb2[h];
        #pragma unroll
        for (int t = 0; t < 8; t++) {
            float r0 = fmaxf(fmaf(d0, cw1[t], cb1[t]), 0.f);
            float r1 = fmaxf(fmaf(d1, cw1[t], cb1[t]), 0.f);
            f0 = fmaf(cw2[h*8 + t], r0, f0);
            f1 = fmaf(cw2[h*8 + t], r1, f1);
        }
        tblB[h*256 + i] = f0 * SCALE;
        tblA[h*256 + i] = (f1 - f0) * SCALE;
    }
}

// ---------------- conv precompute v2: table lerp + code in LSBs ----------------
__global__ __launch_bounds__(256) void conv_kernel(
    const float* __restrict__ dist, const int* __restrict__ mask,
    const float* __restrict__ tblA, const float* __restrict__ tblB,
    float* __restrict__ convp)
{
    __shared__ float sA[8][256], sB[8][256];
    const int tid = threadIdx.x;
    for (int t = tid; t < 2048; t += 256) {
        sA[t >> 8][t & 255] = tblA[t];
        sB[t >> 8][t & 255] = tblB[t];
    }
    __syncthreads();

    const int bi = blockIdx.x;               // b*512 + i
    const int b = bi >> 9, i = bi & 511;
    const float* drow = dist + (size_t)bi * Nseq;
    const int*   mrow = mask + (size_t)bi * Nseq;

    for (int j = tid; j < Nseq; j += 256) {
        float d = drow[j];
        int   m = mrow[j];
        unsigned code = (m == 0) ? 3u
                      : (i == 0 || j == 0) ? 0u
                      : (d < 0.3f) ? 0u : (d < 0.7f) ? 1u : 2u;
        float df = d * 256.0f;
        int idx = (int)df; idx = idx > 255 ? 255 : (idx < 0 ? 0 : idx);
        float frac = df - (float)idx;
        #pragma unroll
        for (int h = 0; h < 8; h++) {
            float c = fmaf(frac, sA[h][idx], sB[h][idx]);
            unsigned u = (__float_as_uint(c) & ~3u) | code;
            convp[(((size_t)(b*Hh + h) * Nseq + i) * Nseq) + j] = __uint_as_float(u);
        }
    }
}

// ---------------- tf32 mma GEMM (R9, + tf32-rounded output for QKV) ------------
__global__ __launch_bounds__(256) void gemm_tc(
    const float* __restrict__ A0, const float* __restrict__ A1, const float* __restrict__ A2,
    const float* __restrict__ W0, const float* __restrict__ W1, const float* __restrict__ W2,
    const float* __restrict__ bias0, const float* __restrict__ bias1, const float* __restrict__ bias2,
    float* __restrict__ C0, float* __restrict__ C1, float* __restrict__ C2,
    int Kd, int ldw, int ldc, int do_relu, int headsplit)
{
    const int z = blockIdx.z;
    const float* A    = (z == 0) ? A0 : (z == 1) ? A1 : A2;
    const float* W    = (z == 0) ? W0 : (z == 1) ? W1 : W2;
    const float* bias = (z == 0) ? bias0 : (z == 1) ? bias1 : bias2;
    float*       C    = (z == 0) ? C0 : (z == 1) ? C1 : C2;

    __shared__ float As[2][16][136];
    __shared__ float Ws[2][16][72];

    const int m0 = blockIdx.x << 7;
    const int n0 = blockIdx.y << 6;
    const int tid = threadIdx.x;
    const int warp = tid >> 5, lane = tid & 31;
    const int g = lane >> 2, r4 = lane & 3;
    const int mb = (warp & 3) << 5;
    const int nb = (warp >> 2) << 5;

    const int ar = tid >> 1;
    const int ac = (tid & 1) << 3;
    const int wr = tid >> 4;
    const int wc = (tid & 15) << 2;

    const float* Aptr = A + (size_t)(m0 + ar) * Kd + ac;
    const float* Wptr = W + (size_t)wr * ldw + n0 + wc;

    float4 a0p = *(const float4*)(Aptr);
    float4 a1p = *(const float4*)(Aptr + 4);
    float4 wp  = *(const float4*)(Wptr);

    float c[2][4][4] = {};

    As[0][ac+0][ar] = tf32_of(a0p.x); As[0][ac+1][ar] = tf32_of(a0p.y);
    As[0][ac+2][ar] = tf32_of(a0p.z); As[0][ac+3][ar] = tf32_of(a0p.w);
    As[0][ac+4][ar] = tf32_of(a1p.x); As[0][ac+5][ar] = tf32_of(a1p.y);
    As[0][ac+6][ar] = tf32_of(a1p.z); As[0][ac+7][ar] = tf32_of(a1p.w);
    Ws[0][wr][wc+0] = tf32_of(wp.x);  Ws[0][wr][wc+1] = tf32_of(wp.y);
    Ws[0][wr][wc+2] = tf32_of(wp.z);  Ws[0][wr][wc+3] = tf32_of(wp.w);
    __syncthreads();

    const int nk = Kd >> 4;
    for (int kt = 0; kt < nk; kt++) {
        const int cur = kt & 1, nxt = cur ^ 1;
        if (kt + 1 < nk) {
            a0p = *(const float4*)(Aptr + (kt+1)*16);
            a1p = *(const float4*)(Aptr + (kt+1)*16 + 4);
            wp  = *(const float4*)(Wptr + (size_t)(kt+1)*16*ldw);
        }
        #pragma unroll
        for (int ks = 0; ks < 2; ks++) {
            unsigned af[2][4], bf[4][2];
            #pragma unroll
            for (int mt = 0; mt < 2; mt++) {
                const int row = mb + mt*16 + g;
                af[mt][0] = __float_as_uint(As[cur][ks*8 + r4    ][row    ]);
                af[mt][1] = __float_as_uint(As[cur][ks*8 + r4    ][row + 8]);
                af[mt][2] = __float_as_uint(As[cur][ks*8 + r4 + 4][row    ]);
                af[mt][3] = __float_as_uint(As[cur][ks*8 + r4 + 4][row + 8]);
            }
            #pragma unroll
            for (int nt = 0; nt < 4; nt++) {
                const int col = nb + nt*8 + g;
                bf[nt][0] = __float_as_uint(Ws[cur][ks*8 + r4    ][col]);
                bf[nt][1] = __float_as_uint(Ws[cur][ks*8 + r4 + 4][col]);
            }
            #pragma unroll
            for (int mt = 0; mt < 2; mt++)
                #pragma unroll
                for (int nt = 0; nt < 4; nt++)
                    mma_tf32(c[mt][nt], af[mt], bf[nt][0], bf[nt][1]);
        }
        if (kt + 1 < nk) {
            As[nxt][ac+0][ar] = tf32_of(a0p.x); As[nxt][ac+1][ar] = tf32_of(a0p.y);
            As[nxt][ac+2][ar] = tf32_of(a0p.z); As[nxt][ac+3][ar] = tf32_of(a0p.w);
            As[nxt][ac+4][ar] = tf32_of(a1p.x); As[nxt][ac+5][ar] = tf32_of(a1p.y);
            As[nxt][ac+6][ar] = tf32_of(a1p.z); As[nxt][ac+7][ar] = tf32_of(a1p.w);
            Ws[nxt][wr][wc+0] = tf32_of(wp.x);  Ws[nxt][wr][wc+1] = tf32_of(wp.y);
            Ws[nxt][wr][wc+2] = tf32_of(wp.z);  Ws[nxt][wr][wc+3] = tf32_of(wp.w);
        }
        __syncthreads();
    }

    #pragma unroll
    for (int nt = 0; nt < 4; nt++) {
        const int col0 = n0 + nb + nt*8 + 2*r4;
        const float2 bb = *(const float2*)&bias[col0];
        #pragma unroll
        for (int mt = 0; mt < 2; mt++) {
            const int row0 = m0 + mb + mt*16 + g;
            float2 v0 = make_float2(c[mt][nt][0] + bb.x, c[mt][nt][1] + bb.y);
            float2 v1 = make_float2(c[mt][nt][2] + bb.x, c[mt][nt][3] + bb.y);
            if (do_relu) {
                v0.x = fmaxf(v0.x, 0.f); v0.y = fmaxf(v0.y, 0.f);
                v1.x = fmaxf(v1.x, 0.f); v1.y = fmaxf(v1.y, 0.f);
            }
            if (headsplit) {
                // QKV outputs: pre-round to tf32 so attn can stage without cvt
                v0.x = tf32_of(v0.x); v0.y = tf32_of(v0.y);
                v1.x = tf32_of(v1.x); v1.y = tf32_of(v1.y);
                const int h = col0 >> 5, d = col0 & 31;
                int b = row0 >> 9, n = row0 & 511;
                *(float2*)&C[(((size_t)(b*Hh + h))*Nseq + n)*DKd + d] = v0;
                b = (row0+8) >> 9; n = (row0+8) & 511;
                *(float2*)&C[(((size_t)(b*Hh + h))*Nseq + n)*DKd + d] = v1;
            } else {
                *(float2*)&C[(size_t)row0 * ldc + col0] = v0;
                *(float2*)&C[(size_t)(row0+8) * ldc + col0] = v1;
            }
        }
    }
}

// ---------------- bias fold ---------------------------------------------------
__global__ void bias_fold(const float* __restrict__ bo, const float* __restrict__ Ws1,
                          const float* __restrict__ bs1, float* __restrict__ bfull)
{
    int n = threadIdx.x;
    float s = bs1[n];
    #pragma unroll 8
    for (int r = 0; r < 3*Edim; r++)
        s += bo[r & (Edim-1)] * Ws1[(size_t)r * Edim + n];
    bfull[n] = s;
}

// ---------------- tf32 mma attention (float4 staging, no cvt) ------------------
#define ATTN_SMEM 98304

__global__ __launch_bounds__(256) void attn_mma(
    const float* __restrict__ Q, const float* __restrict__ K, const float* __restrict__ V,
    const float* __restrict__ convp, float* __restrict__ xcat)
{
    extern __shared__ float sm[];
    float (*Qs)[36] = (float(*)[36])(sm);
    float (*Ks)[36] = (float(*)[36])(sm + 2304);
    float (*Vt)[68] = (float(*)[68])(sm + 4608);
    float*  E3      = sm + 6784;
    float*  lsA     = sm + 24192;
    float*  lsB     = sm + 24384;

    const int qt = blockIdx.x;
    const int bh = blockIdx.y;
    const int b = bh >> 3, h = bh & 7;
    const int q0 = qt << 6;
    const int tid = threadIdx.x;
    const int warp = tid >> 5, lane = tid & 31;
    const int g = lane >> 2, r4 = lane & 3;
    const int wg = warp >> 2;
    const int mwarp = warp & 3;
    const int mrow = mwarp << 4;
    const int keybase = wg << 5;

    const size_t headbase = (size_t)bh * Nseq * DKd;

    // ---- stage Q (already tf32 bits in gmem): float4, no cvt ----
    const float* Qb = Q + headbase + (size_t)q0 * DKd;
    #pragma unroll
    for (int i = 0; i < 2; i++) {
        int idx = tid + i*256;                // 0..511
        int row = idx >> 3, c4 = (idx & 7) << 2;
        *(float4*)&Qs[row][c4] = *(const float4*)&Qb[row*32 + c4];
    }
    __syncthreads();

    unsigned qa[4][4];
    #pragma unroll
    for (int ks = 0; ks < 4; ks++) {
        qa[ks][0] = __float_as_uint(Qs[mrow + g    ][ks*8 + r4    ]);
        qa[ks][1] = __float_as_uint(Qs[mrow + g + 8][ks*8 + r4    ]);
        qa[ks][2] = __float_as_uint(Qs[mrow + g    ][ks*8 + r4 + 4]);
        qa[ks][3] = __float_as_uint(Qs[mrow + g + 8][ks*8 + r4 + 4]);
    }

    float o[3][4][4] = {};
    float lsum[3][2] = {};

    const float* cbase = convp + ((size_t)bh * Nseq + q0 + mrow) * Nseq;

    for (int kt = 0; kt < 8; kt++) {
        const int k0 = kt << 6;
        const float* Kb = K + headbase + (size_t)k0 * DKd;
        const float* Vb = V + headbase + (size_t)k0 * DKd;
        __syncthreads();
        #pragma unroll
        for (int i = 0; i < 2; i++) {
            int idx = tid + i*256;
            int row = idx >> 3, c4 = (idx & 7) << 2;
            *(float4*)&Ks[row][c4] = *(const float4*)&Kb[row*32 + c4];
            float4 vv = *(const float4*)&Vb[row*32 + c4];
            Vt[c4+0][row] = vv.x; Vt[c4+1][row] = vv.y;
            Vt[c4+2][row] = vv.z; Vt[c4+3][row] = vv.w;
        }
        __syncthreads();

        float s[4][4] = {};
        #pragma unroll
        for (int ks = 0; ks < 4; ks++) {
            #pragma unroll
            for (int nt = 0; nt < 4; nt++) {
                unsigned b0 = __float_as_uint(Ks[keybase + nt*8 + g][ks*8 + r4    ]);
                unsigned b1 = __float_as_uint(Ks[keybase + nt*8 + g][ks*8 + r4 + 4]);
                mma_tf32(s[nt], qa[ks], b0, b1);
            }
        }

        #pragma unroll
        for (int nt = 0; nt < 4; nt++) {
            #pragma unroll
            for (int rr = 0; rr < 2; rr++) {
                const int trow = mrow + g + rr*8;
                const int col = keybase + nt*8 + 2*r4;
                const float2 c2 = *(const float2*)&cbase[(size_t)(g + rr*8) * Nseq
                                                         + k0 + col];
                float sx = s[nt][rr*2 + 0], sy = s[nt][rr*2 + 1];
                unsigned cx = __float_as_uint(c2.x) & 3u;
                unsigned cy = __float_as_uint(c2.y) & 3u;
                float ex = fexp(sx * c2.x);
                float ey = fexp(sy * c2.y);
                ex = (cx == 3u) ? 0.f : ex;
                ey = (cy == 3u) ? 0.f : ey;
                float ex1 = (cx < 2u) ? ex : 0.f;
                float ey1 = (cy < 2u) ? ey : 0.f;
                float ex0 = (cx == 0u) ? ex : 0.f;
                float ey0 = (cy == 0u) ? ey : 0.f;
                lsum[2][rr] += ex + ey;
                lsum[1][rr] += ex1 + ey1;
                lsum[0][rr] += ex0 + ey0;
                *(float4*)&E3[trow*272 + col*4] =
                    make_float4(tf32_of(ex),  tf32_of(ex1), tf32_of(ex0), 0.f);
                *(float4*)&E3[trow*272 + (col+1)*4] =
                    make_float4(tf32_of(ey),  tf32_of(ey1), tf32_of(ey0), 0.f);
            }
        }
        __syncthreads();

        #pragma unroll
        for (int ks = 0; ks < 4; ks++) {
            const int kk = keybase + ks*8;
            unsigned vb[4][2];
            #pragma unroll
            for (int nt = 0; nt < 4; nt++) {
                vb[nt][0] = __float_as_uint(Vt[nt*8 + g][kk + r4    ]);
                vb[nt][1] = __float_as_uint(Vt[nt*8 + g][kk + r4 + 4]);
            }
            float4 f00 = *(const float4*)&E3[(mrow + g    )*272 + (kk + r4    )*4];
            float4 f10 = *(const float4*)&E3[(mrow + g + 8)*272 + (kk + r4    )*4];
            float4 f01 = *(const float4*)&E3[(mrow + g    )*272 + (kk + r4 + 4)*4];
            float4 f11 = *(const float4*)&E3[(mrow + g + 8)*272 + (kk + r4 + 4)*4];
            unsigned a[4];
            a[0]=__float_as_uint(f00.x); a[1]=__float_as_uint(f10.x);
            a[2]=__float_as_uint(f01.x); a[3]=__float_as_uint(f11.x);
            #pragma unroll
            for (int nt = 0; nt < 4; nt++) mma_tf32(o[2][nt], a, vb[nt][0], vb[nt][1]);
            a[0]=__float_as_uint(f00.y); a[1]=__float_as_uint(f10.y);
            a[2]=__float_as_uint(f01.y); a[3]=__float_as_uint(f11.y);
            #pragma unroll
            for (int nt = 0; nt < 4; nt++) mma_tf32(o[1][nt], a, vb[nt][0], vb[nt][1]);
            a[0]=__float_as_uint(f00.z); a[1]=__float_as_uint(f10.z);
            a[2]=__float_as_uint(f01.z); a[3]=__float_as_uint(f11.z);
            #pragma unroll
            for (int nt = 0; nt < 4; nt++) mma_tf32(o[0][nt], a, vb[nt][0], vb[nt][1]);
        }
    }

    float* lsX = wg ? lsB : lsA;
    #pragma unroll
    for (int bar = 0; bar < 3; bar++)
        #pragma unroll
        for (int rr = 0; rr < 2; rr++) {
            float v = lsum[bar][rr];
            v += __shfl_xor_sync(0xffffffffu, v, 1);
            v += __shfl_xor_sync(0xffffffffu, v, 2);
            if (r4 == 0) lsX[bar*64 + mrow + g + rr*8] = v;
        }

    if (wg == 1) {
        const int idx = tid - 128;
        #pragma unroll
        for (int bar = 0; bar < 3; bar++)
            #pragma unroll
            for (int nt = 0; nt < 4; nt++)
                *(float4*)&E3[(idx*12 + bar*4 + nt)*4] =
                    make_float4(o[bar][nt][0], o[bar][nt][1], o[bar][nt][2], o[bar][nt][3]);
    }
    __syncthreads();

    if (wg == 0) {
        const int idx = tid;
        const int rowA = q0 + mrow + g;
        const int rowB = rowA + 8;
        #pragma unroll
        for (int bar = 0; bar < 3; bar++) {
            const float rlA = 1.f / (lsA[bar*64 + mrow + g    ] + lsB[bar*64 + mrow + g    ]);
            const float rlB = 1.f / (lsA[bar*64 + mrow + g + 8] + lsB[bar*64 + mrow + g + 8]);
            #pragma unroll
            for (int nt = 0; nt < 4; nt++) {
                float4 p = *(const float4*)&E3[(idx*12 + bar*4 + nt)*4];
                const int col = bar*Edim + h*DKd + nt*8 + 2*r4;
                size_t baseA = ((size_t)b*Nseq + rowA) * (3*Edim) + col;
                size_t baseB = ((size_t)b*Nseq + rowB) * (3*Edim) + col;
                *(float2*)&xcat[baseA] = make_float2((o[bar][nt][0] + p.x)*rlA,
                                                     (o[bar][nt][1] + p.y)*rlA);
                *(float2*)&xcat[baseB] = make_float2((o[bar][nt][2] + p.z)*rlB,
                                                     (o[bar][nt][3] + p.w)*rlB);
            }
        }
    }
}

// ---------------- host launcher ----------------------------------------------
extern "C" void kernel_launch(void* const* d_in, const int* in_sizes, int n_in,
                              void* d_out, int out_size)
{
    const float* query = (const float*)d_in[0];
    const float* key   = (const float*)d_in[1];
    const float* value = (const float*)d_in[2];
    const float* dist  = (const float*)d_in[3];
    const int*   mask  = (const int*)d_in[4];
    const float* Wq = (const float*)d_in[5];
    const float* bq = (const float*)d_in[6];
    const float* Wk = (const float*)d_in[7];
    const float* bk = (const float*)d_in[8];
    const float* Wv = (const float*)d_in[9];
    const float* bv = (const float*)d_in[10];
    const float* Wo = (const float*)d_in[11];
    const float* bo = (const float*)d_in[12];
    const float* cw1 = (const float*)d_in[13];
    const float* cb1 = (const float*)d_in[14];
    const float* cw2 = (const float*)d_in[15];
    const float* cb2 = (const float*)d_in[16];
    const float* Ws1 = (const float*)d_in[17];
    const float* bs1 = (const float*)d_in[18];
    const float* Ws2 = (const float*)d_in[19];
    const float* bs2 = (const float*)d_in[20];
    float* out = (float*)d_out;

    float *q_p, *k_p, *v_p, *x_p, *h1_p, *wcat_p, *bfull_p, *zero_p, *conv_p;
    float *tA_p, *tB_p;
    cudaGetSymbolAddress((void**)&q_p,    g_q);
    cudaGetSymbolAddress((void**)&k_p,    g_k);
    cudaGetSymbolAddress((void**)&v_p,    g_v);
    cudaGetSymbolAddress((void**)&x_p,    g_x);
    cudaGetSymbolAddress((void**)&h1_p,   g_h1);
    cudaGetSymbolAddress((void**)&wcat_p, g_wcat);
    cudaGetSymbolAddress((void**)&bfull_p,g_bfull);
    cudaGetSymbolAddress((void**)&zero_p, g_zero);
    cudaGetSymbolAddress((void**)&conv_p, g_conv);
    cudaGetSymbolAddress((void**)&tA_p,   g_tblA);
    cudaGetSymbolAddress((void**)&tB_p,   g_tblB);

    cudaFuncSetAttribute(attn_mma,
                         cudaFuncAttributeMaxDynamicSharedMemorySize, ATTN_SMEM);

    const int M = Bq * Nseq;          // 4096
    dim3 blk(256);

    // lerp table then conv precompute
    tbl_kernel<<<1, 256>>>(cw1, cb1, cw2, cb2, tA_p, tB_p);
    conv_kernel<<<Bq * Nseq, blk>>>(dist, mask, tA_p, tB_p, conv_p);

    // Wcat = [Wo @ Ws1_bar] and folded bias
    {
        dim3 grid(Edim / 128, Edim / 64, 3);
        gemm_tc<<<grid, blk>>>(Wo, Wo, Wo,
                               Ws1, Ws1 + Edim*Edim, Ws1 + 2*Edim*Edim,
                               zero_p, zero_p, zero_p,
                               wcat_p, wcat_p + Edim*Edim, wcat_p + 2*Edim*Edim,
                               Edim, Edim, Edim, 0, 0);
        bias_fold<<<1, Edim>>>(bo, Ws1, bs1, bfull_p);
    }

    // QKV projections -> (B,H,N,DK), z-batched, outputs tf32-rounded
    {
        dim3 grid(M / 128, Edim / 64, 3);
        gemm_tc<<<grid, blk>>>(query, key, value,
                               Wq, Wk, Wv,
                               bq, bk, bv,
                               q_p, k_p, v_p,
                               Edim, Edim, 0, 0, 1);
    }

    // tf32 mma attention -> concat g_x (B,N,768)
    {
        dim3 grid(Nseq / 64, Bq * Hh);
        attn_mma<<<grid, 256, ATTN_SMEM>>>(q_p, k_p, v_p, conv_p, x_p);
    }

    // h1 = relu(xcat @ Wcat + bfull)
    {
        dim3 grid(M / 128, Edim / 64, 1);
        gemm_tc<<<grid, blk>>>(x_p, x_p, x_p, wcat_p, wcat_p, wcat_p,
                               bfull_p, bfull_p, bfull_p,
                               h1_p, h1_p, h1_p, 3*Edim, Edim, Edim, 1, 0);
    }

    // out = h1 @ Ws2 + bs2
    {
        dim3 grid(M / 128, Edim / 64, 1);
        gemm_tc<<<grid, blk>>>(h1_p, h1_p, h1_p, Ws2, Ws2, Ws2, bs2, bs2, bs2,
                               out, out, out, Edim, Edim, Edim, 0, 0);
    }
}

// round 11
// speedup vs baseline: 1.8015x; 1.1129x over previous
#include <cuda_runtime.h>
#include <math.h>

#define Bq   8
#define Nseq 512
#define Edim 256
#define Hh   8
#define DKd  32
#define SCALE 0.17677669529663687f   // 1/sqrt(32)

typedef unsigned long long ull;

// ---------------- scratch (device globals) ------------------------------------
__device__ float g_q[Bq*Hh*Nseq*DKd];
__device__ float g_k[Bq*Hh*Nseq*DKd];
__device__ float g_v[Bq*Hh*Nseq*DKd];
__device__ float g_x[Bq*Nseq*3*Edim];
__device__ float g_h1[Bq*Nseq*Edim];
__device__ float g_wcat[3*Edim*Edim];
__device__ float g_bfull[Edim];
__device__ float g_zero[Edim];
__device__ float g_conv[(size_t)Bq*Hh*Nseq*Nseq];  // conv*SCALE, code in 2 LSBs
__device__ float g_tblA[Hh*256];                    // lerp slope  (×SCALE)
__device__ float g_tblB[Hh*256];                    // lerp offset (×SCALE)

// ---------------- tf32 helpers --------------------------------------------------
__device__ __forceinline__ float tf32_of(float f) {
    unsigned u;
    asm("cvt.rna.tf32.f32 %0, %1;" : "=r"(u) : "f"(f));
    return __uint_as_float(u);
}
__device__ __forceinline__ void mma_tf32(float* d, const unsigned* a,
                                         unsigned b0, unsigned b1) {
    asm volatile(
        "mma.sync.aligned.m16n8k8.row.col.f32.tf32.tf32.f32 "
        "{%0,%1,%2,%3}, {%4,%5,%6,%7}, {%8,%9}, {%0,%1,%2,%3};"
        : "+f"(d[0]), "+f"(d[1]), "+f"(d[2]), "+f"(d[3])
        : "r"(a[0]), "r"(a[1]), "r"(a[2]), "r"(a[3]), "r"(b0), "r"(b1));
}
__device__ __forceinline__ float fexp(float x) {
    float e = fmaf(x, 0.041666667f, 0.16666667f);
    e = fmaf(e, x, 0.5f);
    e = fmaf(e, x, 1.0f);
    e = fmaf(e, x, 1.0f);
    if (fabsf(x) > 0.25f) e = __expf(x);
    return e;
}

// ---------------- lerp table build: 256 bins x 8 heads -------------------------
__global__ void tbl_kernel(const float* __restrict__ cw1, const float* __restrict__ cb1,
                           const float* __restrict__ cw2, const float* __restrict__ cb2,
                           float* __restrict__ tblA, float* __restrict__ tblB)
{
    const int i = threadIdx.x;              // bin 0..255
    const float d0 = i * (1.0f/256.0f);
    const float d1 = (i+1) * (1.0f/256.0f);
    #pragma unroll
    for (int h = 0; h < 8; h++) {
        float f0 = cb2[h], f1 = cb2[h];
        #pragma unroll
        for (int t = 0; t < 8; t++) {
            float r0 = fmaxf(fmaf(d0, cw1[t], cb1[t]), 0.f);
            float r1 = fmaxf(fmaf(d1, cw1[t], cb1[t]), 0.f);
            f0 = fmaf(cw2[h*8 + t], r0, f0);
            f1 = fmaf(cw2[h*8 + t], r1, f1);
        }
        tblB[h*256 + i] = f0 * SCALE;
        tblA[h*256 + i] = (f1 - f0) * SCALE;
    }
}

// ---------------- conv precompute v2: table lerp + code in LSBs ----------------
__global__ __launch_bounds__(256) void conv_kernel(
    const float* __restrict__ dist, const int* __restrict__ mask,
    const float* __restrict__ tblA, const float* __restrict__ tblB,
    float* __restrict__ convp)
{
    __shared__ float sA[8][256], sB[8][256];
    const int tid = threadIdx.x;
    for (int t = tid; t < 2048; t += 256) {
        sA[t >> 8][t & 255] = tblA[t];
        sB[t >> 8][t & 255] = tblB[t];
    }
    __syncthreads();

    const int bi = blockIdx.x;               // b*512 + i
    const int b = bi >> 9, i = bi & 511;
    const float* drow = dist + (size_t)bi * Nseq;
    const int*   mrow = mask + (size_t)bi * Nseq;

    for (int j = tid; j < Nseq; j += 256) {
        float d = drow[j];
        int   m = mrow[j];
        unsigned code = (m == 0) ? 3u
                      : (i == 0 || j == 0) ? 0u
                      : (d < 0.3f) ? 0u : (d < 0.7f) ? 1u : 2u;
        float df = d * 256.0f;
        int idx = (int)df; idx = idx > 255 ? 255 : (idx < 0 ? 0 : idx);
        float frac = df - (float)idx;
        #pragma unroll
        for (int h = 0; h < 8; h++) {
            float c = fmaf(frac, sA[h][idx], sB[h][idx]);
            unsigned u = (__float_as_uint(c) & ~3u) | code;
            convp[(((size_t)(b*Hh + h) * Nseq + i) * Nseq) + j] = __uint_as_float(u);
        }
    }
}

// ---------------- tf32 mma GEMM (unchanged from R10) ---------------------------
__global__ __launch_bounds__(256) void gemm_tc(
    const float* __restrict__ A0, const float* __restrict__ A1, const float* __restrict__ A2,
    const float* __restrict__ W0, const float* __restrict__ W1, const float* __restrict__ W2,
    const float* __restrict__ bias0, const float* __restrict__ bias1, const float* __restrict__ bias2,
    float* __restrict__ C0, float* __restrict__ C1, float* __restrict__ C2,
    int Kd, int ldw, int ldc, int do_relu, int headsplit)
{
    const int z = blockIdx.z;
    const float* A    = (z == 0) ? A0 : (z == 1) ? A1 : A2;
    const float* W    = (z == 0) ? W0 : (z == 1) ? W1 : W2;
    const float* bias = (z == 0) ? bias0 : (z == 1) ? bias1 : bias2;
    float*       C    = (z == 0) ? C0 : (z == 1) ? C1 : C2;

    __shared__ float As[2][16][136];
    __shared__ float Ws[2][16][72];

    const int m0 = blockIdx.x << 7;
    const int n0 = blockIdx.y << 6;
    const int tid = threadIdx.x;
    const int warp = tid >> 5, lane = tid & 31;
    const int g = lane >> 2, r4 = lane & 3;
    const int mb = (warp & 3) << 5;
    const int nb = (warp >> 2) << 5;

    const int ar = tid >> 1;
    const int ac = (tid & 1) << 3;
    const int wr = tid >> 4;
    const int wc = (tid & 15) << 2;

    const float* Aptr = A + (size_t)(m0 + ar) * Kd + ac;
    const float* Wptr = W + (size_t)wr * ldw + n0 + wc;

    float4 a0p = *(const float4*)(Aptr);
    float4 a1p = *(const float4*)(Aptr + 4);
    float4 wp  = *(const float4*)(Wptr);

    float c[2][4][4] = {};

    As[0][ac+0][ar] = tf32_of(a0p.x); As[0][ac+1][ar] = tf32_of(a0p.y);
    As[0][ac+2][ar] = tf32_of(a0p.z); As[0][ac+3][ar] = tf32_of(a0p.w);
    As[0][ac+4][ar] = tf32_of(a1p.x); As[0][ac+5][ar] = tf32_of(a1p.y);
    As[0][ac+6][ar] = tf32_of(a1p.z); As[0][ac+7][ar] = tf32_of(a1p.w);
    Ws[0][wr][wc+0] = tf32_of(wp.x);  Ws[0][wr][wc+1] = tf32_of(wp.y);
    Ws[0][wr][wc+2] = tf32_of(wp.z);  Ws[0][wr][wc+3] = tf32_of(wp.w);
    __syncthreads();

    const int nk = Kd >> 4;
    for (int kt = 0; kt < nk; kt++) {
        const int cur = kt & 1, nxt = cur ^ 1;
        if (kt + 1 < nk) {
            a0p = *(const float4*)(Aptr + (kt+1)*16);
            a1p = *(const float4*)(Aptr + (kt+1)*16 + 4);
            wp  = *(const float4*)(Wptr + (size_t)(kt+1)*16*ldw);
        }
        #pragma unroll
        for (int ks = 0; ks < 2; ks++) {
            unsigned af[2][4], bf[4][2];
            #pragma unroll
            for (int mt = 0; mt < 2; mt++) {
                const int row = mb + mt*16 + g;
                af[mt][0] = __float_as_uint(As[cur][ks*8 + r4    ][row    ]);
                af[mt][1] = __float_as_uint(As[cur][ks*8 + r4    ][row + 8]);
                af[mt][2] = __float_as_uint(As[cur][ks*8 + r4 + 4][row    ]);
                af[mt][3] = __float_as_uint(As[cur][ks*8 + r4 + 4][row + 8]);
            }
            #pragma unroll
            for (int nt = 0; nt < 4; nt++) {
                const int col = nb + nt*8 + g;
                bf[nt][0] = __float_as_uint(Ws[cur][ks*8 + r4    ][col]);
                bf[nt][1] = __float_as_uint(Ws[cur][ks*8 + r4 + 4][col]);
            }
            #pragma unroll
            for (int mt = 0; mt < 2; mt++)
                #pragma unroll
                for (int nt = 0; nt < 4; nt++)
                    mma_tf32(c[mt][nt], af[mt], bf[nt][0], bf[nt][1]);
        }
        if (kt + 1 < nk) {
            As[nxt][ac+0][ar] = tf32_of(a0p.x); As[nxt][ac+1][ar] = tf32_of(a0p.y);
            As[nxt][ac+2][ar] = tf32_of(a0p.z); As[nxt][ac+3][ar] = tf32_of(a0p.w);
            As[nxt][ac+4][ar] = tf32_of(a1p.x); As[nxt][ac+5][ar] = tf32_of(a1p.y);
            As[nxt][ac+6][ar] = tf32_of(a1p.z); As[nxt][ac+7][ar] = tf32_of(a1p.w);
            Ws[nxt][wr][wc+0] = tf32_of(wp.x);  Ws[nxt][wr][wc+1] = tf32_of(wp.y);
            Ws[nxt][wr][wc+2] = tf32_of(wp.z);  Ws[nxt][wr][wc+3] = tf32_of(wp.w);
        }
        __syncthreads();
    }

    #pragma unroll
    for (int nt = 0; nt < 4; nt++) {
        const int col0 = n0 + nb + nt*8 + 2*r4;
        const float2 bb = *(const float2*)&bias[col0];
        #pragma unroll
        for (int mt = 0; mt < 2; mt++) {
            const int row0 = m0 + mb + mt*16 + g;
            float2 v0 = make_float2(c[mt][nt][0] + bb.x, c[mt][nt][1] + bb.y);
            float2 v1 = make_float2(c[mt][nt][2] + bb.x, c[mt][nt][3] + bb.y);
            if (do_relu) {
                v0.x = fmaxf(v0.x, 0.f); v0.y = fmaxf(v0.y, 0.f);
                v1.x = fmaxf(v1.x, 0.f); v1.y = fmaxf(v1.y, 0.f);
            }
            if (headsplit) {
                v0.x = tf32_of(v0.x); v0.y = tf32_of(v0.y);
                v1.x = tf32_of(v1.x); v1.y = tf32_of(v1.y);
                const int h = col0 >> 5, d = col0 & 31;
                int b = row0 >> 9, n = row0 & 511;
                *(float2*)&C[(((size_t)(b*Hh + h))*Nseq + n)*DKd + d] = v0;
                b = (row0+8) >> 9; n = (row0+8) & 511;
                *(float2*)&C[(((size_t)(b*Hh + h))*Nseq + n)*DKd + d] = v1;
            } else {
                *(float2*)&C[(size_t)row0 * ldc + col0] = v0;
                *(float2*)&C[(size_t)(row0+8) * ldc + col0] = v1;
            }
        }
    }
}

// ---------------- bias fold v2: parallel, deterministic ------------------------
// grid = 4 blocks x 256 threads. Block owns 64 n-columns; threads split 768 rows
// four ways (coalesced), reduce via smem. ~3 us instead of 63 us single-block.
__global__ __launch_bounds__(256) void bias_fold(
    const float* __restrict__ bo, const float* __restrict__ Ws1,
    const float* __restrict__ bs1, float* __restrict__ bfull)
{
    __shared__ float red[4][64];
    const int nl = threadIdx.x & 63;
    const int rg = threadIdx.x >> 6;          // 0..3
    const int n  = blockIdx.x * 64 + nl;
    float s = 0.f;
    for (int r = rg; r < 3*Edim; r += 4)
        s = fmaf(bo[r & (Edim-1)], Ws1[(size_t)r * Edim + n], s);
    red[rg][nl] = s;
    __syncthreads();
    if (rg == 0)
        bfull[n] = bs1[n] + ((red[0][nl] + red[1][nl]) + (red[2][nl] + red[3][nl]));
}

// ---------------- tf32 mma attention (unchanged from R10) ----------------------
#define ATTN_SMEM 98304

__global__ __launch_bounds__(256) void attn_mma(
    const float* __restrict__ Q, const float* __restrict__ K, const float* __restrict__ V,
    const float* __restrict__ convp, float* __restrict__ xcat)
{
    extern __shared__ float sm[];
    float (*Qs)[36] = (float(*)[36])(sm);
    float (*Ks)[36] = (float(*)[36])(sm + 2304);
    float (*Vt)[68] = (float(*)[68])(sm + 4608);
    float*  E3      = sm + 6784;
    float*  lsA     = sm + 24192;
    float*  lsB     = sm + 24384;

    const int qt = blockIdx.x;
    const int bh = blockIdx.y;
    const int b = bh >> 3, h = bh & 7;
    const int q0 = qt << 6;
    const int tid = threadIdx.x;
    const int warp = tid >> 5, lane = tid & 31;
    const int g = lane >> 2, r4 = lane & 3;
    const int wg = warp >> 2;
    const int mwarp = warp & 3;
    const int mrow = mwarp << 4;
    const int keybase = wg << 5;

    const size_t headbase = (size_t)bh * Nseq * DKd;

    const float* Qb = Q + headbase + (size_t)q0 * DKd;
    #pragma unroll
    for (int i = 0; i < 2; i++) {
        int idx = tid + i*256;
        int row = idx >> 3, c4 = (idx & 7) << 2;
        *(float4*)&Qs[row][c4] = *(const float4*)&Qb[row*32 + c4];
    }
    __syncthreads();

    unsigned qa[4][4];
    #pragma unroll
    for (int ks = 0; ks < 4; ks++) {
        qa[ks][0] = __float_as_uint(Qs[mrow + g    ][ks*8 + r4    ]);
        qa[ks][1] = __float_as_uint(Qs[mrow + g + 8][ks*8 + r4    ]);
        qa[ks][2] = __float_as_uint(Qs[mrow + g    ][ks*8 + r4 + 4]);
        qa[ks][3] = __float_as_uint(Qs[mrow + g + 8][ks*8 + r4 + 4]);
    }

    float o[3][4][4] = {};
    float lsum[3][2] = {};

    const float* cbase = convp + ((size_t)bh * Nseq + q0 + mrow) * Nseq;

    for (int kt = 0; kt < 8; kt++) {
        const int k0 = kt << 6;
        const float* Kb = K + headbase + (size_t)k0 * DKd;
        const float* Vb = V + headbase + (size_t)k0 * DKd;
        __syncthreads();
        #pragma unroll
        for (int i = 0; i < 2; i++) {
            int idx = tid + i*256;
            int row = idx >> 3, c4 = (idx & 7) << 2;
            *(float4*)&Ks[row][c4] = *(const float4*)&Kb[row*32 + c4];
            float4 vv = *(const float4*)&Vb[row*32 + c4];
            Vt[c4+0][row] = vv.x; Vt[c4+1][row] = vv.y;
            Vt[c4+2][row] = vv.z; Vt[c4+3][row] = vv.w;
        }
        __syncthreads();

        float s[4][4] = {};
        #pragma unroll
        for (int ks = 0; ks < 4; ks++) {
            #pragma unroll
            for (int nt = 0; nt < 4; nt++) {
                unsigned b0 = __float_as_uint(Ks[keybase + nt*8 + g][ks*8 + r4    ]);
                unsigned b1 = __float_as_uint(Ks[keybase + nt*8 + g][ks*8 + r4 + 4]);
                mma_tf32(s[nt], qa[ks], b0, b1);
            }
        }

        #pragma unroll
        for (int nt = 0; nt < 4; nt++) {
            #pragma unroll
            for (int rr = 0; rr < 2; rr++) {
                const int trow = mrow + g + rr*8;
                const int col = keybase + nt*8 + 2*r4;
                const float2 c2 = *(const float2*)&cbase[(size_t)(g + rr*8) * Nseq
                                                         + k0 + col];
                float sx = s[nt][rr*2 + 0], sy = s[nt][rr*2 + 1];
                unsigned cx = __float_as_uint(c2.x) & 3u;
                unsigned cy = __float_as_uint(c2.y) & 3u;
                float ex = fexp(sx * c2.x);
                float ey = fexp(sy * c2.y);
                ex = (cx == 3u) ? 0.f : ex;
                ey = (cy == 3u) ? 0.f : ey;
                float ex1 = (cx < 2u) ? ex : 0.f;
                float ey1 = (cy < 2u) ? ey : 0.f;
                float ex0 = (cx == 0u) ? ex : 0.f;
                float ey0 = (cy == 0u) ? ey : 0.f;
                lsum[2][rr] += ex + ey;
                lsum[1][rr] += ex1 + ey1;
                lsum[0][rr] += ex0 + ey0;
                *(float4*)&E3[trow*272 + col*4] =
                    make_float4(tf32_of(ex),  tf32_of(ex1), tf32_of(ex0), 0.f);
                *(float4*)&E3[trow*272 + (col+1)*4] =
                    make_float4(tf32_of(ey),  tf32_of(ey1), tf32_of(ey0), 0.f);
            }
        }
        __syncthreads();

        #pragma unroll
        for (int ks = 0; ks < 4; ks++) {
            const int kk = keybase + ks*8;
            unsigned vb[4][2];
            #pragma unroll
            for (int nt = 0; nt < 4; nt++) {
                vb[nt][0] = __float_as_uint(Vt[nt*8 + g][kk + r4    ]);
                vb[nt][1] = __float_as_uint(Vt[nt*8 + g][kk + r4 + 4]);
            }
            float4 f00 = *(const float4*)&E3[(mrow + g    )*272 + (kk + r4    )*4];
            float4 f10 = *(const float4*)&E3[(mrow + g + 8)*272 + (kk + r4    )*4];
            float4 f01 = *(const float4*)&E3[(mrow + g    )*272 + (kk + r4 + 4)*4];
            float4 f11 = *(const float4*)&E3[(mrow + g + 8)*272 + (kk + r4 + 4)*4];
            unsigned a[4];
            a[0]=__float_as_uint(f00.x); a[1]=__float_as_uint(f10.x);
            a[2]=__float_as_uint(f01.x); a[3]=__float_as_uint(f11.x);
            #pragma unroll
            for (int nt = 0; nt < 4; nt++) mma_tf32(o[2][nt], a, vb[nt][0], vb[nt][1]);
            a[0]=__float_as_uint(f00.y); a[1]=__float_as_uint(f10.y);
            a[2]=__float_as_uint(f01.y); a[3]=__float_as_uint(f11.y);
            #pragma unroll
            for (int nt = 0; nt < 4; nt++) mma_tf32(o[1][nt], a, vb[nt][0], vb[nt][1]);
            a[0]=__float_as_uint(f00.z); a[1]=__float_as_uint(f10.z);
            a[2]=__float_as_uint(f01.z); a[3]=__float_as_uint(f11.z);
            #pragma unroll
            for (int nt = 0; nt < 4; nt++) mma_tf32(o[0][nt], a, vb[nt][0], vb[nt][1]);
        }
    }

    float* lsX = wg ? lsB : lsA;
    #pragma unroll
    for (int bar = 0; bar < 3; bar++)
        #pragma unroll
        for (int rr = 0; rr < 2; rr++) {
            float v = lsum[bar][rr];
            v += __shfl_xor_sync(0xffffffffu, v, 1);
            v += __shfl_xor_sync(0xffffffffu, v, 2);
            if (r4 == 0) lsX[bar*64 + mrow + g + rr*8] = v;
        }

    if (wg == 1) {
        const int idx = tid - 128;
        #pragma unroll
        for (int bar = 0; bar < 3; bar++)
            #pragma unroll
            for (int nt = 0; nt < 4; nt++)
                *(float4*)&E3[(idx*12 + bar*4 + nt)*4] =
                    make_float4(o[bar][nt][0], o[bar][nt][1], o[bar][nt][2], o[bar][nt][3]);
    }
    __syncthreads();

    if (wg == 0) {
        const int idx = tid;
        const int rowA = q0 + mrow + g;
        const int rowB = rowA + 8;
        #pragma unroll
        for (int bar = 0; bar < 3; bar++) {
            const float rlA = 1.f / (lsA[bar*64 + mrow + g    ] + lsB[bar*64 + mrow + g    ]);
            const float rlB = 1.f / (lsA[bar*64 + mrow + g + 8] + lsB[bar*64 + mrow + g + 8]);
            #pragma unroll
            for (int nt = 0; nt < 4; nt++) {
                float4 p = *(const float4*)&E3[(idx*12 + bar*4 + nt)*4];
                const int col = bar*Edim + h*DKd + nt*8 + 2*r4;
                size_t baseA = ((size_t)b*Nseq + rowA) * (3*Edim) + col;
                size_t baseB = ((size_t)b*Nseq + rowB) * (3*Edim) + col;
                *(float2*)&xcat[baseA] = make_float2((o[bar][nt][0] + p.x)*rlA,
                                                     (o[bar][nt][1] + p.y)*rlA);
                *(float2*)&xcat[baseB] = make_float2((o[bar][nt][2] + p.z)*rlB,
                                                     (o[bar][nt][3] + p.w)*rlB);
            }
        }
    }
}

// ---------------- host launcher ----------------------------------------------
extern "C" void kernel_launch(void* const* d_in, const int* in_sizes, int n_in,
                              void* d_out, int out_size)
{
    const float* query = (const float*)d_in[0];
    const float* key   = (const float*)d_in[1];
    const float* value = (const float*)d_in[2];
    const float* dist  = (const float*)d_in[3];
    const int*   mask  = (const int*)d_in[4];
    const float* Wq = (const float*)d_in[5];
    const float* bq = (const float*)d_in[6];
    const float* Wk = (const float*)d_in[7];
    const float* bk = (const float*)d_in[8];
    const float* Wv = (const float*)d_in[9];
    const float* bv = (const float*)d_in[10];
    const float* Wo = (const float*)d_in[11];
    const float* bo = (const float*)d_in[12];
    const float* cw1 = (const float*)d_in[13];
    const float* cb1 = (const float*)d_in[14];
    const float* cw2 = (const float*)d_in[15];
    const float* cb2 = (const float*)d_in[16];
    const float* Ws1 = (const float*)d_in[17];
    const float* bs1 = (const float*)d_in[18];
    const float* Ws2 = (const float*)d_in[19];
    const float* bs2 = (const float*)d_in[20];
    float* out = (float*)d_out;

    float *q_p, *k_p, *v_p, *x_p, *h1_p, *wcat_p, *bfull_p, *zero_p, *conv_p;
    float *tA_p, *tB_p;
    cudaGetSymbolAddress((void**)&q_p,    g_q);
    cudaGetSymbolAddress((void**)&k_p,    g_k);
    cudaGetSymbolAddress((void**)&v_p,    g_v);
    cudaGetSymbolAddress((void**)&x_p,    g_x);
    cudaGetSymbolAddress((void**)&h1_p,   g_h1);
    cudaGetSymbolAddress((void**)&wcat_p, g_wcat);
    cudaGetSymbolAddress((void**)&bfull_p,g_bfull);
    cudaGetSymbolAddress((void**)&zero_p, g_zero);
    cudaGetSymbolAddress((void**)&conv_p, g_conv);
    cudaGetSymbolAddress((void**)&tA_p,   g_tblA);
    cudaGetSymbolAddress((void**)&tB_p,   g_tblB);

    cudaFuncSetAttribute(attn_mma,
                         cudaFuncAttributeMaxDynamicSharedMemorySize, ATTN_SMEM);

    const int M = Bq * Nseq;          // 4096
    dim3 blk(256);

    // lerp table then conv precompute
    tbl_kernel<<<1, 256>>>(cw1, cb1, cw2, cb2, tA_p, tB_p);
    conv_kernel<<<Bq * Nseq, blk>>>(dist, mask, tA_p, tB_p, conv_p);

    // Wcat = [Wo @ Ws1_bar] and folded bias (parallel)
    {
        dim3 grid(Edim / 128, Edim / 64, 3);
        gemm_tc<<<grid, blk>>>(Wo, Wo, Wo,
                               Ws1, Ws1 + Edim*Edim, Ws1 + 2*Edim*Edim,
                               zero_p, zero_p, zero_p,
                               wcat_p, wcat_p + Edim*Edim, wcat_p + 2*Edim*Edim,
                               Edim, Edim, Edim, 0, 0);
        bias_fold<<<Edim / 64, 256>>>(bo, Ws1, bs1, bfull_p);
    }

    // QKV projections -> (B,H,N,DK), z-batched, outputs tf32-rounded
    {
        dim3 grid(M / 128, Edim / 64, 3);
        gemm_tc<<<grid, blk>>>(query, key, value,
                               Wq, Wk, Wv,
                               bq, bk, bv,
                               q_p, k_p, v_p,
                               Edim, Edim, 0, 0, 1);
    }

    // tf32 mma attention -> concat g_x (B,N,768)
    {
        dim3 grid(Nseq / 64, Bq * Hh);
        attn_mma<<<grid, 256, ATTN_SMEM>>>(q_p, k_p, v_p, conv_p, x_p);
    }

    // h1 = relu(xcat @ Wcat + bfull)
    {
        dim3 grid(M / 128, Edim / 64, 1);
        gemm_tc<<<grid, blk>>>(x_p, x_p, x_p, wcat_p, wcat_p, wcat_p,
                               bfull_p, bfull_p, bfull_p,
                               h1_p, h1_p, h1_p, 3*Edim, Edim, Edim, 1, 0);
    }

    // out = h1 @ Ws2 + bs2
    {
        dim3 grid(M / 128, Edim / 64, 1);
        gemm_tc<<<grid, blk>>>(h1_p, h1_p, h1_p, Ws2, Ws2, Ws2, bs2, bs2, bs2,
                               out, out, out, Edim, Edim, Edim, 0, 0);
    }
}

// round 12
// speedup vs baseline: 2.1172x; 1.1753x over previous
#include <cuda_runtime.h>
#include <math.h>

#define Bq   8
#define Nseq 512
#define Edim 256
#define Hh   8
#define DKd  32
#define SCALE 0.17677669529663687f   // 1/sqrt(32)

typedef unsigned long long ull;

// ---------------- scratch (device globals) ------------------------------------
__device__ float g_q[Bq*Hh*Nseq*DKd];
__device__ float g_k[Bq*Hh*Nseq*DKd];
__device__ float g_v[Bq*Hh*Nseq*DKd];
__device__ float g_x[Bq*Nseq*3*Edim];
__device__ float g_h1[Bq*Nseq*Edim];
__device__ float g_wcat[3*Edim*Edim];
__device__ float g_bfull[Edim];
__device__ float g_zero[Edim];
__device__ float g_conv[(size_t)Bq*Hh*Nseq*Nseq];  // conv*SCALE, code in 2 LSBs
__device__ float g_tblA[Hh*256];                    // lerp slope  (×SCALE)
__device__ float g_tblB[Hh*256];                    // lerp offset (×SCALE)

// ---------------- tf32 helpers --------------------------------------------------
__device__ __forceinline__ float tf32_of(float f) {
    unsigned u;
    asm("cvt.rna.tf32.f32 %0, %1;" : "=r"(u) : "f"(f));
    return __uint_as_float(u);
}
__device__ __forceinline__ void mma_tf32(float* d, const unsigned* a,
                                         unsigned b0, unsigned b1) {
    asm volatile(
        "mma.sync.aligned.m16n8k8.row.col.f32.tf32.tf32.f32 "
        "{%0,%1,%2,%3}, {%4,%5,%6,%7}, {%8,%9}, {%0,%1,%2,%3};"
        : "+f"(d[0]), "+f"(d[1]), "+f"(d[2]), "+f"(d[3])
        : "r"(a[0]), "r"(a[1]), "r"(a[2]), "r"(a[3]), "r"(b0), "r"(b1));
}
__device__ __forceinline__ float fexp(float x) {
    float e = fmaf(x, 0.041666667f, 0.16666667f);
    e = fmaf(e, x, 0.5f);
    e = fmaf(e, x, 1.0f);
    e = fmaf(e, x, 1.0f);
    if (fabsf(x) > 0.25f) e = __expf(x);
    return e;
}

// ---------------- lerp table build: 256 bins x 8 heads -------------------------
__global__ void tbl_kernel(const float* __restrict__ cw1, const float* __restrict__ cb1,
                           const float* __restrict__ cw2, const float* __restrict__ cb2,
                           float* __restrict__ tblA, float* __restrict__ tblB)
{
    const int i = threadIdx.x;              // bin 0..255
    const float d0 = i * (1.0f/256.0f);
    const float d1 = (i+1) * (1.0f/256.0f);
    #pragma unroll
    for (int h = 0; h < 8; h++) {
        float f0 = cb2[h], f1 = cb2[h];
        #pragma unroll
        for (int t = 0; t < 8; t++) {
            float r0 = fmaxf(fmaf(d0, cw1[t], cb1[t]), 0.f);
            float r1 = fmaxf(fmaf(d1, cw1[t], cb1[t]), 0.f);
            f0 = fmaf(cw2[h*8 + t], r0, f0);
            f1 = fmaf(cw2[h*8 + t], r1, f1);
        }
        tblB[h*256 + i] = f0 * SCALE;
        tblA[h*256 + i] = (f1 - f0) * SCALE;
    }
}

// ---------------- conv precompute v3: 4 rows per block -------------------------
__global__ __launch_bounds__(256) void conv_kernel(
    const float* __restrict__ dist, const int* __restrict__ mask,
    const float* __restrict__ tblA, const float* __restrict__ tblB,
    float* __restrict__ convp)
{
    __shared__ float sA[8][256], sB[8][256];
    const int tid = threadIdx.x;
    for (int t = tid; t < 2048; t += 256) {
        sA[t >> 8][t & 255] = tblA[t];
        sB[t >> 8][t & 255] = tblB[t];
    }
    __syncthreads();

    const int bi4 = blockIdx.x;              // b*128 + i/4
    const int b  = bi4 >> 7;
    const int i0 = (bi4 & 127) << 2;

    #pragma unroll
    for (int ri = 0; ri < 4; ri++) {
        const int i = i0 + ri;
        const float* drow = dist + ((size_t)b * Nseq + i) * Nseq;
        const int*   mrow = mask + ((size_t)b * Nseq + i) * Nseq;
        for (int j = tid; j < Nseq; j += 256) {
            float d = drow[j];
            int   m = mrow[j];
            unsigned code = (m == 0) ? 3u
                          : (i == 0 || j == 0) ? 0u
                          : (d < 0.3f) ? 0u : (d < 0.7f) ? 1u : 2u;
            float df = d * 256.0f;
            int idx = (int)df; idx = idx > 255 ? 255 : (idx < 0 ? 0 : idx);
            float frac = df - (float)idx;
            #pragma unroll
            for (int h = 0; h < 8; h++) {
                float c = fmaf(frac, sA[h][idx], sB[h][idx]);
                unsigned u = (__float_as_uint(c) & ~3u) | code;
                convp[(((size_t)(b*Hh + h) * Nseq + i) * Nseq) + j] = __uint_as_float(u);
            }
        }
    }
}

// ---------------- tf32 mma GEMM (unchanged) ------------------------------------
__global__ __launch_bounds__(256) void gemm_tc(
    const float* __restrict__ A0, const float* __restrict__ A1, const float* __restrict__ A2,
    const float* __restrict__ W0, const float* __restrict__ W1, const float* __restrict__ W2,
    const float* __restrict__ bias0, const float* __restrict__ bias1, const float* __restrict__ bias2,
    float* __restrict__ C0, float* __restrict__ C1, float* __restrict__ C2,
    int Kd, int ldw, int ldc, int do_relu, int headsplit)
{
    const int z = blockIdx.z;
    const float* A    = (z == 0) ? A0 : (z == 1) ? A1 : A2;
    const float* W    = (z == 0) ? W0 : (z == 1) ? W1 : W2;
    const float* bias = (z == 0) ? bias0 : (z == 1) ? bias1 : bias2;
    float*       C    = (z == 0) ? C0 : (z == 1) ? C1 : C2;

    __shared__ float As[2][16][136];
    __shared__ float Ws[2][16][72];

    const int m0 = blockIdx.x << 7;
    const int n0 = blockIdx.y << 6;
    const int tid = threadIdx.x;
    const int warp = tid >> 5, lane = tid & 31;
    const int g = lane >> 2, r4 = lane & 3;
    const int mb = (warp & 3) << 5;
    const int nb = (warp >> 2) << 5;

    const int ar = tid >> 1;
    const int ac = (tid & 1) << 3;
    const int wr = tid >> 4;
    const int wc = (tid & 15) << 2;

    const float* Aptr = A + (size_t)(m0 + ar) * Kd + ac;
    const float* Wptr = W + (size_t)wr * ldw + n0 + wc;

    float4 a0p = *(const float4*)(Aptr);
    float4 a1p = *(const float4*)(Aptr + 4);
    float4 wp  = *(const float4*)(Wptr);

    float c[2][4][4] = {};

    As[0][ac+0][ar] = tf32_of(a0p.x); As[0][ac+1][ar] = tf32_of(a0p.y);
    As[0][ac+2][ar] = tf32_of(a0p.z); As[0][ac+3][ar] = tf32_of(a0p.w);
    As[0][ac+4][ar] = tf32_of(a1p.x); As[0][ac+5][ar] = tf32_of(a1p.y);
    As[0][ac+6][ar] = tf32_of(a1p.z); As[0][ac+7][ar] = tf32_of(a1p.w);
    Ws[0][wr][wc+0] = tf32_of(wp.x);  Ws[0][wr][wc+1] = tf32_of(wp.y);
    Ws[0][wr][wc+2] = tf32_of(wp.z);  Ws[0][wr][wc+3] = tf32_of(wp.w);
    __syncthreads();

    const int nk = Kd >> 4;
    for (int kt = 0; kt < nk; kt++) {
        const int cur = kt & 1, nxt = cur ^ 1;
        if (kt + 1 < nk) {
            a0p = *(const float4*)(Aptr + (kt+1)*16);
            a1p = *(const float4*)(Aptr + (kt+1)*16 + 4);
            wp  = *(const float4*)(Wptr + (size_t)(kt+1)*16*ldw);
        }
        #pragma unroll
        for (int ks = 0; ks < 2; ks++) {
            unsigned af[2][4], bf[4][2];
            #pragma unroll
            for (int mt = 0; mt < 2; mt++) {
                const int row = mb + mt*16 + g;
                af[mt][0] = __float_as_uint(As[cur][ks*8 + r4    ][row    ]);
                af[mt][1] = __float_as_uint(As[cur][ks*8 + r4    ][row + 8]);
                af[mt][2] = __float_as_uint(As[cur][ks*8 + r4 + 4][row    ]);
                af[mt][3] = __float_as_uint(As[cur][ks*8 + r4 + 4][row + 8]);
            }
            #pragma unroll
            for (int nt = 0; nt < 4; nt++) {
                const int col = nb + nt*8 + g;
                bf[nt][0] = __float_as_uint(Ws[cur][ks*8 + r4    ][col]);
                bf[nt][1] = __float_as_uint(Ws[cur][ks*8 + r4 + 4][col]);
            }
            #pragma unroll
            for (int mt = 0; mt < 2; mt++)
                #pragma unroll
                for (int nt = 0; nt < 4; nt++)
                    mma_tf32(c[mt][nt], af[mt], bf[nt][0], bf[nt][1]);
        }
        if (kt + 1 < nk) {
            As[nxt][ac+0][ar] = tf32_of(a0p.x); As[nxt][ac+1][ar] = tf32_of(a0p.y);
            As[nxt][ac+2][ar] = tf32_of(a0p.z); As[nxt][ac+3][ar] = tf32_of(a0p.w);
            As[nxt][ac+4][ar] = tf32_of(a1p.x); As[nxt][ac+5][ar] = tf32_of(a1p.y);
            As[nxt][ac+6][ar] = tf32_of(a1p.z); As[nxt][ac+7][ar] = tf32_of(a1p.w);
            Ws[nxt][wr][wc+0] = tf32_of(wp.x);  Ws[nxt][wr][wc+1] = tf32_of(wp.y);
            Ws[nxt][wr][wc+2] = tf32_of(wp.z);  Ws[nxt][wr][wc+3] = tf32_of(wp.w);
        }
        __syncthreads();
    }

    #pragma unroll
    for (int nt = 0; nt < 4; nt++) {
        const int col0 = n0 + nb + nt*8 + 2*r4;
        const float2 bb = *(const float2*)&bias[col0];
        #pragma unroll
        for (int mt = 0; mt < 2; mt++) {
            const int row0 = m0 + mb + mt*16 + g;
            float2 v0 = make_float2(c[mt][nt][0] + bb.x, c[mt][nt][1] + bb.y);
            float2 v1 = make_float2(c[mt][nt][2] + bb.x, c[mt][nt][3] + bb.y);
            if (do_relu) {
                v0.x = fmaxf(v0.x, 0.f); v0.y = fmaxf(v0.y, 0.f);
                v1.x = fmaxf(v1.x, 0.f); v1.y = fmaxf(v1.y, 0.f);
            }
            if (headsplit) {
                v0.x = tf32_of(v0.x); v0.y = tf32_of(v0.y);
                v1.x = tf32_of(v1.x); v1.y = tf32_of(v1.y);
                const int h = col0 >> 5, d = col0 & 31;
                int b = row0 >> 9, n = row0 & 511;
                *(float2*)&C[(((size_t)(b*Hh + h))*Nseq + n)*DKd + d] = v0;
                b = (row0+8) >> 9; n = (row0+8) & 511;
                *(float2*)&C[(((size_t)(b*Hh + h))*Nseq + n)*DKd + d] = v1;
            } else {
                *(float2*)&C[(size_t)row0 * ldc + col0] = v0;
                *(float2*)&C[(size_t)(row0+8) * ldc + col0] = v1;
            }
        }
    }
}

// ---------------- bias fold v3: grid=16, short chains --------------------------
__global__ __launch_bounds__(256) void bias_fold(
    const float* __restrict__ bo, const float* __restrict__ Ws1,
    const float* __restrict__ bs1, float* __restrict__ bfull)
{
    __shared__ float red[16][16];
    const int nl = threadIdx.x & 15;
    const int rg = threadIdx.x >> 4;          // 0..15
    const int n  = blockIdx.x * 16 + nl;
    float s = 0.f;
    for (int r = rg; r < 3*Edim; r += 16)     // 48 iterations
        s = fmaf(bo[r & (Edim-1)], Ws1[(size_t)r * Edim + n], s);
    red[rg][nl] = s;
    __syncthreads();
    if (rg == 0) {
        float t = 0.f;
        #pragma unroll
        for (int k = 0; k < 16; k++) t += red[k][nl];
        bfull[n] = bs1[n] + t;
    }
}

// ---------------- tf32 mma attention (+ conv register prefetch) ----------------
#define ATTN_SMEM 98304

__global__ __launch_bounds__(256, 2) void attn_mma(
    const float* __restrict__ Q, const float* __restrict__ K, const float* __restrict__ V,
    const float* __restrict__ convp, float* __restrict__ xcat)
{
    extern __shared__ float sm[];
    float (*Qs)[36] = (float(*)[36])(sm);
    float (*Ks)[36] = (float(*)[36])(sm + 2304);
    float (*Vt)[68] = (float(*)[68])(sm + 4608);
    float*  E3      = sm + 6784;
    float*  lsA     = sm + 24192;
    float*  lsB     = sm + 24384;

    const int qt = blockIdx.x;
    const int bh = blockIdx.y;
    const int b = bh >> 3, h = bh & 7;
    const int q0 = qt << 6;
    const int tid = threadIdx.x;
    const int warp = tid >> 5, lane = tid & 31;
    const int g = lane >> 2, r4 = lane & 3;
    const int wg = warp >> 2;
    const int mwarp = warp & 3;
    const int mrow = mwarp << 4;
    const int keybase = wg << 5;

    const size_t headbase = (size_t)bh * Nseq * DKd;

    const float* Qb = Q + headbase + (size_t)q0 * DKd;
    #pragma unroll
    for (int i = 0; i < 2; i++) {
        int idx = tid + i*256;
        int row = idx >> 3, c4 = (idx & 7) << 2;
        *(float4*)&Qs[row][c4] = *(const float4*)&Qb[row*32 + c4];
    }
    __syncthreads();

    unsigned qa[4][4];
    #pragma unroll
    for (int ks = 0; ks < 4; ks++) {
        qa[ks][0] = __float_as_uint(Qs[mrow + g    ][ks*8 + r4    ]);
        qa[ks][1] = __float_as_uint(Qs[mrow + g + 8][ks*8 + r4    ]);
        qa[ks][2] = __float_as_uint(Qs[mrow + g    ][ks*8 + r4 + 4]);
        qa[ks][3] = __float_as_uint(Qs[mrow + g + 8][ks*8 + r4 + 4]);
    }

    float o[3][4][4] = {};
    float lsum[3][2] = {};

    const float* cbase = convp + ((size_t)bh * Nseq + q0 + mrow) * Nseq;

    for (int kt = 0; kt < 8; kt++) {
        const int k0 = kt << 6;
        const float* Kb = K + headbase + (size_t)k0 * DKd;
        const float* Vb = V + headbase + (size_t)k0 * DKd;
        __syncthreads();
        #pragma unroll
        for (int i = 0; i < 2; i++) {
            int idx = tid + i*256;
            int row = idx >> 3, c4 = (idx & 7) << 2;
            *(float4*)&Ks[row][c4] = *(const float4*)&Kb[row*32 + c4];
            float4 vv = *(const float4*)&Vb[row*32 + c4];
            Vt[c4+0][row] = vv.x; Vt[c4+1][row] = vv.y;
            Vt[c4+2][row] = vv.z; Vt[c4+3][row] = vv.w;
        }

        // prefetch conv pairs (address-independent of staged data) to overlap
        // L2 latency with the staging barrier + QK mma
        float2 cc[4][2];
        #pragma unroll
        for (int nt = 0; nt < 4; nt++)
            #pragma unroll
            for (int rr = 0; rr < 2; rr++)
                cc[nt][rr] = *(const float2*)&cbase[(size_t)(g + rr*8) * Nseq
                                                    + k0 + keybase + nt*8 + 2*r4];
        __syncthreads();

        float s[4][4] = {};
        #pragma unroll
        for (int ks = 0; ks < 4; ks++) {
            #pragma unroll
            for (int nt = 0; nt < 4; nt++) {
                unsigned b0 = __float_as_uint(Ks[keybase + nt*8 + g][ks*8 + r4    ]);
                unsigned b1 = __float_as_uint(Ks[keybase + nt*8 + g][ks*8 + r4 + 4]);
                mma_tf32(s[nt], qa[ks], b0, b1);
            }
        }

        #pragma unroll
        for (int nt = 0; nt < 4; nt++) {
            #pragma unroll
            for (int rr = 0; rr < 2; rr++) {
                const int trow = mrow + g + rr*8;
                const int col = keybase + nt*8 + 2*r4;
                const float2 c2 = cc[nt][rr];
                float sx = s[nt][rr*2 + 0], sy = s[nt][rr*2 + 1];
                unsigned cx = __float_as_uint(c2.x) & 3u;
                unsigned cy = __float_as_uint(c2.y) & 3u;
                float ex = fexp(sx * c2.x);
                float ey = fexp(sy * c2.y);
                ex = (cx == 3u) ? 0.f : ex;
                ey = (cy == 3u) ? 0.f : ey;
                float ex1 = (cx < 2u) ? ex : 0.f;
                float ey1 = (cy < 2u) ? ey : 0.f;
                float ex0 = (cx == 0u) ? ex : 0.f;
                float ey0 = (cy == 0u) ? ey : 0.f;
                lsum[2][rr] += ex + ey;
                lsum[1][rr] += ex1 + ey1;
                lsum[0][rr] += ex0 + ey0;
                *(float4*)&E3[trow*272 + col*4] =
                    make_float4(tf32_of(ex),  tf32_of(ex1), tf32_of(ex0), 0.f);
                *(float4*)&E3[trow*272 + (col+1)*4] =
                    make_float4(tf32_of(ey),  tf32_of(ey1), tf32_of(ey0), 0.f);
            }
        }
        __syncthreads();

        #pragma unroll
        for (int ks = 0; ks < 4; ks++) {
            const int kk = keybase + ks*8;
            unsigned vb[4][2];
            #pragma unroll
            for (int nt = 0; nt < 4; nt++) {
                vb[nt][0] = __float_as_uint(Vt[nt*8 + g][kk + r4    ]);
                vb[nt][1] = __float_as_uint(Vt[nt*8 + g][kk + r4 + 4]);
            }
            float4 f00 = *(const float4*)&E3[(mrow + g    )*272 + (kk + r4    )*4];
            float4 f10 = *(const float4*)&E3[(mrow + g + 8)*272 + (kk + r4    )*4];
            float4 f01 = *(const float4*)&E3[(mrow + g    )*272 + (kk + r4 + 4)*4];
            float4 f11 = *(const float4*)&E3[(mrow + g + 8)*272 + (kk + r4 + 4)*4];
            unsigned a[4];
            a[0]=__float_as_uint(f00.x); a[1]=__float_as_uint(f10.x);
            a[2]=__float_as_uint(f01.x); a[3]=__float_as_uint(f11.x);
            #pragma unroll
            for (int nt = 0; nt < 4; nt++) mma_tf32(o[2][nt], a, vb[nt][0], vb[nt][1]);
            a[0]=__float_as_uint(f00.y); a[1]=__float_as_uint(f10.y);
            a[2]=__float_as_uint(f01.y); a[3]=__float_as_uint(f11.y);
            #pragma unroll
            for (int nt = 0; nt < 4; nt++) mma_tf32(o[1][nt], a, vb[nt][0], vb[nt][1]);
            a[0]=__float_as_uint(f00.z); a[1]=__float_as_uint(f10.z);
            a[2]=__float_as_uint(f01.z); a[3]=__float_as_uint(f11.z);
            #pragma unroll
            for (int nt = 0; nt < 4; nt++) mma_tf32(o[0][nt], a, vb[nt][0], vb[nt][1]);
        }
    }

    float* lsX = wg ? lsB : lsA;
    #pragma unroll
    for (int bar = 0; bar < 3; bar++)
        #pragma unroll
        for (int rr = 0; rr < 2; rr++) {
            float v = lsum[bar][rr];
            v += __shfl_xor_sync(0xffffffffu, v, 1);
            v += __shfl_xor_sync(0xffffffffu, v, 2);
            if (r4 == 0) lsX[bar*64 + mrow + g + rr*8] = v;
        }

    if (wg == 1) {
        const int idx = tid - 128;
        #pragma unroll
        for (int bar = 0; bar < 3; bar++)
            #pragma unroll
            for (int nt = 0; nt < 4; nt++)
                *(float4*)&E3[(idx*12 + bar*4 + nt)*4] =
                    make_float4(o[bar][nt][0], o[bar][nt][1], o[bar][nt][2], o[bar][nt][3]);
    }
    __syncthreads();

    if (wg == 0) {
        const int idx = tid;
        const int rowA = q0 + mrow + g;
        const int rowB = rowA + 8;
        #pragma unroll
        for (int bar = 0; bar < 3; bar++) {
            const float rlA = 1.f / (lsA[bar*64 + mrow + g    ] + lsB[bar*64 + mrow + g    ]);
            const float rlB = 1.f / (lsA[bar*64 + mrow + g + 8] + lsB[bar*64 + mrow + g + 8]);
            #pragma unroll
            for (int nt = 0; nt < 4; nt++) {
                float4 p = *(const float4*)&E3[(idx*12 + bar*4 + nt)*4];
                const int col = bar*Edim + h*DKd + nt*8 + 2*r4;
                size_t baseA = ((size_t)b*Nseq + rowA) * (3*Edim) + col;
                size_t baseB = ((size_t)b*Nseq + rowB) * (3*Edim) + col;
                *(float2*)&xcat[baseA] = make_float2((o[bar][nt][0] + p.x)*rlA,
                                                     (o[bar][nt][1] + p.y)*rlA);
                *(float2*)&xcat[baseB] = make_float2((o[bar][nt][2] + p.z)*rlB,
                                                     (o[bar][nt][3] + p.w)*rlB);
            }
        }
    }
}

// ---------------- host launcher ----------------------------------------------
extern "C" void kernel_launch(void* const* d_in, const int* in_sizes, int n_in,
                              void* d_out, int out_size)
{
    const float* query = (const float*)d_in[0];
    const float* key   = (const float*)d_in[1];
    const float* value = (const float*)d_in[2];
    const float* dist  = (const float*)d_in[3];
    const int*   mask  = (const int*)d_in[4];
    const float* Wq = (const float*)d_in[5];
    const float* bq = (const float*)d_in[6];
    const float* Wk = (const float*)d_in[7];
    const float* bk = (const float*)d_in[8];
    const float* Wv = (const float*)d_in[9];
    const float* bv = (const float*)d_in[10];
    const float* Wo = (const float*)d_in[11];
    const float* bo = (const float*)d_in[12];
    const float* cw1 = (const float*)d_in[13];
    const float* cb1 = (const float*)d_in[14];
    const float* cw2 = (const float*)d_in[15];
    const float* cb2 = (const float*)d_in[16];
    const float* Ws1 = (const float*)d_in[17];
    const float* bs1 = (const float*)d_in[18];
    const float* Ws2 = (const float*)d_in[19];
    const float* bs2 = (const float*)d_in[20];
    float* out = (float*)d_out;

    float *q_p, *k_p, *v_p, *x_p, *h1_p, *wcat_p, *bfull_p, *zero_p, *conv_p;
    float *tA_p, *tB_p;
    cudaGetSymbolAddress((void**)&q_p,    g_q);
    cudaGetSymbolAddress((void**)&k_p,    g_k);
    cudaGetSymbolAddress((void**)&v_p,    g_v);
    cudaGetSymbolAddress((void**)&x_p,    g_x);
    cudaGetSymbolAddress((void**)&h1_p,   g_h1);
    cudaGetSymbolAddress((void**)&wcat_p, g_wcat);
    cudaGetSymbolAddress((void**)&bfull_p,g_bfull);
    cudaGetSymbolAddress((void**)&zero_p, g_zero);
    cudaGetSymbolAddress((void**)&conv_p, g_conv);
    cudaGetSymbolAddress((void**)&tA_p,   g_tblA);
    cudaGetSymbolAddress((void**)&tB_p,   g_tblB);

    cudaFuncSetAttribute(attn_mma,
                         cudaFuncAttributeMaxDynamicSharedMemorySize, ATTN_SMEM);

    const int M = Bq * Nseq;          // 4096
    dim3 blk(256);

    // lerp table then conv precompute
    tbl_kernel<<<1, 256>>>(cw1, cb1, cw2, cb2, tA_p, tB_p);
    conv_kernel<<<Bq * Nseq / 4, blk>>>(dist, mask, tA_p, tB_p, conv_p);

    // Wcat = [Wo @ Ws1_bar] and folded bias (parallel)
    {
        dim3 grid(Edim / 128, Edim / 64, 3);
        gemm_tc<<<grid, blk>>>(Wo, Wo, Wo,
                               Ws1, Ws1 + Edim*Edim, Ws1 + 2*Edim*Edim,
                               zero_p, zero_p, zero_p,
                               wcat_p, wcat_p + Edim*Edim, wcat_p + 2*Edim*Edim,
                               Edim, Edim, Edim, 0, 0);
        bias_fold<<<Edim / 16, 256>>>(bo, Ws1, bs1, bfull_p);
    }

    // QKV projections -> (B,H,N,DK), z-batched, outputs tf32-rounded
    {
        dim3 grid(M / 128, Edim / 64, 3);
        gemm_tc<<<grid, blk>>>(query, key, value,
                               Wq, Wk, Wv,
                               bq, bk, bv,
                               q_p, k_p, v_p,
                               Edim, Edim, 0, 0, 1);
    }

    // tf32 mma attention -> concat g_x (B,N,768)
    {
        dim3 grid(Nseq / 64, Bq * Hh);
        attn_mma<<<grid, 256, ATTN_SMEM>>>(q_p, k_p, v_p, conv_p, x_p);
    }

    // h1 = relu(xcat @ Wcat + bfull)
    {
        dim3 grid(M / 128, Edim / 64, 1);
        gemm_tc<<<grid, blk>>>(x_p, x_p, x_p, wcat_p, wcat_p, wcat_p,
                               bfull_p, bfull_p, bfull_p,
                               h1_p, h1_p, h1_p, 3*Edim, Edim, Edim, 1, 0);
    }

    // out = h1 @ Ws2 + bs2
    {
        dim3 grid(M / 128, Edim / 64, 1);
        gemm_tc<<<grid, blk>>>(h1_p, h1_p, h1_p, Ws2, Ws2, Ws2, bs2, bs2, bs2,
                               out, out, out, Edim, Edim, Edim, 0, 0);
    }
}

// round 13
// speedup vs baseline: 2.3175x; 1.0946x over previous
#include <cuda_runtime.h>
#include <math.h>

#define Bq   8
#define Nseq 512
#define Edim 256
#define Hh   8
#define DKd  32
#define SCALE 0.17677669529663687f   // 1/sqrt(32)

typedef unsigned long long ull;

// ---------------- scratch (device globals) ------------------------------------
__device__ float g_q[Bq*Hh*Nseq*DKd];
__device__ float g_k[Bq*Hh*Nseq*DKd];
__device__ float g_v[Bq*Hh*Nseq*DKd];
__device__ float g_x[Bq*Nseq*3*Edim];
__device__ float g_h1[Bq*Nseq*Edim];
__device__ float g_wcat[3*Edim*Edim];
__device__ float g_bfull[Edim];
__device__ float g_zero[Edim];
__device__ float g_conv[(size_t)Bq*Hh*Nseq*Nseq];  // conv*SCALE, code in 2 LSBs
__device__ float g_tblA[Hh*256];                    // lerp slope  (×SCALE)
__device__ float g_tblB[Hh*256];                    // lerp offset (×SCALE)

// ---------------- tf32 helpers --------------------------------------------------
__device__ __forceinline__ float tf32_of(float f) {
    unsigned u;
    asm("cvt.rna.tf32.f32 %0, %1;" : "=r"(u) : "f"(f));
    return __uint_as_float(u);
}
__device__ __forceinline__ void mma_tf32(float* d, const unsigned* a,
                                         unsigned b0, unsigned b1) {
    asm volatile(
        "mma.sync.aligned.m16n8k8.row.col.f32.tf32.tf32.f32 "
        "{%0,%1,%2,%3}, {%4,%5,%6,%7}, {%8,%9}, {%0,%1,%2,%3};"
        : "+f"(d[0]), "+f"(d[1]), "+f"(d[2]), "+f"(d[3])
        : "r"(a[0]), "r"(a[1]), "r"(a[2]), "r"(a[3]), "r"(b0), "r"(b1));
}
__device__ __forceinline__ float fexp(float x) {
    float e = fmaf(x, 0.041666667f, 0.16666667f);
    e = fmaf(e, x, 0.5f);
    e = fmaf(e, x, 1.0f);
    e = fmaf(e, x, 1.0f);
    if (fabsf(x) > 0.25f) e = __expf(x);
    return e;
}

// ---------------- lerp table build: 256 bins x 8 heads -------------------------
__global__ void tbl_kernel(const float* __restrict__ cw1, const float* __restrict__ cb1,
                           const float* __restrict__ cw2, const float* __restrict__ cb2,
                           float* __restrict__ tblA, float* __restrict__ tblB)
{
    const int i = threadIdx.x;              // bin 0..255
    const float d0 = i * (1.0f/256.0f);
    const float d1 = (i+1) * (1.0f/256.0f);
    #pragma unroll
    for (int h = 0; h < 8; h++) {
        float f0 = cb2[h], f1 = cb2[h];
        #pragma unroll
        for (int t = 0; t < 8; t++) {
            float r0 = fmaxf(fmaf(d0, cw1[t], cb1[t]), 0.f);
            float r1 = fmaxf(fmaf(d1, cw1[t], cb1[t]), 0.f);
            f0 = fmaf(cw2[h*8 + t], r0, f0);
            f1 = fmaf(cw2[h*8 + t], r1, f1);
        }
        tblB[h*256 + i] = f0 * SCALE;
        tblA[h*256 + i] = (f1 - f0) * SCALE;
    }
}

// ---------------- conv precompute v3: 4 rows per block -------------------------
__global__ __launch_bounds__(256) void conv_kernel(
    const float* __restrict__ dist, const int* __restrict__ mask,
    const float* __restrict__ tblA, const float* __restrict__ tblB,
    float* __restrict__ convp)
{
    __shared__ float sA[8][256], sB[8][256];
    const int tid = threadIdx.x;
    for (int t = tid; t < 2048; t += 256) {
        sA[t >> 8][t & 255] = tblA[t];
        sB[t >> 8][t & 255] = tblB[t];
    }
    __syncthreads();

    const int bi4 = blockIdx.x;              // b*128 + i/4
    const int b  = bi4 >> 7;
    const int i0 = (bi4 & 127) << 2;

    #pragma unroll
    for (int ri = 0; ri < 4; ri++) {
        const int i = i0 + ri;
        const float* drow = dist + ((size_t)b * Nseq + i) * Nseq;
        const int*   mrow = mask + ((size_t)b * Nseq + i) * Nseq;
        for (int j = tid; j < Nseq; j += 256) {
            float d = drow[j];
            int   m = mrow[j];
            unsigned code = (m == 0) ? 3u
                          : (i == 0 || j == 0) ? 0u
                          : (d < 0.3f) ? 0u : (d < 0.7f) ? 1u : 2u;
            float df = d * 256.0f;
            int idx = (int)df; idx = idx > 255 ? 255 : (idx < 0 ? 0 : idx);
            float frac = df - (float)idx;
            #pragma unroll
            for (int h = 0; h < 8; h++) {
                float c = fmaf(frac, sA[h][idx], sB[h][idx]);
                unsigned u = (__float_as_uint(c) & ~3u) | code;
                convp[(((size_t)(b*Hh + h) * Nseq + i) * Nseq) + j] = __uint_as_float(u);
            }
        }
    }
}

// ---------------- tf32 mma GEMM (unchanged) ------------------------------------
__global__ __launch_bounds__(256) void gemm_tc(
    const float* __restrict__ A0, const float* __restrict__ A1, const float* __restrict__ A2,
    const float* __restrict__ W0, const float* __restrict__ W1, const float* __restrict__ W2,
    const float* __restrict__ bias0, const float* __restrict__ bias1, const float* __restrict__ bias2,
    float* __restrict__ C0, float* __restrict__ C1, float* __restrict__ C2,
    int Kd, int ldw, int ldc, int do_relu, int headsplit)
{
    const int z = blockIdx.z;
    const float* A    = (z == 0) ? A0 : (z == 1) ? A1 : A2;
    const float* W    = (z == 0) ? W0 : (z == 1) ? W1 : W2;
    const float* bias = (z == 0) ? bias0 : (z == 1) ? bias1 : bias2;
    float*       C    = (z == 0) ? C0 : (z == 1) ? C1 : C2;

    __shared__ float As[2][16][136];
    __shared__ float Ws[2][16][72];

    const int m0 = blockIdx.x << 7;
    const int n0 = blockIdx.y << 6;
    const int tid = threadIdx.x;
    const int warp = tid >> 5, lane = tid & 31;
    const int g = lane >> 2, r4 = lane & 3;
    const int mb = (warp & 3) << 5;
    const int nb = (warp >> 2) << 5;

    const int ar = tid >> 1;
    const int ac = (tid & 1) << 3;
    const int wr = tid >> 4;
    const int wc = (tid & 15) << 2;

    const float* Aptr = A + (size_t)(m0 + ar) * Kd + ac;
    const float* Wptr = W + (size_t)wr * ldw + n0 + wc;

    float4 a0p = *(const float4*)(Aptr);
    float4 a1p = *(const float4*)(Aptr + 4);
    float4 wp  = *(const float4*)(Wptr);

    float c[2][4][4] = {};

    As[0][ac+0][ar] = tf32_of(a0p.x); As[0][ac+1][ar] = tf32_of(a0p.y);
    As[0][ac+2][ar] = tf32_of(a0p.z); As[0][ac+3][ar] = tf32_of(a0p.w);
    As[0][ac+4][ar] = tf32_of(a1p.x); As[0][ac+5][ar] = tf32_of(a1p.y);
    As[0][ac+6][ar] = tf32_of(a1p.z); As[0][ac+7][ar] = tf32_of(a1p.w);
    Ws[0][wr][wc+0] = tf32_of(wp.x);  Ws[0][wr][wc+1] = tf32_of(wp.y);
    Ws[0][wr][wc+2] = tf32_of(wp.z);  Ws[0][wr][wc+3] = tf32_of(wp.w);
    __syncthreads();

    const int nk = Kd >> 4;
    for (int kt = 0; kt < nk; kt++) {
        const int cur = kt & 1, nxt = cur ^ 1;
        if (kt + 1 < nk) {
            a0p = *(const float4*)(Aptr + (kt+1)*16);
            a1p = *(const float4*)(Aptr + (kt+1)*16 + 4);
            wp  = *(const float4*)(Wptr + (size_t)(kt+1)*16*ldw);
        }
        #pragma unroll
        for (int ks = 0; ks < 2; ks++) {
            unsigned af[2][4], bf[4][2];
            #pragma unroll
            for (int mt = 0; mt < 2; mt++) {
                const int row = mb + mt*16 + g;
                af[mt][0] = __float_as_uint(As[cur][ks*8 + r4    ][row    ]);
                af[mt][1] = __float_as_uint(As[cur][ks*8 + r4    ][row + 8]);
                af[mt][2] = __float_as_uint(As[cur][ks*8 + r4 + 4][row    ]);
                af[mt][3] = __float_as_uint(As[cur][ks*8 + r4 + 4][row + 8]);
            }
            #pragma unroll
            for (int nt = 0; nt < 4; nt++) {
                const int col = nb + nt*8 + g;
                bf[nt][0] = __float_as_uint(Ws[cur][ks*8 + r4    ][col]);
                bf[nt][1] = __float_as_uint(Ws[cur][ks*8 + r4 + 4][col]);
            }
            #pragma unroll
            for (int mt = 0; mt < 2; mt++)
                #pragma unroll
                for (int nt = 0; nt < 4; nt++)
                    mma_tf32(c[mt][nt], af[mt], bf[nt][0], bf[nt][1]);
        }
        if (kt + 1 < nk) {
            As[nxt][ac+0][ar] = tf32_of(a0p.x); As[nxt][ac+1][ar] = tf32_of(a0p.y);
            As[nxt][ac+2][ar] = tf32_of(a0p.z); As[nxt][ac+3][ar] = tf32_of(a0p.w);
            As[nxt][ac+4][ar] = tf32_of(a1p.x); As[nxt][ac+5][ar] = tf32_of(a1p.y);
            As[nxt][ac+6][ar] = tf32_of(a1p.z); As[nxt][ac+7][ar] = tf32_of(a1p.w);
            Ws[nxt][wr][wc+0] = tf32_of(wp.x);  Ws[nxt][wr][wc+1] = tf32_of(wp.y);
            Ws[nxt][wr][wc+2] = tf32_of(wp.z);  Ws[nxt][wr][wc+3] = tf32_of(wp.w);
        }
        __syncthreads();
    }

    #pragma unroll
    for (int nt = 0; nt < 4; nt++) {
        const int col0 = n0 + nb + nt*8 + 2*r4;
        const float2 bb = *(const float2*)&bias[col0];
        #pragma unroll
        for (int mt = 0; mt < 2; mt++) {
            const int row0 = m0 + mb + mt*16 + g;
            float2 v0 = make_float2(c[mt][nt][0] + bb.x, c[mt][nt][1] + bb.y);
            float2 v1 = make_float2(c[mt][nt][2] + bb.x, c[mt][nt][3] + bb.y);
            if (do_relu) {
                v0.x = fmaxf(v0.x, 0.f); v0.y = fmaxf(v0.y, 0.f);
                v1.x = fmaxf(v1.x, 0.f); v1.y = fmaxf(v1.y, 0.f);
            }
            if (headsplit) {
                v0.x = tf32_of(v0.x); v0.y = tf32_of(v0.y);
                v1.x = tf32_of(v1.x); v1.y = tf32_of(v1.y);
                const int h = col0 >> 5, d = col0 & 31;
                int b = row0 >> 9, n = row0 & 511;
                *(float2*)&C[(((size_t)(b*Hh + h))*Nseq + n)*DKd + d] = v0;
                b = (row0+8) >> 9; n = (row0+8) & 511;
                *(float2*)&C[(((size_t)(b*Hh + h))*Nseq + n)*DKd + d] = v1;
            } else {
                *(float2*)&C[(size_t)row0 * ldc + col0] = v0;
                *(float2*)&C[(size_t)(row0+8) * ldc + col0] = v1;
            }
        }
    }
}

// ---------------- bias fold v3: grid=16, short chains --------------------------
__global__ __launch_bounds__(256) void bias_fold(
    const float* __restrict__ bo, const float* __restrict__ Ws1,
    const float* __restrict__ bs1, float* __restrict__ bfull)
{
    __shared__ float red[16][16];
    const int nl = threadIdx.x & 15;
    const int rg = threadIdx.x >> 4;          // 0..15
    const int n  = blockIdx.x * 16 + nl;
    float s = 0.f;
    for (int r = rg; r < 3*Edim; r += 16)     // 48 iterations
        s = fmaf(bo[r & (Edim-1)], Ws1[(size_t)r * Edim + n], s);
    red[rg][nl] = s;
    __syncthreads();
    if (rg == 0) {
        float t = 0.f;
        #pragma unroll
        for (int k = 0; k < 16; k++) t += red[k][nl];
        bfull[n] = bs1[n] + t;
    }
}

// ---------------- tf32 mma attention (unchanged from R12) ----------------------
#define ATTN_SMEM 98304

__global__ __launch_bounds__(256, 2) void attn_mma(
    const float* __restrict__ Q, const float* __restrict__ K, const float* __restrict__ V,
    const float* __restrict__ convp, float* __restrict__ xcat)
{
    extern __shared__ float sm[];
    float (*Qs)[36] = (float(*)[36])(sm);
    float (*Ks)[36] = (float(*)[36])(sm + 2304);
    float (*Vt)[68] = (float(*)[68])(sm + 4608);
    float*  E3      = sm + 6784;
    float*  lsA     = sm + 24192;
    float*  lsB     = sm + 24384;

    const int qt = blockIdx.x;
    const int bh = blockIdx.y;
    const int b = bh >> 3, h = bh & 7;
    const int q0 = qt << 6;
    const int tid = threadIdx.x;
    const int warp = tid >> 5, lane = tid & 31;
    const int g = lane >> 2, r4 = lane & 3;
    const int wg = warp >> 2;
    const int mwarp = warp & 3;
    const int mrow = mwarp << 4;
    const int keybase = wg << 5;

    const size_t headbase = (size_t)bh * Nseq * DKd;

    const float* Qb = Q + headbase + (size_t)q0 * DKd;
    #pragma unroll
    for (int i = 0; i < 2; i++) {
        int idx = tid + i*256;
        int row = idx >> 3, c4 = (idx & 7) << 2;
        *(float4*)&Qs[row][c4] = *(const float4*)&Qb[row*32 + c4];
    }
    __syncthreads();

    unsigned qa[4][4];
    #pragma unroll
    for (int ks = 0; ks < 4; ks++) {
        qa[ks][0] = __float_as_uint(Qs[mrow + g    ][ks*8 + r4    ]);
        qa[ks][1] = __float_as_uint(Qs[mrow + g + 8][ks*8 + r4    ]);
        qa[ks][2] = __float_as_uint(Qs[mrow + g    ][ks*8 + r4 + 4]);
        qa[ks][3] = __float_as_uint(Qs[mrow + g + 8][ks*8 + r4 + 4]);
    }

    float o[3][4][4] = {};
    float lsum[3][2] = {};

    const float* cbase = convp + ((size_t)bh * Nseq + q0 + mrow) * Nseq;

    for (int kt = 0; kt < 8; kt++) {
        const int k0 = kt << 6;
        const float* Kb = K + headbase + (size_t)k0 * DKd;
        const float* Vb = V + headbase + (size_t)k0 * DKd;
        __syncthreads();
        #pragma unroll
        for (int i = 0; i < 2; i++) {
            int idx = tid + i*256;
            int row = idx >> 3, c4 = (idx & 7) << 2;
            *(float4*)&Ks[row][c4] = *(const float4*)&Kb[row*32 + c4];
            float4 vv = *(const float4*)&Vb[row*32 + c4];
            Vt[c4+0][row] = vv.x; Vt[c4+1][row] = vv.y;
            Vt[c4+2][row] = vv.z; Vt[c4+3][row] = vv.w;
        }

        float2 cc[4][2];
        #pragma unroll
        for (int nt = 0; nt < 4; nt++)
            #pragma unroll
            for (int rr = 0; rr < 2; rr++)
                cc[nt][rr] = *(const float2*)&cbase[(size_t)(g + rr*8) * Nseq
                                                    + k0 + keybase + nt*8 + 2*r4];
        __syncthreads();

        float s[4][4] = {};
        #pragma unroll
        for (int ks = 0; ks < 4; ks++) {
            #pragma unroll
            for (int nt = 0; nt < 4; nt++) {
                unsigned b0 = __float_as_uint(Ks[keybase + nt*8 + g][ks*8 + r4    ]);
                unsigned b1 = __float_as_uint(Ks[keybase + nt*8 + g][ks*8 + r4 + 4]);
                mma_tf32(s[nt], qa[ks], b0, b1);
            }
        }

        #pragma unroll
        for (int nt = 0; nt < 4; nt++) {
            #pragma unroll
            for (int rr = 0; rr < 2; rr++) {
                const int trow = mrow + g + rr*8;
                const int col = keybase + nt*8 + 2*r4;
                const float2 c2 = cc[nt][rr];
                float sx = s[nt][rr*2 + 0], sy = s[nt][rr*2 + 1];
                unsigned cx = __float_as_uint(c2.x) & 3u;
                unsigned cy = __float_as_uint(c2.y) & 3u;
                float ex = fexp(sx * c2.x);
                float ey = fexp(sy * c2.y);
                ex = (cx == 3u) ? 0.f : ex;
                ey = (cy == 3u) ? 0.f : ey;
                float ex1 = (cx < 2u) ? ex : 0.f;
                float ey1 = (cy < 2u) ? ey : 0.f;
                float ex0 = (cx == 0u) ? ex : 0.f;
                float ey0 = (cy == 0u) ? ey : 0.f;
                lsum[2][rr] += ex + ey;
                lsum[1][rr] += ex1 + ey1;
                lsum[0][rr] += ex0 + ey0;
                *(float4*)&E3[trow*272 + col*4] =
                    make_float4(tf32_of(ex),  tf32_of(ex1), tf32_of(ex0), 0.f);
                *(float4*)&E3[trow*272 + (col+1)*4] =
                    make_float4(tf32_of(ey),  tf32_of(ey1), tf32_of(ey0), 0.f);
            }
        }
        __syncthreads();

        #pragma unroll
        for (int ks = 0; ks < 4; ks++) {
            const int kk = keybase + ks*8;
            unsigned vb[4][2];
            #pragma unroll
            for (int nt = 0; nt < 4; nt++) {
                vb[nt][0] = __float_as_uint(Vt[nt*8 + g][kk + r4    ]);
                vb[nt][1] = __float_as_uint(Vt[nt*8 + g][kk + r4 + 4]);
            }
            float4 f00 = *(const float4*)&E3[(mrow + g    )*272 + (kk + r4    )*4];
            float4 f10 = *(const float4*)&E3[(mrow + g + 8)*272 + (kk + r4    )*4];
            float4 f01 = *(const float4*)&E3[(mrow + g    )*272 + (kk + r4 + 4)*4];
            float4 f11 = *(const float4*)&E3[(mrow + g + 8)*272 + (kk + r4 + 4)*4];
            unsigned a[4];
            a[0]=__float_as_uint(f00.x); a[1]=__float_as_uint(f10.x);
            a[2]=__float_as_uint(f01.x); a[3]=__float_as_uint(f11.x);
            #pragma unroll
            for (int nt = 0; nt < 4; nt++) mma_tf32(o[2][nt], a, vb[nt][0], vb[nt][1]);
            a[0]=__float_as_uint(f00.y); a[1]=__float_as_uint(f10.y);
            a[2]=__float_as_uint(f01.y); a[3]=__float_as_uint(f11.y);
            #pragma unroll
            for (int nt = 0; nt < 4; nt++) mma_tf32(o[1][nt], a, vb[nt][0], vb[nt][1]);
            a[0]=__float_as_uint(f00.z); a[1]=__float_as_uint(f10.z);
            a[2]=__float_as_uint(f01.z); a[3]=__float_as_uint(f11.z);
            #pragma unroll
            for (int nt = 0; nt < 4; nt++) mma_tf32(o[0][nt], a, vb[nt][0], vb[nt][1]);
        }
    }

    float* lsX = wg ? lsB : lsA;
    #pragma unroll
    for (int bar = 0; bar < 3; bar++)
        #pragma unroll
        for (int rr = 0; rr < 2; rr++) {
            float v = lsum[bar][rr];
            v += __shfl_xor_sync(0xffffffffu, v, 1);
            v += __shfl_xor_sync(0xffffffffu, v, 2);
            if (r4 == 0) lsX[bar*64 + mrow + g + rr*8] = v;
        }

    if (wg == 1) {
        const int idx = tid - 128;
        #pragma unroll
        for (int bar = 0; bar < 3; bar++)
            #pragma unroll
            for (int nt = 0; nt < 4; nt++)
                *(float4*)&E3[(idx*12 + bar*4 + nt)*4] =
                    make_float4(o[bar][nt][0], o[bar][nt][1], o[bar][nt][2], o[bar][nt][3]);
    }
    __syncthreads();

    if (wg == 0) {
        const int idx = tid;
        const int rowA = q0 + mrow + g;
        const int rowB = rowA + 8;
        #pragma unroll
        for (int bar = 0; bar < 3; bar++) {
            const float rlA = 1.f / (lsA[bar*64 + mrow + g    ] + lsB[bar*64 + mrow + g    ]);
            const float rlB = 1.f / (lsA[bar*64 + mrow + g + 8] + lsB[bar*64 + mrow + g + 8]);
            #pragma unroll
            for (int nt = 0; nt < 4; nt++) {
                float4 p = *(const float4*)&E3[(idx*12 + bar*4 + nt)*4];
                const int col = bar*Edim + h*DKd + nt*8 + 2*r4;
                size_t baseA = ((size_t)b*Nseq + rowA) * (3*Edim) + col;
                size_t baseB = ((size_t)b*Nseq + rowB) * (3*Edim) + col;
                *(float2*)&xcat[baseA] = make_float2((o[bar][nt][0] + p.x)*rlA,
                                                     (o[bar][nt][1] + p.y)*rlA);
                *(float2*)&xcat[baseB] = make_float2((o[bar][nt][2] + p.z)*rlB,
                                                     (o[bar][nt][3] + p.w)*rlB);
            }
        }
    }
}

// ---------------- host launcher: forked streams --------------------------------
extern "C" void kernel_launch(void* const* d_in, const int* in_sizes, int n_in,
                              void* d_out, int out_size)
{
    const float* query = (const float*)d_in[0];
    const float* key   = (const float*)d_in[1];
    const float* value = (const float*)d_in[2];
    const float* dist  = (const float*)d_in[3];
    const int*   mask  = (const int*)d_in[4];
    const float* Wq = (const float*)d_in[5];
    const float* bq = (const float*)d_in[6];
    const float* Wk = (const float*)d_in[7];
    const float* bk = (const float*)d_in[8];
    const float* Wv = (const float*)d_in[9];
    const float* bv = (const float*)d_in[10];
    const float* Wo = (const float*)d_in[11];
    const float* bo = (const float*)d_in[12];
    const float* cw1 = (const float*)d_in[13];
    const float* cb1 = (const float*)d_in[14];
    const float* cw2 = (const float*)d_in[15];
    const float* cb2 = (const float*)d_in[16];
    const float* Ws1 = (const float*)d_in[17];
    const float* bs1 = (const float*)d_in[18];
    const float* Ws2 = (const float*)d_in[19];
    const float* bs2 = (const float*)d_in[20];
    float* out = (float*)d_out;

    float *q_p, *k_p, *v_p, *x_p, *h1_p, *wcat_p, *bfull_p, *zero_p, *conv_p;
    float *tA_p, *tB_p;
    cudaGetSymbolAddress((void**)&q_p,    g_q);
    cudaGetSymbolAddress((void**)&k_p,    g_k);
    cudaGetSymbolAddress((void**)&v_p,    g_v);
    cudaGetSymbolAddress((void**)&x_p,    g_x);
    cudaGetSymbolAddress((void**)&h1_p,   g_h1);
    cudaGetSymbolAddress((void**)&wcat_p, g_wcat);
    cudaGetSymbolAddress((void**)&bfull_p,g_bfull);
    cudaGetSymbolAddress((void**)&zero_p, g_zero);
    cudaGetSymbolAddress((void**)&conv_p, g_conv);
    cudaGetSymbolAddress((void**)&tA_p,   g_tblA);
    cudaGetSymbolAddress((void**)&tB_p,   g_tblB);

    // one-time infra (created on the uncaptured correctness call)
    static cudaStream_t sB = nullptr, sC = nullptr;
    static cudaEvent_t evRoot = nullptr, evB = nullptr, evC = nullptr;
    if (sB == nullptr) {
        cudaStreamCreateWithFlags(&sB, cudaStreamNonBlocking);
        cudaStreamCreateWithFlags(&sC, cudaStreamNonBlocking);
        cudaEventCreateWithFlags(&evRoot, cudaEventDisableTiming);
        cudaEventCreateWithFlags(&evB,   cudaEventDisableTiming);
        cudaEventCreateWithFlags(&evC,   cudaEventDisableTiming);
        cudaFuncSetAttribute(attn_mma,
                             cudaFuncAttributeMaxDynamicSharedMemorySize, ATTN_SMEM);
    }

    const int M = Bq * Nseq;          // 4096
    dim3 blk(256);

    // ---- fork ----
    cudaEventRecord(evRoot, 0);
    cudaStreamWaitEvent(sB, evRoot, 0);
    cudaStreamWaitEvent(sC, evRoot, 0);

    // stream B: conv precompute (depends on dist/mask only)
    tbl_kernel<<<1, 256, 0, sB>>>(cw1, cb1, cw2, cb2, tA_p, tB_p);
    conv_kernel<<<Bq * Nseq / 4, blk, 0, sB>>>(dist, mask, tA_p, tB_p, conv_p);
    cudaEventRecord(evB, sB);

    // stream C: Wcat + folded bias (depends on weights only)
    {
        dim3 grid(Edim / 128, Edim / 64, 3);
        gemm_tc<<<grid, blk, 0, sC>>>(Wo, Wo, Wo,
                               Ws1, Ws1 + Edim*Edim, Ws1 + 2*Edim*Edim,
                               zero_p, zero_p, zero_p,
                               wcat_p, wcat_p + Edim*Edim, wcat_p + 2*Edim*Edim,
                               Edim, Edim, Edim, 0, 0);
        bias_fold<<<Edim / 16, 256, 0, sC>>>(bo, Ws1, bs1, bfull_p);
    }
    cudaEventRecord(evC, sC);

    // default stream: QKV projections (tf32-rounded outputs)
    {
        dim3 grid(M / 128, Edim / 64, 3);
        gemm_tc<<<grid, blk>>>(query, key, value,
                               Wq, Wk, Wv,
                               bq, bk, bv,
                               q_p, k_p, v_p,
                               Edim, Edim, 0, 0, 1);
    }

    // join conv, run attention
    cudaStreamWaitEvent(0, evB, 0);
    {
        dim3 grid(Nseq / 64, Bq * Hh);
        attn_mma<<<grid, 256, ATTN_SMEM>>>(q_p, k_p, v_p, conv_p, x_p);
    }

    // join Wcat/bias, run h1 then out
    cudaStreamWaitEvent(0, evC, 0);
    {
        dim3 grid(M / 128, Edim / 64, 1);
        gemm_tc<<<grid, blk>>>(x_p, x_p, x_p, wcat_p, wcat_p, wcat_p,
                               bfull_p, bfull_p, bfull_p,
                               h1_p, h1_p, h1_p, 3*Edim, Edim, Edim, 1, 0);
    }
    {
        dim3 grid(M / 128, Edim / 64, 1);
        gemm_tc<<<grid, blk>>>(h1_p, h1_p, h1_p, Ws2, Ws2, Ws2, bs2, bs2, bs2,
                               out, out, out, Edim, Edim, Edim, 0, 0);
    }
}

// round 14
// speedup vs baseline: 2.5517x; 1.1010x over previous
#include <cuda_runtime.h>
#include <math.h>

#define Bq   8
#define Nseq 512
#define Edim 256
#define Hh   8
#define DKd  32
#define SCALE 0.17677669529663687f   // 1/sqrt(32)

typedef unsigned long long ull;

// ---------------- scratch (device globals) ------------------------------------
__device__ float g_q[Bq*Hh*Nseq*DKd];
__device__ float g_k[Bq*Hh*Nseq*DKd];
__device__ float g_v[Bq*Hh*Nseq*DKd];
__device__ float g_x[Bq*Nseq*3*Edim];
__device__ float g_h1[Bq*Nseq*Edim];
__device__ float g_wcat[3*Edim*Edim];
__device__ float g_bfull[Edim];
__device__ float g_zero[Edim];
__device__ float g_conv[(size_t)Bq*Hh*Nseq*Nseq];  // conv*SCALE, code in 2 LSBs, key-permuted
__device__ float g_tblA[Hh*256];                    // lerp slope  (×SCALE)
__device__ float g_tblB[Hh*256];                    // lerp offset (×SCALE)

// ---------------- tf32 helpers --------------------------------------------------
__device__ __forceinline__ float tf32_of(float f) {
    unsigned u;
    asm("cvt.rna.tf32.f32 %0, %1;" : "=r"(u) : "f"(f));
    return __uint_as_float(u);
}
__device__ __forceinline__ void mma_tf32(float* d, const unsigned* a,
                                         unsigned b0, unsigned b1) {
    asm volatile(
        "mma.sync.aligned.m16n8k8.row.col.f32.tf32.tf32.f32 "
        "{%0,%1,%2,%3}, {%4,%5,%6,%7}, {%8,%9}, {%0,%1,%2,%3};"
        : "+f"(d[0]), "+f"(d[1]), "+f"(d[2]), "+f"(d[3])
        : "r"(a[0]), "r"(a[1]), "r"(a[2]), "r"(a[3]), "r"(b0), "r"(b1));
}
__device__ __forceinline__ float fexp(float x) {
    float e = fmaf(x, 0.041666667f, 0.16666667f);
    e = fmaf(e, x, 0.5f);
    e = fmaf(e, x, 1.0f);
    e = fmaf(e, x, 1.0f);
    if (fabsf(x) > 0.25f) e = __expf(x);
    return e;
}

// ---------------- lerp table build: 256 bins x 8 heads -------------------------
__global__ void tbl_kernel(const float* __restrict__ cw1, const float* __restrict__ cb1,
                           const float* __restrict__ cw2, const float* __restrict__ cb2,
                           float* __restrict__ tblA, float* __restrict__ tblB)
{
    const int i = threadIdx.x;              // bin 0..255
    const float d0 = i * (1.0f/256.0f);
    const float d1 = (i+1) * (1.0f/256.0f);
    #pragma unroll
    for (int h = 0; h < 8; h++) {
        float f0 = cb2[h], f1 = cb2[h];
        #pragma unroll
        for (int t = 0; t < 8; t++) {
            float r0 = fmaxf(fmaf(d0, cw1[t], cb1[t]), 0.f);
            float r1 = fmaxf(fmaf(d1, cw1[t], cb1[t]), 0.f);
            f0 = fmaf(cw2[h*8 + t], r0, f0);
            f1 = fmaf(cw2[h*8 + t], r1, f1);
        }
        tblB[h*256 + i] = f0 * SCALE;
        tblA[h*256 + i] = (f1 - f0) * SCALE;
    }
}

// ---------------- conv precompute: table lerp, key-permuted columns ------------
// physical key j stored at column (j&~7) | ((j&3)<<1 | (j>>2)&1), so the attn
// C-fragment column pair (2r4, 2r4+1) corresponds to physical keys (r4, r4+4).
__global__ __launch_bounds__(256) void conv_kernel(
    const float* __restrict__ dist, const int* __restrict__ mask,
    const float* __restrict__ tblA, const float* __restrict__ tblB,
    float* __restrict__ convp)
{
    __shared__ float sA[8][256], sB[8][256];
    const int tid = threadIdx.x;
    for (int t = tid; t < 2048; t += 256) {
        sA[t >> 8][t & 255] = tblA[t];
        sB[t >> 8][t & 255] = tblB[t];
    }
    __syncthreads();

    const int bi4 = blockIdx.x;              // b*128 + i/4
    const int b  = bi4 >> 7;
    const int i0 = (bi4 & 127) << 2;

    #pragma unroll
    for (int ri = 0; ri < 4; ri++) {
        const int i = i0 + ri;
        const float* drow = dist + ((size_t)b * Nseq + i) * Nseq;
        const int*   mrow = mask + ((size_t)b * Nseq + i) * Nseq;
        for (int j = tid; j < Nseq; j += 256) {
            float d = drow[j];
            int   m = mrow[j];
            unsigned code = (m == 0) ? 3u
                          : (i == 0 || j == 0) ? 0u
                          : (d < 0.3f) ? 0u : (d < 0.7f) ? 1u : 2u;
            float df = d * 256.0f;
            int idx = (int)df; idx = idx > 255 ? 255 : (idx < 0 ? 0 : idx);
            float frac = df - (float)idx;
            const int jp = (j & ~7) | (((j & 3) << 1) | ((j >> 2) & 1));
            #pragma unroll
            for (int h = 0; h < 8; h++) {
                float c = fmaf(frac, sA[h][idx], sB[h][idx]);
                unsigned u = (__float_as_uint(c) & ~3u) | code;
                convp[(((size_t)(b*Hh + h) * Nseq + i) * Nseq) + jp] = __uint_as_float(u);
            }
        }
    }
}

// ---------------- tf32 mma GEMM (unchanged) ------------------------------------
__global__ __launch_bounds__(256) void gemm_tc(
    const float* __restrict__ A0, const float* __restrict__ A1, const float* __restrict__ A2,
    const float* __restrict__ W0, const float* __restrict__ W1, const float* __restrict__ W2,
    const float* __restrict__ bias0, const float* __restrict__ bias1, const float* __restrict__ bias2,
    float* __restrict__ C0, float* __restrict__ C1, float* __restrict__ C2,
    int Kd, int ldw, int ldc, int do_relu, int headsplit)
{
    const int z = blockIdx.z;
    const float* A    = (z == 0) ? A0 : (z == 1) ? A1 : A2;
    const float* W    = (z == 0) ? W0 : (z == 1) ? W1 : W2;
    const float* bias = (z == 0) ? bias0 : (z == 1) ? bias1 : bias2;
    float*       C    = (z == 0) ? C0 : (z == 1) ? C1 : C2;

    __shared__ float As[2][16][136];
    __shared__ float Ws[2][16][72];

    const int m0 = blockIdx.x << 7;
    const int n0 = blockIdx.y << 6;
    const int tid = threadIdx.x;
    const int warp = tid >> 5, lane = tid & 31;
    const int g = lane >> 2, r4 = lane & 3;
    const int mb = (warp & 3) << 5;
    const int nb = (warp >> 2) << 5;

    const int ar = tid >> 1;
    const int ac = (tid & 1) << 3;
    const int wr = tid >> 4;
    const int wc = (tid & 15) << 2;

    const float* Aptr = A + (size_t)(m0 + ar) * Kd + ac;
    const float* Wptr = W + (size_t)wr * ldw + n0 + wc;

    float4 a0p = *(const float4*)(Aptr);
    float4 a1p = *(const float4*)(Aptr + 4);
    float4 wp  = *(const float4*)(Wptr);

    float c[2][4][4] = {};

    As[0][ac+0][ar] = tf32_of(a0p.x); As[0][ac+1][ar] = tf32_of(a0p.y);
    As[0][ac+2][ar] = tf32_of(a0p.z); As[0][ac+3][ar] = tf32_of(a0p.w);
    As[0][ac+4][ar] = tf32_of(a1p.x); As[0][ac+5][ar] = tf32_of(a1p.y);
    As[0][ac+6][ar] = tf32_of(a1p.z); As[0][ac+7][ar] = tf32_of(a1p.w);
    Ws[0][wr][wc+0] = tf32_of(wp.x);  Ws[0][wr][wc+1] = tf32_of(wp.y);
    Ws[0][wr][wc+2] = tf32_of(wp.z);  Ws[0][wr][wc+3] = tf32_of(wp.w);
    __syncthreads();

    const int nk = Kd >> 4;
    for (int kt = 0; kt < nk; kt++) {
        const int cur = kt & 1, nxt = cur ^ 1;
        if (kt + 1 < nk) {
            a0p = *(const float4*)(Aptr + (kt+1)*16);
            a1p = *(const float4*)(Aptr + (kt+1)*16 + 4);
            wp  = *(const float4*)(Wptr + (size_t)(kt+1)*16*ldw);
        }
        #pragma unroll
        for (int ks = 0; ks < 2; ks++) {
            unsigned af[2][4], bf[4][2];
            #pragma unroll
            for (int mt = 0; mt < 2; mt++) {
                const int row = mb + mt*16 + g;
                af[mt][0] = __float_as_uint(As[cur][ks*8 + r4    ][row    ]);
                af[mt][1] = __float_as_uint(As[cur][ks*8 + r4    ][row + 8]);
                af[mt][2] = __float_as_uint(As[cur][ks*8 + r4 + 4][row    ]);
                af[mt][3] = __float_as_uint(As[cur][ks*8 + r4 + 4][row + 8]);
            }
            #pragma unroll
            for (int nt = 0; nt < 4; nt++) {
                const int col = nb + nt*8 + g;
                bf[nt][0] = __float_as_uint(Ws[cur][ks*8 + r4    ][col]);
                bf[nt][1] = __float_as_uint(Ws[cur][ks*8 + r4 + 4][col]);
            }
            #pragma unroll
            for (int mt = 0; mt < 2; mt++)
                #pragma unroll
                for (int nt = 0; nt < 4; nt++)
                    mma_tf32(c[mt][nt], af[mt], bf[nt][0], bf[nt][1]);
        }
        if (kt + 1 < nk) {
            As[nxt][ac+0][ar] = tf32_of(a0p.x); As[nxt][ac+1][ar] = tf32_of(a0p.y);
            As[nxt][ac+2][ar] = tf32_of(a0p.z); As[nxt][ac+3][ar] = tf32_of(a0p.w);
            As[nxt][ac+4][ar] = tf32_of(a1p.x); As[nxt][ac+5][ar] = tf32_of(a1p.y);
            As[nxt][ac+6][ar] = tf32_of(a1p.z); As[nxt][ac+7][ar] = tf32_of(a1p.w);
            Ws[nxt][wr][wc+0] = tf32_of(wp.x);  Ws[nxt][wr][wc+1] = tf32_of(wp.y);
            Ws[nxt][wr][wc+2] = tf32_of(wp.z);  Ws[nxt][wr][wc+3] = tf32_of(wp.w);
        }
        __syncthreads();
    }

    #pragma unroll
    for (int nt = 0; nt < 4; nt++) {
        const int col0 = n0 + nb + nt*8 + 2*r4;
        const float2 bb = *(const float2*)&bias[col0];
        #pragma unroll
        for (int mt = 0; mt < 2; mt++) {
            const int row0 = m0 + mb + mt*16 + g;
            float2 v0 = make_float2(c[mt][nt][0] + bb.x, c[mt][nt][1] + bb.y);
            float2 v1 = make_float2(c[mt][nt][2] + bb.x, c[mt][nt][3] + bb.y);
            if (do_relu) {
                v0.x = fmaxf(v0.x, 0.f); v0.y = fmaxf(v0.y, 0.f);
                v1.x = fmaxf(v1.x, 0.f); v1.y = fmaxf(v1.y, 0.f);
            }
            if (headsplit) {
                v0.x = tf32_of(v0.x); v0.y = tf32_of(v0.y);
                v1.x = tf32_of(v1.x); v1.y = tf32_of(v1.y);
                const int h = col0 >> 5, d = col0 & 31;
                int b = row0 >> 9, n = row0 & 511;
                *(float2*)&C[(((size_t)(b*Hh + h))*Nseq + n)*DKd + d] = v0;
                b = (row0+8) >> 9; n = (row0+8) & 511;
                *(float2*)&C[(((size_t)(b*Hh + h))*Nseq + n)*DKd + d] = v1;
            } else {
                *(float2*)&C[(size_t)row0 * ldc + col0] = v0;
                *(float2*)&C[(size_t)(row0+8) * ldc + col0] = v1;
            }
        }
    }
}

// ---------------- bias fold v3 (unchanged) -------------------------------------
__global__ __launch_bounds__(256) void bias_fold(
    const float* __restrict__ bo, const float* __restrict__ Ws1,
    const float* __restrict__ bs1, float* __restrict__ bfull)
{
    __shared__ float red[16][16];
    const int nl = threadIdx.x & 15;
    const int rg = threadIdx.x >> 4;
    const int n  = blockIdx.x * 16 + nl;
    float s = 0.f;
    for (int r = rg; r < 3*Edim; r += 16)
        s = fmaf(bo[r & (Edim-1)], Ws1[(size_t)r * Edim + n], s);
    red[rg][nl] = s;
    __syncthreads();
    if (rg == 0) {
        float t = 0.f;
        #pragma unroll
        for (int k = 0; k < 16; k++) t += red[k][nl];
        bfull[n] = bs1[n] + t;
    }
}

// ---------------- tf32 mma attention: register-resident E (no smem E) ----------
// smem (floats): Qs[64][36]@0, Ks[64][36]@2304 (key-PERMUTED rows), Vt[32][68]@4608,
// lsA[3][64]@6784, lsB[3][64]@6976 -> 7168 floats = 28672 B.
// Final wg1->wg0 O dump reuses [0, 6144) after the mainloop.
#define ATTN_SMEM 28672

__global__ __launch_bounds__(256, 2) void attn_mma(
    const float* __restrict__ Q, const float* __restrict__ K, const float* __restrict__ V,
    const float* __restrict__ convp, float* __restrict__ xcat)
{
    extern __shared__ float sm[];
    float (*Qs)[36] = (float(*)[36])(sm);
    float (*Ks)[36] = (float(*)[36])(sm + 2304);
    float (*Vt)[68] = (float(*)[68])(sm + 4608);
    float*  dump    = sm;                 // reused after mainloop
    float*  lsA     = sm + 6784;
    float*  lsB     = sm + 6976;

    const int qt = blockIdx.x;
    const int bh = blockIdx.y;
    const int b = bh >> 3, h = bh & 7;
    const int q0 = qt << 6;
    const int tid = threadIdx.x;
    const int warp = tid >> 5, lane = tid & 31;
    const int g = lane >> 2, r4 = lane & 3;
    const int wg = warp >> 2;
    const int mwarp = warp & 3;
    const int mrow = mwarp << 4;
    const int keybase = wg << 5;

    const size_t headbase = (size_t)bh * Nseq * DKd;

    // ---- stage Q (natural order) ----
    const float* Qb = Q + headbase + (size_t)q0 * DKd;
    #pragma unroll
    for (int i = 0; i < 2; i++) {
        int idx = tid + i*256;
        int row = idx >> 3, c4 = (idx & 7) << 2;
        *(float4*)&Qs[row][c4] = *(const float4*)&Qb[row*32 + c4];
    }
    __syncthreads();

    unsigned qa[4][4];
    #pragma unroll
    for (int ks = 0; ks < 4; ks++) {
        qa[ks][0] = __float_as_uint(Qs[mrow + g    ][ks*8 + r4    ]);
        qa[ks][1] = __float_as_uint(Qs[mrow + g + 8][ks*8 + r4    ]);
        qa[ks][2] = __float_as_uint(Qs[mrow + g    ][ks*8 + r4 + 4]);
        qa[ks][3] = __float_as_uint(Qs[mrow + g + 8][ks*8 + r4 + 4]);
    }

    float o[3][4][4] = {};
    float lsum[3][2] = {};

    const float* cbase = convp + ((size_t)bh * Nseq + q0 + mrow) * Nseq;

    for (int kt = 0; kt < 8; kt++) {
        const int k0 = kt << 6;
        const float* Kb = K + headbase + (size_t)k0 * DKd;
        const float* Vb = V + headbase + (size_t)k0 * DKd;
        __syncthreads();
        #pragma unroll
        for (int i = 0; i < 2; i++) {
            int idx = tid + i*256;
            int row = idx >> 3, c4 = (idx & 7) << 2;
            // K staged with keys permuted within 8-groups: physical key p -> row inv(p)
            int pr = (row & ~7) | (((row & 3) << 1) | ((row >> 2) & 1));
            *(float4*)&Ks[pr][c4] = *(const float4*)&Kb[row*32 + c4];
            float4 vv = *(const float4*)&Vb[row*32 + c4];
            Vt[c4+0][row] = vv.x; Vt[c4+1][row] = vv.y;
            Vt[c4+2][row] = vv.z; Vt[c4+3][row] = vv.w;
        }

        // conv prefetch (permuted storage -> pair = physical keys r4, r4+4)
        float2 cc[4][2];
        #pragma unroll
        for (int nt = 0; nt < 4; nt++)
            #pragma unroll
            for (int rr = 0; rr < 2; rr++)
                cc[nt][rr] = *(const float2*)&cbase[(size_t)(g + rr*8) * Nseq
                                                    + k0 + keybase + nt*8 + 2*r4];
        __syncthreads();

        // ---- S = Q K^T (columns are permuted keys) ----
        float s[4][4] = {};
        #pragma unroll
        for (int ks = 0; ks < 4; ks++) {
            #pragma unroll
            for (int nt = 0; nt < 4; nt++) {
                unsigned b0 = __float_as_uint(Ks[keybase + nt*8 + g][ks*8 + r4    ]);
                unsigned b1 = __float_as_uint(Ks[keybase + nt*8 + g][ks*8 + r4 + 4]);
                mma_tf32(s[nt], qa[ks], b0, b1);
            }
        }

        // ---- fused exp + 3-bar PV, E entirely in registers ----
        #pragma unroll
        for (int nt = 0; nt < 4; nt++) {
            const float2 cR0 = cc[nt][0];   // row g:   phys keys r4, r4+4
            const float2 cR1 = cc[nt][1];   // row g+8: phys keys r4, r4+4
            unsigned m0 = __float_as_uint(cR0.x) & 3u;
            unsigned m1 = __float_as_uint(cR0.y) & 3u;
            unsigned m2 = __float_as_uint(cR1.x) & 3u;
            unsigned m3 = __float_as_uint(cR1.y) & 3u;
            float e0 = fexp(s[nt][0] * cR0.x);
            float e1 = fexp(s[nt][1] * cR0.y);
            float e2 = fexp(s[nt][2] * cR1.x);
            float e3 = fexp(s[nt][3] * cR1.y);
            e0 = (m0 == 3u) ? 0.f : e0;
            e1 = (m1 == 3u) ? 0.f : e1;
            e2 = (m2 == 3u) ? 0.f : e2;
            e3 = (m3 == 3u) ? 0.f : e3;
            float b10 = (m0 < 2u) ? e0 : 0.f;
            float b11 = (m1 < 2u) ? e1 : 0.f;
            float b12 = (m2 < 2u) ? e2 : 0.f;
            float b13 = (m3 < 2u) ? e3 : 0.f;
            float b00 = (m0 == 0u) ? e0 : 0.f;
            float b01 = (m1 == 0u) ? e1 : 0.f;
            float b02 = (m2 == 0u) ? e2 : 0.f;
            float b03 = (m3 == 0u) ? e3 : 0.f;
            lsum[2][0] += e0 + e1;   lsum[2][1] += e2 + e3;
            lsum[1][0] += b10 + b11; lsum[1][1] += b12 + b13;
            lsum[0][0] += b00 + b01; lsum[0][1] += b02 + b03;
            // PV A-fragments: a = {row g k=r4, row g+8 k=r4, row g k=r4+4, row g+8 k=r4+4}
            //               =  {c0,          c2,           c1,            c3}
            unsigned a2[4] = {__float_as_uint(e0),  __float_as_uint(e2),
                              __float_as_uint(e1),  __float_as_uint(e3)};
            unsigned a1[4] = {__float_as_uint(b10), __float_as_uint(b12),
                              __float_as_uint(b11), __float_as_uint(b13)};
            unsigned a0[4] = {__float_as_uint(b00), __float_as_uint(b02),
                              __float_as_uint(b01), __float_as_uint(b03)};
            const int kk = keybase + nt*8;
            #pragma unroll
            for (int dnt = 0; dnt < 4; dnt++) {
                unsigned vb0 = __float_as_uint(Vt[dnt*8 + g][kk + r4    ]);
                unsigned vb1 = __float_as_uint(Vt[dnt*8 + g][kk + r4 + 4]);
                mma_tf32(o[2][dnt], a2, vb0, vb1);
                mma_tf32(o[1][dnt], a1, vb0, vb1);
                mma_tf32(o[0][dnt], a0, vb0, vb1);
            }
        }
    }

    // ---- lane-reduce lsum within quad, publish per-wg row sums ----
    __syncthreads();     // mainloop smem reads done; safe to reuse
    float* lsX = wg ? lsB : lsA;
    #pragma unroll
    for (int bar = 0; bar < 3; bar++)
        #pragma unroll
        for (int rr = 0; rr < 2; rr++) {
            float v = lsum[bar][rr];
            v += __shfl_xor_sync(0xffffffffu, v, 1);
            v += __shfl_xor_sync(0xffffffffu, v, 2);
            if (r4 == 0) lsX[bar*64 + mrow + g + rr*8] = v;
        }

    if (wg == 1) {
        const int idx = tid - 128;
        #pragma unroll
        for (int bar = 0; bar < 3; bar++)
            #pragma unroll
            for (int nt = 0; nt < 4; nt++)
                *(float4*)&dump[(idx*12 + bar*4 + nt)*4] =
                    make_float4(o[bar][nt][0], o[bar][nt][1], o[bar][nt][2], o[bar][nt][3]);
    }
    __syncthreads();

    if (wg == 0) {
        const int idx = tid;
        const int rowA = q0 + mrow + g;
        const int rowB = rowA + 8;
        #pragma unroll
        for (int bar = 0; bar < 3; bar++) {
            const float rlA = 1.f / (lsA[bar*64 + mrow + g    ] + lsB[bar*64 + mrow + g    ]);
            const float rlB = 1.f / (lsA[bar*64 + mrow + g + 8] + lsB[bar*64 + mrow + g + 8]);
            #pragma unroll
            for (int nt = 0; nt < 4; nt++) {
                float4 p = *(const float4*)&dump[(idx*12 + bar*4 + nt)*4];
                const int col = bar*Edim + h*DKd + nt*8 + 2*r4;
                size_t baseA = ((size_t)b*Nseq + rowA) * (3*Edim) + col;
                size_t baseB = ((size_t)b*Nseq + rowB) * (3*Edim) + col;
                *(float2*)&xcat[baseA] = make_float2((o[bar][nt][0] + p.x)*rlA,
                                                     (o[bar][nt][1] + p.y)*rlA);
                *(float2*)&xcat[baseB] = make_float2((o[bar][nt][2] + p.z)*rlB,
                                                     (o[bar][nt][3] + p.w)*rlB);
            }
        }
    }
}

// ---------------- host launcher: forked streams --------------------------------
extern "C" void kernel_launch(void* const* d_in, const int* in_sizes, int n_in,
                              void* d_out, int out_size)
{
    const float* query = (const float*)d_in[0];
    const float* key   = (const float*)d_in[1];
    const float* value = (const float*)d_in[2];
    const float* dist  = (const float*)d_in[3];
    const int*   mask  = (const int*)d_in[4];
    const float* Wq = (const float*)d_in[5];
    const float* bq = (const float*)d_in[6];
    const float* Wk = (const float*)d_in[7];
    const float* bk = (const float*)d_in[8];
    const float* Wv = (const float*)d_in[9];
    const float* bv = (const float*)d_in[10];
    const float* Wo = (const float*)d_in[11];
    const float* bo = (const float*)d_in[12];
    const float* cw1 = (const float*)d_in[13];
    const float* cb1 = (const float*)d_in[14];
    const float* cw2 = (const float*)d_in[15];
    const float* cb2 = (const float*)d_in[16];
    const float* Ws1 = (const float*)d_in[17];
    const float* bs1 = (const float*)d_in[18];
    const float* Ws2 = (const float*)d_in[19];
    const float* bs2 = (const float*)d_in[20];
    float* out = (float*)d_out;

    float *q_p, *k_p, *v_p, *x_p, *h1_p, *wcat_p, *bfull_p, *zero_p, *conv_p;
    float *tA_p, *tB_p;
    cudaGetSymbolAddress((void**)&q_p,    g_q);
    cudaGetSymbolAddress((void**)&k_p,    g_k);
    cudaGetSymbolAddress((void**)&v_p,    g_v);
    cudaGetSymbolAddress((void**)&x_p,    g_x);
    cudaGetSymbolAddress((void**)&h1_p,   g_h1);
    cudaGetSymbolAddress((void**)&wcat_p, g_wcat);
    cudaGetSymbolAddress((void**)&bfull_p,g_bfull);
    cudaGetSymbolAddress((void**)&zero_p, g_zero);
    cudaGetSymbolAddress((void**)&conv_p, g_conv);
    cudaGetSymbolAddress((void**)&tA_p,   g_tblA);
    cudaGetSymbolAddress((void**)&tB_p,   g_tblB);

    static cudaStream_t sB = nullptr, sC = nullptr;
    static cudaEvent_t evRoot = nullptr, evB = nullptr, evC = nullptr;
    if (sB == nullptr) {
        cudaStreamCreateWithFlags(&sB, cudaStreamNonBlocking);
        cudaStreamCreateWithFlags(&sC, cudaStreamNonBlocking);
        cudaEventCreateWithFlags(&evRoot, cudaEventDisableTiming);
        cudaEventCreateWithFlags(&evB,   cudaEventDisableTiming);
        cudaEventCreateWithFlags(&evC,   cudaEventDisableTiming);
        cudaFuncSetAttribute(attn_mma,
                             cudaFuncAttributeMaxDynamicSharedMemorySize, ATTN_SMEM);
    }

    const int M = Bq * Nseq;          // 4096
    dim3 blk(256);

    // ---- fork ----
    cudaEventRecord(evRoot, 0);
    cudaStreamWaitEvent(sB, evRoot, 0);
    cudaStreamWaitEvent(sC, evRoot, 0);

    // stream B: conv precompute (inputs only)
    tbl_kernel<<<1, 256, 0, sB>>>(cw1, cb1, cw2, cb2, tA_p, tB_p);
    conv_kernel<<<Bq * Nseq / 4, blk, 0, sB>>>(dist, mask, tA_p, tB_p, conv_p);
    cudaEventRecord(evB, sB);

    // stream C: Wcat + folded bias (weights only)
    {
        dim3 grid(Edim / 128, Edim / 64, 3);
        gemm_tc<<<grid, blk, 0, sC>>>(Wo, Wo, Wo,
                               Ws1, Ws1 + Edim*Edim, Ws1 + 2*Edim*Edim,
                               zero_p, zero_p, zero_p,
                               wcat_p, wcat_p + Edim*Edim, wcat_p + 2*Edim*Edim,
                               Edim, Edim, Edim, 0, 0);
        bias_fold<<<Edim / 16, 256, 0, sC>>>(bo, Ws1, bs1, bfull_p);
    }
    cudaEventRecord(evC, sC);

    // default: QKV projections (tf32-rounded outputs)
    {
        dim3 grid(M / 128, Edim / 64, 3);
        gemm_tc<<<grid, blk>>>(query, key, value,
                               Wq, Wk, Wv,
                               bq, bk, bv,
                               q_p, k_p, v_p,
                               Edim, Edim, 0, 0, 1);
    }

    cudaStreamWaitEvent(0, evB, 0);
    {
        dim3 grid(Nseq / 64, Bq * Hh);
        attn_mma<<<grid, 256, ATTN_SMEM>>>(q_p, k_p, v_p, conv_p, x_p);
    }

    cudaStreamWaitEvent(0, evC, 0);
    {
        dim3 grid(M / 128, Edim / 64, 1);
        gemm_tc<<<grid, blk>>>(x_p, x_p, x_p, wcat_p, wcat_p, wcat_p,
                               bfull_p, bfull_p, bfull_p,
                               h1_p, h1_p, h1_p, 3*Edim, Edim, Edim, 1, 0);
    }
    {
        dim3 grid(M / 128, Edim / 64, 1);
        gemm_tc<<<grid, blk>>>(h1_p, h1_p, h1_p, Ws2, Ws2, Ws2, bs2, bs2, bs2,
                               out, out, out, Edim, Edim, Edim, 0, 0);
    }
}

// round 15
// speedup vs baseline: 2.6485x; 1.0379x over previous
#include <cuda_runtime.h>
#include <math.h>

#define Bq   8
#define Nseq 512
#define Edim 256
#define Hh   8
#define DKd  32
#define SCALE 0.17677669529663687f   // 1/sqrt(32)

typedef unsigned long long ull;

// ---------------- scratch (device globals) ------------------------------------
__device__ float g_q[Bq*Hh*Nseq*DKd];
__device__ float g_k[Bq*Hh*Nseq*DKd];
__device__ float g_v[Bq*Hh*Nseq*DKd];
__device__ float g_x[Bq*Nseq*3*Edim];
__device__ float g_h1[Bq*Nseq*Edim];
__device__ float g_wcat[3*Edim*Edim];
__device__ float g_bfull[Edim];
__device__ float g_zero[Edim];
__device__ float g_conv[(size_t)Bq*Hh*Nseq*Nseq];  // conv*SCALE, code in 2 LSBs, key-permuted
__device__ float g_tblA[Hh*256];
__device__ float g_tblB[Hh*256];

// ---------------- tf32 / cp.async helpers --------------------------------------
__device__ __forceinline__ float tf32_of(float f) {
    unsigned u;
    asm("cvt.rna.tf32.f32 %0, %1;" : "=r"(u) : "f"(f));
    return __uint_as_float(u);
}
__device__ __forceinline__ void mma_tf32(float* d, const unsigned* a,
                                         unsigned b0, unsigned b1) {
    asm volatile(
        "mma.sync.aligned.m16n8k8.row.col.f32.tf32.tf32.f32 "
        "{%0,%1,%2,%3}, {%4,%5,%6,%7}, {%8,%9}, {%0,%1,%2,%3};"
        : "+f"(d[0]), "+f"(d[1]), "+f"(d[2]), "+f"(d[3])
        : "r"(a[0]), "r"(a[1]), "r"(a[2]), "r"(a[3]), "r"(b0), "r"(b1));
}
__device__ __forceinline__ float fexp(float x) {
    float e = fmaf(x, 0.041666667f, 0.16666667f);
    e = fmaf(e, x, 0.5f);
    e = fmaf(e, x, 1.0f);
    e = fmaf(e, x, 1.0f);
    if (fabsf(x) > 0.25f) e = __expf(x);
    return e;
}
__device__ __forceinline__ unsigned smaddr(const void* p) {
    unsigned a;
    asm("{ .reg .u64 t; cvta.to.shared.u64 t, %1; cvt.u32.u64 %0, t; }"
        : "=r"(a) : "l"(p));
    return a;
}
#define CP16(dst, src)  asm volatile("cp.async.ca.shared.global [%0], [%1], 16;" :: "r"(dst), "l"(src))
#define CPCOMMIT()      asm volatile("cp.async.commit_group;")
#define CPWAIT0()       asm volatile("cp.async.wait_group 0;" ::: "memory")

// ---------------- lerp table build ---------------------------------------------
__global__ void tbl_kernel(const float* __restrict__ cw1, const float* __restrict__ cb1,
                           const float* __restrict__ cw2, const float* __restrict__ cb2,
                           float* __restrict__ tblA, float* __restrict__ tblB)
{
    const int i = threadIdx.x;
    const float d0 = i * (1.0f/256.0f);
    const float d1 = (i+1) * (1.0f/256.0f);
    #pragma unroll
    for (int h = 0; h < 8; h++) {
        float f0 = cb2[h], f1 = cb2[h];
        #pragma unroll
        for (int t = 0; t < 8; t++) {
            float r0 = fmaxf(fmaf(d0, cw1[t], cb1[t]), 0.f);
            float r1 = fmaxf(fmaf(d1, cw1[t], cb1[t]), 0.f);
            f0 = fmaf(cw2[h*8 + t], r0, f0);
            f1 = fmaf(cw2[h*8 + t], r1, f1);
        }
        tblB[h*256 + i] = f0 * SCALE;
        tblA[h*256 + i] = (f1 - f0) * SCALE;
    }
}

// ---------------- conv precompute (key-permuted columns) -----------------------
__global__ __launch_bounds__(256) void conv_kernel(
    const float* __restrict__ dist, const int* __restrict__ mask,
    const float* __restrict__ tblA, const float* __restrict__ tblB,
    float* __restrict__ convp)
{
    __shared__ float sA[8][256], sB[8][256];
    const int tid = threadIdx.x;
    for (int t = tid; t < 2048; t += 256) {
        sA[t >> 8][t & 255] = tblA[t];
        sB[t >> 8][t & 255] = tblB[t];
    }
    __syncthreads();

    const int bi4 = blockIdx.x;
    const int b  = bi4 >> 7;
    const int i0 = (bi4 & 127) << 2;

    #pragma unroll
    for (int ri = 0; ri < 4; ri++) {
        const int i = i0 + ri;
        const float* drow = dist + ((size_t)b * Nseq + i) * Nseq;
        const int*   mrow = mask + ((size_t)b * Nseq + i) * Nseq;
        for (int j = tid; j < Nseq; j += 256) {
            float d = drow[j];
            int   m = mrow[j];
            unsigned code = (m == 0) ? 3u
                          : (i == 0 || j == 0) ? 0u
                          : (d < 0.3f) ? 0u : (d < 0.7f) ? 1u : 2u;
            float df = d * 256.0f;
            int idx = (int)df; idx = idx > 255 ? 255 : (idx < 0 ? 0 : idx);
            float frac = df - (float)idx;
            const int jp = (j & ~7) | (((j & 3) << 1) | ((j >> 2) & 1));
            #pragma unroll
            for (int h = 0; h < 8; h++) {
                float c = fmaf(frac, sA[h][idx], sB[h][idx]);
                unsigned u = (__float_as_uint(c) & ~3u) | code;
                convp[(((size_t)(b*Hh + h) * Nseq + i) * Nseq) + jp] = __uint_as_float(u);
            }
        }
    }
}

// ---------------- tf32 mma GEMM -------------------------------------------------
__global__ __launch_bounds__(256, 3) void gemm_tc(
    const float* __restrict__ A0, const float* __restrict__ A1, const float* __restrict__ A2,
    const float* __restrict__ W0, const float* __restrict__ W1, const float* __restrict__ W2,
    const float* __restrict__ bias0, const float* __restrict__ bias1, const float* __restrict__ bias2,
    float* __restrict__ C0, float* __restrict__ C1, float* __restrict__ C2,
    int Kd, int ldw, int ldc, int do_relu, int headsplit)
{
    const int z = blockIdx.z;
    const float* A    = (z == 0) ? A0 : (z == 1) ? A1 : A2;
    const float* W    = (z == 0) ? W0 : (z == 1) ? W1 : W2;
    const float* bias = (z == 0) ? bias0 : (z == 1) ? bias1 : bias2;
    float*       C    = (z == 0) ? C0 : (z == 1) ? C1 : C2;

    __shared__ float As[2][16][136];
    __shared__ float Ws[2][16][72];

    const int m0 = blockIdx.x << 7;
    const int n0 = blockIdx.y << 6;
    const int tid = threadIdx.x;
    const int warp = tid >> 5, lane = tid & 31;
    const int g = lane >> 2, r4 = lane & 3;
    const int mb = (warp & 3) << 5;
    const int nb = (warp >> 2) << 5;

    const int ar = tid >> 1;
    const int ac = (tid & 1) << 3;
    const int wr = tid >> 4;
    const int wc = (tid & 15) << 2;

    const float* Aptr = A + (size_t)(m0 + ar) * Kd + ac;
    const float* Wptr = W + (size_t)wr * ldw + n0 + wc;

    float4 a0p = *(const float4*)(Aptr);
    float4 a1p = *(const float4*)(Aptr + 4);
    float4 wp  = *(const float4*)(Wptr);

    float c[2][4][4] = {};

    As[0][ac+0][ar] = tf32_of(a0p.x); As[0][ac+1][ar] = tf32_of(a0p.y);
    As[0][ac+2][ar] = tf32_of(a0p.z); As[0][ac+3][ar] = tf32_of(a0p.w);
    As[0][ac+4][ar] = tf32_of(a1p.x); As[0][ac+5][ar] = tf32_of(a1p.y);
    As[0][ac+6][ar] = tf32_of(a1p.z); As[0][ac+7][ar] = tf32_of(a1p.w);
    Ws[0][wr][wc+0] = tf32_of(wp.x);  Ws[0][wr][wc+1] = tf32_of(wp.y);
    Ws[0][wr][wc+2] = tf32_of(wp.z);  Ws[0][wr][wc+3] = tf32_of(wp.w);
    __syncthreads();

    const int nk = Kd >> 4;
    for (int kt = 0; kt < nk; kt++) {
        const int cur = kt & 1, nxt = cur ^ 1;
        if (kt + 1 < nk) {
            a0p = *(const float4*)(Aptr + (kt+1)*16);
            a1p = *(const float4*)(Aptr + (kt+1)*16 + 4);
            wp  = *(const float4*)(Wptr + (size_t)(kt+1)*16*ldw);
        }
        #pragma unroll
        for (int ks = 0; ks < 2; ks++) {
            unsigned af[2][4], bf[4][2];
            #pragma unroll
            for (int mt = 0; mt < 2; mt++) {
                const int row = mb + mt*16 + g;
                af[mt][0] = __float_as_uint(As[cur][ks*8 + r4    ][row    ]);
                af[mt][1] = __float_as_uint(As[cur][ks*8 + r4    ][row + 8]);
                af[mt][2] = __float_as_uint(As[cur][ks*8 + r4 + 4][row    ]);
                af[mt][3] = __float_as_uint(As[cur][ks*8 + r4 + 4][row + 8]);
            }
            #pragma unroll
            for (int nt = 0; nt < 4; nt++) {
                const int col = nb + nt*8 + g;
                bf[nt][0] = __float_as_uint(Ws[cur][ks*8 + r4    ][col]);
                bf[nt][1] = __float_as_uint(Ws[cur][ks*8 + r4 + 4][col]);
            }
            #pragma unroll
            for (int mt = 0; mt < 2; mt++)
                #pragma unroll
                for (int nt = 0; nt < 4; nt++)
                    mma_tf32(c[mt][nt], af[mt], bf[nt][0], bf[nt][1]);
        }
        if (kt + 1 < nk) {
            As[nxt][ac+0][ar] = tf32_of(a0p.x); As[nxt][ac+1][ar] = tf32_of(a0p.y);
            As[nxt][ac+2][ar] = tf32_of(a0p.z); As[nxt][ac+3][ar] = tf32_of(a0p.w);
            As[nxt][ac+4][ar] = tf32_of(a1p.x); As[nxt][ac+5][ar] = tf32_of(a1p.y);
            As[nxt][ac+6][ar] = tf32_of(a1p.z); As[nxt][ac+7][ar] = tf32_of(a1p.w);
            Ws[nxt][wr][wc+0] = tf32_of(wp.x);  Ws[nxt][wr][wc+1] = tf32_of(wp.y);
            Ws[nxt][wr][wc+2] = tf32_of(wp.z);  Ws[nxt][wr][wc+3] = tf32_of(wp.w);
        }
        __syncthreads();
    }

    #pragma unroll
    for (int nt = 0; nt < 4; nt++) {
        const int col0 = n0 + nb + nt*8 + 2*r4;
        const float2 bb = *(const float2*)&bias[col0];
        #pragma unroll
        for (int mt = 0; mt < 2; mt++) {
            const int row0 = m0 + mb + mt*16 + g;
            float2 v0 = make_float2(c[mt][nt][0] + bb.x, c[mt][nt][1] + bb.y);
            float2 v1 = make_float2(c[mt][nt][2] + bb.x, c[mt][nt][3] + bb.y);
            if (do_relu) {
                v0.x = fmaxf(v0.x, 0.f); v0.y = fmaxf(v0.y, 0.f);
                v1.x = fmaxf(v1.x, 0.f); v1.y = fmaxf(v1.y, 0.f);
            }
            if (headsplit) {
                v0.x = tf32_of(v0.x); v0.y = tf32_of(v0.y);
                v1.x = tf32_of(v1.x); v1.y = tf32_of(v1.y);
                const int h = col0 >> 5, d = col0 & 31;
                int b = row0 >> 9, n = row0 & 511;
                *(float2*)&C[(((size_t)(b*Hh + h))*Nseq + n)*DKd + d] = v0;
                b = (row0+8) >> 9; n = (row0+8) & 511;
                *(float2*)&C[(((size_t)(b*Hh + h))*Nseq + n)*DKd + d] = v1;
            } else {
                *(float2*)&C[(size_t)row0 * ldc + col0] = v0;
                *(float2*)&C[(size_t)(row0+8) * ldc + col0] = v1;
            }
        }
    }
}

// ---------------- bias fold ----------------------------------------------------
__global__ __launch_bounds__(256) void bias_fold(
    const float* __restrict__ bo, const float* __restrict__ Ws1,
    const float* __restrict__ bs1, float* __restrict__ bfull)
{
    __shared__ float red[16][16];
    const int nl = threadIdx.x & 15;
    const int rg = threadIdx.x >> 4;
    const int n  = blockIdx.x * 16 + nl;
    float s = 0.f;
    for (int r = rg; r < 3*Edim; r += 16)
        s = fmaf(bo[r & (Edim-1)], Ws1[(size_t)r * Edim + n], s);
    red[rg][nl] = s;
    __syncthreads();
    if (rg == 0) {
        float t = 0.f;
        #pragma unroll
        for (int k = 0; k < 16; k++) t += red[k][nl];
        bfull[n] = bs1[n] + t;
    }
}

// ---------------- tf32 mma attention: cp.async double-buffered -----------------
// smem (floats): Qs[64][36]@0 (2304), Ks[2][64][36]@2304 (4608),
//                Vs[2][64][40]@6912 (5120, ROW-major V: Vs[key][d]),
//                lsA[3][64]@12032, lsB[3][64]@12224 -> 12416 floats = 49664 B.
// dump region reuses sm[0..6144) after the mainloop.
#define ATTN_SMEM 49664

__global__ __launch_bounds__(256, 2) void attn_mma(
    const float* __restrict__ Q, const float* __restrict__ K, const float* __restrict__ V,
    const float* __restrict__ convp, float* __restrict__ xcat)
{
    extern __shared__ float sm[];
    float (*Qs)[36] = (float(*)[36])(sm);
    float* KsB  = sm + 2304;                  // [buf][row][36]
    float* VsB  = sm + 6912;                  // [buf][key][40]
    float* dump = sm;
    float* lsA  = sm + 12032;
    float* lsB  = sm + 12224;
#define KS(buf,row,col) KsB[(buf)*2304 + (row)*36 + (col)]
#define VS(buf,row,col) VsB[(buf)*2560 + (row)*40 + (col)]

    const int qt = blockIdx.x;
    const int bh = blockIdx.y;
    const int b = bh >> 3, h = bh & 7;
    const int q0 = qt << 6;
    const int tid = threadIdx.x;
    const int warp = tid >> 5, lane = tid & 31;
    const int g = lane >> 2, r4 = lane & 3;
    const int wg = warp >> 2;
    const int mwarp = warp & 3;
    const int mrow = mwarp << 4;
    const int keybase = wg << 5;

    const size_t headbase = (size_t)bh * Nseq * DKd;
    const float* Kb = K + headbase;
    const float* Vb = V + headbase;

    // per-thread staging geometry (2 chunks of 16B each for K and V per tile)
    const int srow0 = tid >> 3, sc4 = (tid & 7) << 2;
    const int srow1 = srow0 + 32;
    const int pr0 = (srow0 & ~7) | (((srow0 & 3) << 1) | ((srow0 >> 2) & 1));
    const int pr1 = (srow1 & ~7) | (((srow1 & 3) << 1) | ((srow1 >> 2) & 1));

    // ---- stage Q ----
    const float* Qb = Q + headbase + (size_t)q0 * DKd;
    #pragma unroll
    for (int i = 0; i < 2; i++) {
        int idx = tid + i*256;
        int row = idx >> 3, c4 = (idx & 7) << 2;
        *(float4*)&Qs[row][c4] = *(const float4*)&Qb[row*32 + c4];
    }

    // ---- stage K/V tile 0 via cp.async ----
    {
        CP16(smaddr(&KS(0, pr0, sc4)),  Kb + srow0*32 + sc4);
        CP16(smaddr(&KS(0, pr1, sc4)),  Kb + srow1*32 + sc4);
        CP16(smaddr(&VS(0, srow0, sc4)), Vb + srow0*32 + sc4);
        CP16(smaddr(&VS(0, srow1, sc4)), Vb + srow1*32 + sc4);
        CPCOMMIT();
    }
    CPWAIT0();
    __syncthreads();

    unsigned qa[4][4];
    #pragma unroll
    for (int ks = 0; ks < 4; ks++) {
        qa[ks][0] = __float_as_uint(Qs[mrow + g    ][ks*8 + r4    ]);
        qa[ks][1] = __float_as_uint(Qs[mrow + g + 8][ks*8 + r4    ]);
        qa[ks][2] = __float_as_uint(Qs[mrow + g    ][ks*8 + r4 + 4]);
        qa[ks][3] = __float_as_uint(Qs[mrow + g + 8][ks*8 + r4 + 4]);
    }

    float o[3][4][4] = {};
    float lsum[3][2] = {};

    const float* cbase = convp + ((size_t)bh * Nseq + q0 + mrow) * Nseq;

    for (int kt = 0; kt < 8; kt++) {
        const int cur = kt & 1;
        const int k0 = kt << 6;

        // prefetch next tile (overlaps with this tile's compute)
        if (kt < 7) {
            const int nk0 = (kt + 1) << 6;
            const float* Kn = Kb + (size_t)nk0 * DKd;
            const float* Vn = Vb + (size_t)nk0 * DKd;
            const int nxt = cur ^ 1;
            CP16(smaddr(&KS(nxt, pr0, sc4)),  Kn + srow0*32 + sc4);
            CP16(smaddr(&KS(nxt, pr1, sc4)),  Kn + srow1*32 + sc4);
            CP16(smaddr(&VS(nxt, srow0, sc4)), Vn + srow0*32 + sc4);
            CP16(smaddr(&VS(nxt, srow1, sc4)), Vn + srow1*32 + sc4);
            CPCOMMIT();
        }

        // conv prefetch for this tile
        float2 cc[4][2];
        #pragma unroll
        for (int nt = 0; nt < 4; nt++)
            #pragma unroll
            for (int rr = 0; rr < 2; rr++)
                cc[nt][rr] = *(const float2*)&cbase[(size_t)(g + rr*8) * Nseq
                                                    + k0 + keybase + nt*8 + 2*r4];

        // ---- S = Q K^T (permuted key columns) ----
        float s[4][4] = {};
        #pragma unroll
        for (int ks = 0; ks < 4; ks++) {
            #pragma unroll
            for (int nt = 0; nt < 4; nt++) {
                unsigned b0 = __float_as_uint(KS(cur, keybase + nt*8 + g, ks*8 + r4    ));
                unsigned b1 = __float_as_uint(KS(cur, keybase + nt*8 + g, ks*8 + r4 + 4));
                mma_tf32(s[nt], qa[ks], b0, b1);
            }
        }

        // ---- fused exp + 3-bar PV, E in registers ----
        #pragma unroll
        for (int nt = 0; nt < 4; nt++) {
            const float2 cR0 = cc[nt][0];
            const float2 cR1 = cc[nt][1];
            unsigned m0 = __float_as_uint(cR0.x) & 3u;
            unsigned m1 = __float_as_uint(cR0.y) & 3u;
            unsigned m2 = __float_as_uint(cR1.x) & 3u;
            unsigned m3 = __float_as_uint(cR1.y) & 3u;
            float e0 = fexp(s[nt][0] * cR0.x);
            float e1 = fexp(s[nt][1] * cR0.y);
            float e2 = fexp(s[nt][2] * cR1.x);
            float e3 = fexp(s[nt][3] * cR1.y);
            e0 = (m0 == 3u) ? 0.f : e0;
            e1 = (m1 == 3u) ? 0.f : e1;
            e2 = (m2 == 3u) ? 0.f : e2;
            e3 = (m3 == 3u) ? 0.f : e3;
            float b10 = (m0 < 2u) ? e0 : 0.f;
            float b11 = (m1 < 2u) ? e1 : 0.f;
            float b12 = (m2 < 2u) ? e2 : 0.f;
            float b13 = (m3 < 2u) ? e3 : 0.f;
            float b00 = (m0 == 0u) ? e0 : 0.f;
            float b01 = (m1 == 0u) ? e1 : 0.f;
            float b02 = (m2 == 0u) ? e2 : 0.f;
            float b03 = (m3 == 0u) ? e3 : 0.f;
            lsum[2][0] += e0 + e1;   lsum[2][1] += e2 + e3;
            lsum[1][0] += b10 + b11; lsum[1][1] += b12 + b13;
            lsum[0][0] += b00 + b01; lsum[0][1] += b02 + b03;
            unsigned a2[4] = {__float_as_uint(e0),  __float_as_uint(e2),
                              __float_as_uint(e1),  __float_as_uint(e3)};
            unsigned a1[4] = {__float_as_uint(b10), __float_as_uint(b12),
                              __float_as_uint(b11), __float_as_uint(b13)};
            unsigned a0[4] = {__float_as_uint(b00), __float_as_uint(b02),
                              __float_as_uint(b01), __float_as_uint(b03)};
            const int kk = keybase + nt*8;
            #pragma unroll
            for (int dnt = 0; dnt < 4; dnt++) {
                unsigned vb0 = __float_as_uint(VS(cur, kk + r4,     dnt*8 + g));
                unsigned vb1 = __float_as_uint(VS(cur, kk + r4 + 4, dnt*8 + g));
                mma_tf32(o[2][dnt], a2, vb0, vb1);
                mma_tf32(o[1][dnt], a1, vb0, vb1);
                mma_tf32(o[0][dnt], a0, vb0, vb1);
            }
        }

        if (kt < 7) {
            CPWAIT0();
            __syncthreads();
        }
    }

    // ---- lane-reduce lsum, publish per-wg sums ----
    __syncthreads();
    float* lsX = wg ? lsB : lsA;
    #pragma unroll
    for (int bar = 0; bar < 3; bar++)
        #pragma unroll
        for (int rr = 0; rr < 2; rr++) {
            float v = lsum[bar][rr];
            v += __shfl_xor_sync(0xffffffffu, v, 1);
            v += __shfl_xor_sync(0xffffffffu, v, 2);
            if (r4 == 0) lsX[bar*64 + mrow + g + rr*8] = v;
        }

    if (wg == 1) {
        const int idx = tid - 128;
        #pragma unroll
        for (int bar = 0; bar < 3; bar++)
            #pragma unroll
            for (int nt = 0; nt < 4; nt++)
                *(float4*)&dump[(idx*12 + bar*4 + nt)*4] =
                    make_float4(o[bar][nt][0], o[bar][nt][1], o[bar][nt][2], o[bar][nt][3]);
    }
    __syncthreads();

    if (wg == 0) {
        const int idx = tid;
        const int rowA = q0 + mrow + g;
        const int rowB = rowA + 8;
        #pragma unroll
        for (int bar = 0; bar < 3; bar++) {
            const float rlA = 1.f / (lsA[bar*64 + mrow + g    ] + lsB[bar*64 + mrow + g    ]);
            const float rlB = 1.f / (lsA[bar*64 + mrow + g + 8] + lsB[bar*64 + mrow + g + 8]);
            #pragma unroll
            for (int nt = 0; nt < 4; nt++) {
                float4 p = *(const float4*)&dump[(idx*12 + bar*4 + nt)*4];
                const int col = bar*Edim + h*DKd + nt*8 + 2*r4;
                size_t baseA = ((size_t)b*Nseq + rowA) * (3*Edim) + col;
                size_t baseB = ((size_t)b*Nseq + rowB) * (3*Edim) + col;
                *(float2*)&xcat[baseA] = make_float2((o[bar][nt][0] + p.x)*rlA,
                                                     (o[bar][nt][1] + p.y)*rlA);
                *(float2*)&xcat[baseB] = make_float2((o[bar][nt][2] + p.z)*rlB,
                                                     (o[bar][nt][3] + p.w)*rlB);
            }
        }
    }
#undef KS
#undef VS
}

// ---------------- host launcher: forked streams --------------------------------
extern "C" void kernel_launch(void* const* d_in, const int* in_sizes, int n_in,
                              void* d_out, int out_size)
{
    const float* query = (const float*)d_in[0];
    const float* key   = (const float*)d_in[1];
    const float* value = (const float*)d_in[2];
    const float* dist  = (const float*)d_in[3];
    const int*   mask  = (const int*)d_in[4];
    const float* Wq = (const float*)d_in[5];
    const float* bq = (const float*)d_in[6];
    const float* Wk = (const float*)d_in[7];
    const float* bk = (const float*)d_in[8];
    const float* Wv = (const float*)d_in[9];
    const float* bv = (const float*)d_in[10];
    const float* Wo = (const float*)d_in[11];
    const float* bo = (const float*)d_in[12];
    const float* cw1 = (const float*)d_in[13];
    const float* cb1 = (const float*)d_in[14];
    const float* cw2 = (const float*)d_in[15];
    const float* cb2 = (const float*)d_in[16];
    const float* Ws1 = (const float*)d_in[17];
    const float* bs1 = (const float*)d_in[18];
    const float* Ws2 = (const float*)d_in[19];
    const float* bs2 = (const float*)d_in[20];
    float* out = (float*)d_out;

    float *q_p, *k_p, *v_p, *x_p, *h1_p, *wcat_p, *bfull_p, *zero_p, *conv_p;
    float *tA_p, *tB_p;
    cudaGetSymbolAddress((void**)&q_p,    g_q);
    cudaGetSymbolAddress((void**)&k_p,    g_k);
    cudaGetSymbolAddress((void**)&v_p,    g_v);
    cudaGetSymbolAddress((void**)&x_p,    g_x);
    cudaGetSymbolAddress((void**)&h1_p,   g_h1);
    cudaGetSymbolAddress((void**)&wcat_p, g_wcat);
    cudaGetSymbolAddress((void**)&bfull_p,g_bfull);
    cudaGetSymbolAddress((void**)&zero_p, g_zero);
    cudaGetSymbolAddress((void**)&conv_p, g_conv);
    cudaGetSymbolAddress((void**)&tA_p,   g_tblA);
    cudaGetSymbolAddress((void**)&tB_p,   g_tblB);

    static cudaStream_t sB = nullptr, sC = nullptr;
    static cudaEvent_t evRoot = nullptr, evB = nullptr, evC = nullptr;
    if (sB == nullptr) {
        cudaStreamCreateWithFlags(&sB, cudaStreamNonBlocking);
        cudaStreamCreateWithFlags(&sC, cudaStreamNonBlocking);
        cudaEventCreateWithFlags(&evRoot, cudaEventDisableTiming);
        cudaEventCreateWithFlags(&evB,   cudaEventDisableTiming);
        cudaEventCreateWithFlags(&evC,   cudaEventDisableTiming);
        cudaFuncSetAttribute(attn_mma,
                             cudaFuncAttributeMaxDynamicSharedMemorySize, ATTN_SMEM);
    }

    const int M = Bq * Nseq;          // 4096
    dim3 blk(256);

    // ---- fork ----
    cudaEventRecord(evRoot, 0);
    cudaStreamWaitEvent(sB, evRoot, 0);
    cudaStreamWaitEvent(sC, evRoot, 0);

    // stream B: conv precompute (inputs only)
    tbl_kernel<<<1, 256, 0, sB>>>(cw1, cb1, cw2, cb2, tA_p, tB_p);
    conv_kernel<<<Bq * Nseq / 4, blk, 0, sB>>>(dist, mask, tA_p, tB_p, conv_p);
    cudaEventRecord(evB, sB);

    // stream C: Wcat + folded bias (weights only)
    {
        dim3 grid(Edim / 128, Edim / 64, 3);
        gemm_tc<<<grid, blk, 0, sC>>>(Wo, Wo, Wo,
                               Ws1, Ws1 + Edim*Edim, Ws1 + 2*Edim*Edim,
                               zero_p, zero_p, zero_p,
                               wcat_p, wcat_p + Edim*Edim, wcat_p + 2*Edim*Edim,
                               Edim, Edim, Edim, 0, 0);
        bias_fold<<<Edim / 16, 256, 0, sC>>>(bo, Ws1, bs1, bfull_p);
    }
    cudaEventRecord(evC, sC);

    // default: QKV projections (tf32-rounded outputs)
    {
        dim3 grid(M / 128, Edim / 64, 3);
        gemm_tc<<<grid, blk>>>(query, key, value,
                               Wq, Wk, Wv,
                               bq, bk, bv,
                               q_p, k_p, v_p,
                               Edim, Edim, 0, 0, 1);
    }

    cudaStreamWaitEvent(0, evB, 0);
    {
        dim3 grid(Nseq / 64, Bq * Hh);
        attn_mma<<<grid, 256, ATTN_SMEM>>>(q_p, k_p, v_p, conv_p, x_p);
    }

    cudaStreamWaitEvent(0, evC, 0);
    {
        dim3 grid(M / 128, Edim / 64, 1);
        gemm_tc<<<grid, blk>>>(x_p, x_p, x_p, wcat_p, wcat_p, wcat_p,
                               bfull_p, bfull_p, bfull_p,
                               h1_p, h1_p, h1_p, 3*Edim, Edim, Edim, 1, 0);
    }
    {
        dim3 grid(M / 128, Edim / 64, 1);
        gemm_tc<<<grid, blk>>>(h1_p, h1_p, h1_p, Ws2, Ws2, Ws2, bs2, bs2, bs2,
                               out, out, out, Edim, Edim, Edim, 0, 0);
    }
}

// round 16
// speedup vs baseline: 2.9989x; 1.1323x over previous
#include <cuda_runtime.h>
#include <math.h>

#define Bq   8
#define Nseq 512
#define Edim 256
#define Hh   8
#define DKd  32
#define SCALE 0.17677669529663687f   // 1/sqrt(32)

typedef unsigned long long ull;

// ---------------- scratch (device globals) ------------------------------------
__device__ float g_q[Bq*Hh*Nseq*DKd];
__device__ float g_k[Bq*Hh*Nseq*DKd];
__device__ float g_v[Bq*Hh*Nseq*DKd];
__device__ float g_x[Bq*Nseq*3*Edim];
__device__ float g_h1[Bq*Nseq*Edim];
__device__ float g_wcat[3*Edim*Edim];
__device__ float g_ws2r[Edim*Edim];                // tf32-rounded Ws2
__device__ float g_bfull[Edim];
__device__ float g_zero[Edim];
__device__ float g_conv[(size_t)Bq*Hh*Nseq*Nseq];  // conv*SCALE, code in 2 LSBs, key-permuted
__device__ float g_tblA[Hh*256];
__device__ float g_tblB[Hh*256];

// ---------------- tf32 / cp.async helpers --------------------------------------
__device__ __forceinline__ float tf32_of(float f) {
    unsigned u;
    asm("cvt.rna.tf32.f32 %0, %1;" : "=r"(u) : "f"(f));
    return __uint_as_float(u);
}
__device__ __forceinline__ void mma_tf32(float* d, const unsigned* a,
                                         unsigned b0, unsigned b1) {
    asm volatile(
        "mma.sync.aligned.m16n8k8.row.col.f32.tf32.tf32.f32 "
        "{%0,%1,%2,%3}, {%4,%5,%6,%7}, {%8,%9}, {%0,%1,%2,%3};"
        : "+f"(d[0]), "+f"(d[1]), "+f"(d[2]), "+f"(d[3])
        : "r"(a[0]), "r"(a[1]), "r"(a[2]), "r"(a[3]), "r"(b0), "r"(b1));
}
__device__ __forceinline__ float fexp(float x) {
    float e = fmaf(x, 0.041666667f, 0.16666667f);
    e = fmaf(e, x, 0.5f);
    e = fmaf(e, x, 1.0f);
    e = fmaf(e, x, 1.0f);
    if (fabsf(x) > 0.25f) e = __expf(x);
    return e;
}
__device__ __forceinline__ unsigned smaddr(const void* p) {
    unsigned a;
    asm("{ .reg .u64 t; cvta.to.shared.u64 t, %1; cvt.u32.u64 %0, t; }"
        : "=r"(a) : "l"(p));
    return a;
}
#define CP16(dst, src)  asm volatile("cp.async.ca.shared.global [%0], [%1], 16;" :: "r"(dst), "l"(src))
#define CPCOMMIT()      asm volatile("cp.async.commit_group;")
#define CPWAIT0()       asm volatile("cp.async.wait_group 0;" ::: "memory")
#define CPWAIT2()       asm volatile("cp.async.wait_group 2;" ::: "memory")

// ---------------- lerp table build ---------------------------------------------
__global__ void tbl_kernel(const float* __restrict__ cw1, const float* __restrict__ cb1,
                           const float* __restrict__ cw2, const float* __restrict__ cb2,
                           float* __restrict__ tblA, float* __restrict__ tblB)
{
    const int i = threadIdx.x;
    const float d0 = i * (1.0f/256.0f);
    const float d1 = (i+1) * (1.0f/256.0f);
    #pragma unroll
    for (int h = 0; h < 8; h++) {
        float f0 = cb2[h], f1 = cb2[h];
        #pragma unroll
        for (int t = 0; t < 8; t++) {
            float r0 = fmaxf(fmaf(d0, cw1[t], cb1[t]), 0.f);
            float r1 = fmaxf(fmaf(d1, cw1[t], cb1[t]), 0.f);
            f0 = fmaf(cw2[h*8 + t], r0, f0);
            f1 = fmaf(cw2[h*8 + t], r1, f1);
        }
        tblB[h*256 + i] = f0 * SCALE;
        tblA[h*256 + i] = (f1 - f0) * SCALE;
    }
}

// ---------------- round a tensor to tf32 ---------------------------------------
__global__ __launch_bounds__(256) void round_tf32(const float* __restrict__ in,
                                                  float* __restrict__ outp, int n)
{
    for (int i = blockIdx.x * 256 + threadIdx.x; i < n; i += gridDim.x * 256)
        outp[i] = tf32_of(in[i]);
}

// ---------------- conv precompute (key-permuted columns) -----------------------
__global__ __launch_bounds__(256) void conv_kernel(
    const float* __restrict__ dist, const int* __restrict__ mask,
    const float* __restrict__ tblA, const float* __restrict__ tblB,
    float* __restrict__ convp)
{
    __shared__ float sA[8][256], sB[8][256];
    const int tid = threadIdx.x;
    for (int t = tid; t < 2048; t += 256) {
        sA[t >> 8][t & 255] = tblA[t];
        sB[t >> 8][t & 255] = tblB[t];
    }
    __syncthreads();

    const int bi4 = blockIdx.x;
    const int b  = bi4 >> 7;
    const int i0 = (bi4 & 127) << 2;

    #pragma unroll
    for (int ri = 0; ri < 4; ri++) {
        const int i = i0 + ri;
        const float* drow = dist + ((size_t)b * Nseq + i) * Nseq;
        const int*   mrow = mask + ((size_t)b * Nseq + i) * Nseq;
        for (int j = tid; j < Nseq; j += 256) {
            float d = drow[j];
            int   m = mrow[j];
            unsigned code = (m == 0) ? 3u
                          : (i == 0 || j == 0) ? 0u
                          : (d < 0.3f) ? 0u : (d < 0.7f) ? 1u : 2u;
            float df = d * 256.0f;
            int idx = (int)df; idx = idx > 255 ? 255 : (idx < 0 ? 0 : idx);
            float frac = df - (float)idx;
            const int jp = (j & ~7) | (((j & 3) << 1) | ((j >> 2) & 1));
            #pragma unroll
            for (int h = 0; h < 8; h++) {
                float c = fmaf(frac, sA[h][idx], sB[h][idx]);
                unsigned u = (__float_as_uint(c) & ~3u) | code;
                convp[(((size_t)(b*Hh + h) * Nseq + i) * Nseq) + jp] = __uint_as_float(u);
            }
        }
    }
}

// ---------------- register-staged tf32 GEMM (QKV / Wcat) -----------------------
__global__ __launch_bounds__(256, 3) void gemm_tc(
    const float* __restrict__ A0, const float* __restrict__ A1, const float* __restrict__ A2,
    const float* __restrict__ W0, const float* __restrict__ W1, const float* __restrict__ W2,
    const float* __restrict__ bias0, const float* __restrict__ bias1, const float* __restrict__ bias2,
    float* __restrict__ C0, float* __restrict__ C1, float* __restrict__ C2,
    int Kd, int ldw, int ldc, int do_relu, int headsplit, int roundC)
{
    const int z = blockIdx.z;
    const float* A    = (z == 0) ? A0 : (z == 1) ? A1 : A2;
    const float* W    = (z == 0) ? W0 : (z == 1) ? W1 : W2;
    const float* bias = (z == 0) ? bias0 : (z == 1) ? bias1 : bias2;
    float*       C    = (z == 0) ? C0 : (z == 1) ? C1 : C2;

    __shared__ float As[2][16][136];
    __shared__ float Ws[2][16][72];

    const int m0 = blockIdx.x << 7;
    const int n0 = blockIdx.y << 6;
    const int tid = threadIdx.x;
    const int warp = tid >> 5, lane = tid & 31;
    const int g = lane >> 2, r4 = lane & 3;
    const int mb = (warp & 3) << 5;
    const int nb = (warp >> 2) << 5;

    const int ar = tid >> 1;
    const int ac = (tid & 1) << 3;
    const int wr = tid >> 4;
    const int wc = (tid & 15) << 2;

    const float* Aptr = A + (size_t)(m0 + ar) * Kd + ac;
    const float* Wptr = W + (size_t)wr * ldw + n0 + wc;

    float4 a0p = *(const float4*)(Aptr);
    float4 a1p = *(const float4*)(Aptr + 4);
    float4 wp  = *(const float4*)(Wptr);

    float c[2][4][4] = {};

    As[0][ac+0][ar] = tf32_of(a0p.x); As[0][ac+1][ar] = tf32_of(a0p.y);
    As[0][ac+2][ar] = tf32_of(a0p.z); As[0][ac+3][ar] = tf32_of(a0p.w);
    As[0][ac+4][ar] = tf32_of(a1p.x); As[0][ac+5][ar] = tf32_of(a1p.y);
    As[0][ac+6][ar] = tf32_of(a1p.z); As[0][ac+7][ar] = tf32_of(a1p.w);
    Ws[0][wr][wc+0] = tf32_of(wp.x);  Ws[0][wr][wc+1] = tf32_of(wp.y);
    Ws[0][wr][wc+2] = tf32_of(wp.z);  Ws[0][wr][wc+3] = tf32_of(wp.w);
    __syncthreads();

    const int nk = Kd >> 4;
    for (int kt = 0; kt < nk; kt++) {
        const int cur = kt & 1, nxt = cur ^ 1;
        if (kt + 1 < nk) {
            a0p = *(const float4*)(Aptr + (kt+1)*16);
            a1p = *(const float4*)(Aptr + (kt+1)*16 + 4);
            wp  = *(const float4*)(Wptr + (size_t)(kt+1)*16*ldw);
        }
        #pragma unroll
        for (int ks = 0; ks < 2; ks++) {
            unsigned af[2][4], bf[4][2];
            #pragma unroll
            for (int mt = 0; mt < 2; mt++) {
                const int row = mb + mt*16 + g;
                af[mt][0] = __float_as_uint(As[cur][ks*8 + r4    ][row    ]);
                af[mt][1] = __float_as_uint(As[cur][ks*8 + r4    ][row + 8]);
                af[mt][2] = __float_as_uint(As[cur][ks*8 + r4 + 4][row    ]);
                af[mt][3] = __float_as_uint(As[cur][ks*8 + r4 + 4][row + 8]);
            }
            #pragma unroll
            for (int nt = 0; nt < 4; nt++) {
                const int col = nb + nt*8 + g;
                bf[nt][0] = __float_as_uint(Ws[cur][ks*8 + r4    ][col]);
                bf[nt][1] = __float_as_uint(Ws[cur][ks*8 + r4 + 4][col]);
            }
            #pragma unroll
            for (int mt = 0; mt < 2; mt++)
                #pragma unroll
                for (int nt = 0; nt < 4; nt++)
                    mma_tf32(c[mt][nt], af[mt], bf[nt][0], bf[nt][1]);
        }
        if (kt + 1 < nk) {
            As[nxt][ac+0][ar] = tf32_of(a0p.x); As[nxt][ac+1][ar] = tf32_of(a0p.y);
            As[nxt][ac+2][ar] = tf32_of(a0p.z); As[nxt][ac+3][ar] = tf32_of(a0p.w);
            As[nxt][ac+4][ar] = tf32_of(a1p.x); As[nxt][ac+5][ar] = tf32_of(a1p.y);
            As[nxt][ac+6][ar] = tf32_of(a1p.z); As[nxt][ac+7][ar] = tf32_of(a1p.w);
            Ws[nxt][wr][wc+0] = tf32_of(wp.x);  Ws[nxt][wr][wc+1] = tf32_of(wp.y);
            Ws[nxt][wr][wc+2] = tf32_of(wp.z);  Ws[nxt][wr][wc+3] = tf32_of(wp.w);
        }
        __syncthreads();
    }

    #pragma unroll
    for (int nt = 0; nt < 4; nt++) {
        const int col0 = n0 + nb + nt*8 + 2*r4;
        const float2 bb = *(const float2*)&bias[col0];
        #pragma unroll
        for (int mt = 0; mt < 2; mt++) {
            const int row0 = m0 + mb + mt*16 + g;
            float2 v0 = make_float2(c[mt][nt][0] + bb.x, c[mt][nt][1] + bb.y);
            float2 v1 = make_float2(c[mt][nt][2] + bb.x, c[mt][nt][3] + bb.y);
            if (do_relu) {
                v0.x = fmaxf(v0.x, 0.f); v0.y = fmaxf(v0.y, 0.f);
                v1.x = fmaxf(v1.x, 0.f); v1.y = fmaxf(v1.y, 0.f);
            }
            if (roundC) {
                v0.x = tf32_of(v0.x); v0.y = tf32_of(v0.y);
                v1.x = tf32_of(v1.x); v1.y = tf32_of(v1.y);
            }
            if (headsplit) {
                v0.x = tf32_of(v0.x); v0.y = tf32_of(v0.y);
                v1.x = tf32_of(v1.x); v1.y = tf32_of(v1.y);
                const int h = col0 >> 5, d = col0 & 31;
                int b = row0 >> 9, n = row0 & 511;
                *(float2*)&C[(((size_t)(b*Hh + h))*Nseq + n)*DKd + d] = v0;
                b = (row0+8) >> 9; n = (row0+8) & 511;
                *(float2*)&C[(((size_t)(b*Hh + h))*Nseq + n)*DKd + d] = v1;
            } else {
                *(float2*)&C[(size_t)row0 * ldc + col0] = v0;
                *(float2*)&C[(size_t)(row0+8) * ldc + col0] = v1;
            }
        }
    }
}

// ---------------- 4-stage cp.async pipelined GEMM (pre-rounded operands) -------
// smem: As[4][128][20] @0 (10240 fl), Ws[4][16][72] @10240 (4608 fl) = 59392 B
#define GPL_SMEM 59392

__global__ __launch_bounds__(256, 2) void gemm_pl(
    const float* __restrict__ A, const float* __restrict__ W,
    const float* __restrict__ bias, float* __restrict__ C,
    int Kd, int ldw, int ldc, int do_relu, int roundC)
{
    extern __shared__ float sm[];
#define APL(st,m,k) sm[(st)*2560 + (m)*20 + (k)]
#define WPL(st,k,n) sm[10240 + (st)*1152 + (k)*72 + (n)]

    const int m0 = blockIdx.x << 7;
    const int n0 = blockIdx.y << 6;
    const int tid = threadIdx.x;
    const int warp = tid >> 5, lane = tid & 31;
    const int g = lane >> 2, r4 = lane & 3;
    const int mb = (warp & 3) << 5;
    const int nb = (warp >> 2) << 5;

    // staging geometry
    const int ar = tid >> 1;              // A row
    const int ac = (tid & 1) << 3;        // A k-offset (0 or 8)
    const int wr = tid >> 4;              // W k-row
    const int wc = (tid & 15) << 2;       // W n-offset

    const float* Abase = A + (size_t)(m0 + ar) * Kd + ac;
    const float* Wbase = W + (size_t)wr * ldw + n0 + wc;

    const int nk = Kd >> 4;

    // prologue: stages 0..2
    #pragma unroll
    for (int st = 0; st < 3; st++) {
        if (st < nk) {
            CP16(smaddr(&APL(st, ar, ac)),     Abase + st*16);
            CP16(smaddr(&APL(st, ar, ac + 4)), Abase + st*16 + 4);
            CP16(smaddr(&WPL(st, wr, wc)),     Wbase + (size_t)st*16*ldw);
        }
        CPCOMMIT();
    }

    float c[2][4][4] = {};

    for (int kt = 0; kt < nk; kt++) {
        CPWAIT2();
        __syncthreads();

        // issue stage kt+3 (overwrites buffer used by tile kt-1, already consumed)
        if (kt + 3 < nk) {
            const int st = (kt + 3) & 3;
            CP16(smaddr(&APL(st, ar, ac)),     Abase + (kt+3)*16);
            CP16(smaddr(&APL(st, ar, ac + 4)), Abase + (kt+3)*16 + 4);
            CP16(smaddr(&WPL(st, wr, wc)),     Wbase + (size_t)(kt+3)*16*ldw);
        }
        CPCOMMIT();

        const int cur = kt & 3;
        #pragma unroll
        for (int ks = 0; ks < 2; ks++) {
            unsigned af[2][4], bf[4][2];
            #pragma unroll
            for (int mt = 0; mt < 2; mt++) {
                const int row = mb + mt*16 + g;
                af[mt][0] = __float_as_uint(APL(cur, row,     ks*8 + r4    ));
                af[mt][1] = __float_as_uint(APL(cur, row + 8, ks*8 + r4    ));
                af[mt][2] = __float_as_uint(APL(cur, row,     ks*8 + r4 + 4));
                af[mt][3] = __float_as_uint(APL(cur, row + 8, ks*8 + r4 + 4));
            }
            #pragma unroll
            for (int nt = 0; nt < 4; nt++) {
                const int col = nb + nt*8 + g;
                bf[nt][0] = __float_as_uint(WPL(cur, ks*8 + r4,     col));
                bf[nt][1] = __float_as_uint(WPL(cur, ks*8 + r4 + 4, col));
            }
            #pragma unroll
            for (int mt = 0; mt < 2; mt++)
                #pragma unroll
                for (int nt = 0; nt < 4; nt++)
                    mma_tf32(c[mt][nt], af[mt], bf[nt][0], bf[nt][1]);
        }
    }

    #pragma unroll
    for (int nt = 0; nt < 4; nt++) {
        const int col0 = n0 + nb + nt*8 + 2*r4;
        const float2 bb = *(const float2*)&bias[col0];
        #pragma unroll
        for (int mt = 0; mt < 2; mt++) {
            const int row0 = m0 + mb + mt*16 + g;
            float2 v0 = make_float2(c[mt][nt][0] + bb.x, c[mt][nt][1] + bb.y);
            float2 v1 = make_float2(c[mt][nt][2] + bb.x, c[mt][nt][3] + bb.y);
            if (do_relu) {
                v0.x = fmaxf(v0.x, 0.f); v0.y = fmaxf(v0.y, 0.f);
                v1.x = fmaxf(v1.x, 0.f); v1.y = fmaxf(v1.y, 0.f);
            }
            if (roundC) {
                v0.x = tf32_of(v0.x); v0.y = tf32_of(v0.y);
                v1.x = tf32_of(v1.x); v1.y = tf32_of(v1.y);
            }
            *(float2*)&C[(size_t)row0 * ldc + col0] = v0;
            *(float2*)&C[(size_t)(row0+8) * ldc + col0] = v1;
        }
    }
#undef APL
#undef WPL
}

// ---------------- bias fold ----------------------------------------------------
__global__ __launch_bounds__(256) void bias_fold(
    const float* __restrict__ bo, const float* __restrict__ Ws1,
    const float* __restrict__ bs1, float* __restrict__ bfull)
{
    __shared__ float red[16][16];
    const int nl = threadIdx.x & 15;
    const int rg = threadIdx.x >> 4;
    const int n  = blockIdx.x * 16 + nl;
    float s = 0.f;
    for (int r = rg; r < 3*Edim; r += 16)
        s = fmaf(bo[r & (Edim-1)], Ws1[(size_t)r * Edim + n], s);
    red[rg][nl] = s;
    __syncthreads();
    if (rg == 0) {
        float t = 0.f;
        #pragma unroll
        for (int k = 0; k < 16; k++) t += red[k][nl];
        bfull[n] = bs1[n] + t;
    }
}

// ---------------- tf32 mma attention: cp.async double-buffered -----------------
#define ATTN_SMEM 49664

__global__ __launch_bounds__(256, 2) void attn_mma(
    const float* __restrict__ Q, const float* __restrict__ K, const float* __restrict__ V,
    const float* __restrict__ convp, float* __restrict__ xcat)
{
    extern __shared__ float sm[];
    float (*Qs)[36] = (float(*)[36])(sm);
    float* KsB  = sm + 2304;
    float* VsB  = sm + 6912;
    float* dump = sm;
    float* lsA  = sm + 12032;
    float* lsB  = sm + 12224;
#define KS(buf,row,col) KsB[(buf)*2304 + (row)*36 + (col)]
#define VS(buf,row,col) VsB[(buf)*2560 + (row)*40 + (col)]

    const int qt = blockIdx.x;
    const int bh = blockIdx.y;
    const int b = bh >> 3, h = bh & 7;
    const int q0 = qt << 6;
    const int tid = threadIdx.x;
    const int warp = tid >> 5, lane = tid & 31;
    const int g = lane >> 2, r4 = lane & 3;
    const int wg = warp >> 2;
    const int mwarp = warp & 3;
    const int mrow = mwarp << 4;
    const int keybase = wg << 5;

    const size_t headbase = (size_t)bh * Nseq * DKd;
    const float* Kb = K + headbase;
    const float* Vb = V + headbase;

    const int srow0 = tid >> 3, sc4 = (tid & 7) << 2;
    const int srow1 = srow0 + 32;
    const int pr0 = (srow0 & ~7) | (((srow0 & 3) << 1) | ((srow0 >> 2) & 1));
    const int pr1 = (srow1 & ~7) | (((srow1 & 3) << 1) | ((srow1 >> 2) & 1));

    const float* Qb = Q + headbase + (size_t)q0 * DKd;
    #pragma unroll
    for (int i = 0; i < 2; i++) {
        int idx = tid + i*256;
        int row = idx >> 3, c4 = (idx & 7) << 2;
        *(float4*)&Qs[row][c4] = *(const float4*)&Qb[row*32 + c4];
    }

    {
        CP16(smaddr(&KS(0, pr0, sc4)),  Kb + srow0*32 + sc4);
        CP16(smaddr(&KS(0, pr1, sc4)),  Kb + srow1*32 + sc4);
        CP16(smaddr(&VS(0, srow0, sc4)), Vb + srow0*32 + sc4);
        CP16(smaddr(&VS(0, srow1, sc4)), Vb + srow1*32 + sc4);
        CPCOMMIT();
    }
    CPWAIT0();
    __syncthreads();

    unsigned qa[4][4];
    #pragma unroll
    for (int ks = 0; ks < 4; ks++) {
        qa[ks][0] = __float_as_uint(Qs[mrow + g    ][ks*8 + r4    ]);
        qa[ks][1] = __float_as_uint(Qs[mrow + g + 8][ks*8 + r4    ]);
        qa[ks][2] = __float_as_uint(Qs[mrow + g    ][ks*8 + r4 + 4]);
        qa[ks][3] = __float_as_uint(Qs[mrow + g + 8][ks*8 + r4 + 4]);
    }

    float o[3][4][4] = {};
    float lsum[3][2] = {};

    const float* cbase = convp + ((size_t)bh * Nseq + q0 + mrow) * Nseq;

    for (int kt = 0; kt < 8; kt++) {
        const int cur = kt & 1;
        const int k0 = kt << 6;

        if (kt < 7) {
            const int nk0 = (kt + 1) << 6;
            const float* Kn = Kb + (size_t)nk0 * DKd;
            const float* Vn = Vb + (size_t)nk0 * DKd;
            const int nxt = cur ^ 1;
            CP16(smaddr(&KS(nxt, pr0, sc4)),  Kn + srow0*32 + sc4);
            CP16(smaddr(&KS(nxt, pr1, sc4)),  Kn + srow1*32 + sc4);
            CP16(smaddr(&VS(nxt, srow0, sc4)), Vn + srow0*32 + sc4);
            CP16(smaddr(&VS(nxt, srow1, sc4)), Vn + srow1*32 + sc4);
            CPCOMMIT();
        }

        float2 cc[4][2];
        #pragma unroll
        for (int nt = 0; nt < 4; nt++)
            #pragma unroll
            for (int rr = 0; rr < 2; rr++)
                cc[nt][rr] = *(const float2*)&cbase[(size_t)(g + rr*8) * Nseq
                                                    + k0 + keybase + nt*8 + 2*r4];

        float s[4][4] = {};
        #pragma unroll
        for (int ks = 0; ks < 4; ks++) {
            #pragma unroll
            for (int nt = 0; nt < 4; nt++) {
                unsigned b0 = __float_as_uint(KS(cur, keybase + nt*8 + g, ks*8 + r4    ));
                unsigned b1 = __float_as_uint(KS(cur, keybase + nt*8 + g, ks*8 + r4 + 4));
                mma_tf32(s[nt], qa[ks], b0, b1);
            }
        }

        #pragma unroll
        for (int nt = 0; nt < 4; nt++) {
            const float2 cR0 = cc[nt][0];
            const float2 cR1 = cc[nt][1];
            unsigned m0 = __float_as_uint(cR0.x) & 3u;
            unsigned m1 = __float_as_uint(cR0.y) & 3u;
            unsigned m2 = __float_as_uint(cR1.x) & 3u;
            unsigned m3 = __float_as_uint(cR1.y) & 3u;
            float e0 = fexp(s[nt][0] * cR0.x);
            float e1 = fexp(s[nt][1] * cR0.y);
            float e2 = fexp(s[nt][2] * cR1.x);
            float e3 = fexp(s[nt][3] * cR1.y);
            e0 = (m0 == 3u) ? 0.f : e0;
            e1 = (m1 == 3u) ? 0.f : e1;
            e2 = (m2 == 3u) ? 0.f : e2;
            e3 = (m3 == 3u) ? 0.f : e3;
            float b10 = (m0 < 2u) ? e0 : 0.f;
            float b11 = (m1 < 2u) ? e1 : 0.f;
            float b12 = (m2 < 2u) ? e2 : 0.f;
            float b13 = (m3 < 2u) ? e3 : 0.f;
            float b00 = (m0 == 0u) ? e0 : 0.f;
            float b01 = (m1 == 0u) ? e1 : 0.f;
            float b02 = (m2 == 0u) ? e2 : 0.f;
            float b03 = (m3 == 0u) ? e3 : 0.f;
            lsum[2][0] += e0 + e1;   lsum[2][1] += e2 + e3;
            lsum[1][0] += b10 + b11; lsum[1][1] += b12 + b13;
            lsum[0][0] += b00 + b01; lsum[0][1] += b02 + b03;
            unsigned a2[4] = {__float_as_uint(e0),  __float_as_uint(e2),
                              __float_as_uint(e1),  __float_as_uint(e3)};
            unsigned a1[4] = {__float_as_uint(b10), __float_as_uint(b12),
                              __float_as_uint(b11), __float_as_uint(b13)};
            unsigned a0[4] = {__float_as_uint(b00), __float_as_uint(b02),
                              __float_as_uint(b01), __float_as_uint(b03)};
            const int kk = keybase + nt*8;
            #pragma unroll
            for (int dnt = 0; dnt < 4; dnt++) {
                unsigned vb0 = __float_as_uint(VS(cur, kk + r4,     dnt*8 + g));
                unsigned vb1 = __float_as_uint(VS(cur, kk + r4 + 4, dnt*8 + g));
                mma_tf32(o[2][dnt], a2, vb0, vb1);
                mma_tf32(o[1][dnt], a1, vb0, vb1);
                mma_tf32(o[0][dnt], a0, vb0, vb1);
            }
        }

        if (kt < 7) {
            CPWAIT0();
            __syncthreads();
        }
    }

    __syncthreads();
    float* lsX = wg ? lsB : lsA;
    #pragma unroll
    for (int bar = 0; bar < 3; bar++)
        #pragma unroll
        for (int rr = 0; rr < 2; rr++) {
            float v = lsum[bar][rr];
            v += __shfl_xor_sync(0xffffffffu, v, 1);
            v += __shfl_xor_sync(0xffffffffu, v, 2);
            if (r4 == 0) lsX[bar*64 + mrow + g + rr*8] = v;
        }

    if (wg == 1) {
        const int idx = tid - 128;
        #pragma unroll
        for (int bar = 0; bar < 3; bar++)
            #pragma unroll
            for (int nt = 0; nt < 4; nt++)
                *(float4*)&dump[(idx*12 + bar*4 + nt)*4] =
                    make_float4(o[bar][nt][0], o[bar][nt][1], o[bar][nt][2], o[bar][nt][3]);
    }
    __syncthreads();

    if (wg == 0) {
        const int idx = tid;
        const int rowA = q0 + mrow + g;
        const int rowB = rowA + 8;
        #pragma unroll
        for (int bar = 0; bar < 3; bar++) {
            const float rlA = 1.f / (lsA[bar*64 + mrow + g    ] + lsB[bar*64 + mrow + g    ]);
            const float rlB = 1.f / (lsA[bar*64 + mrow + g + 8] + lsB[bar*64 + mrow + g + 8]);
            #pragma unroll
            for (int nt = 0; nt < 4; nt++) {
                float4 p = *(const float4*)&dump[(idx*12 + bar*4 + nt)*4];
                const int col = bar*Edim + h*DKd + nt*8 + 2*r4;
                size_t baseA = ((size_t)b*Nseq + rowA) * (3*Edim) + col;
                size_t baseB = ((size_t)b*Nseq + rowB) * (3*Edim) + col;
                // outputs rounded to tf32 so gemm_pl can stream them raw
                *(float2*)&xcat[baseA] = make_float2(tf32_of((o[bar][nt][0] + p.x)*rlA),
                                                     tf32_of((o[bar][nt][1] + p.y)*rlA));
                *(float2*)&xcat[baseB] = make_float2(tf32_of((o[bar][nt][2] + p.z)*rlB),
                                                     tf32_of((o[bar][nt][3] + p.w)*rlB));
            }
        }
    }
#undef KS
#undef VS
}

// ---------------- host launcher: forked streams --------------------------------
extern "C" void kernel_launch(void* const* d_in, const int* in_sizes, int n_in,
                              void* d_out, int out_size)
{
    const float* query = (const float*)d_in[0];
    const float* key   = (const float*)d_in[1];
    const float* value = (const float*)d_in[2];
    const float* dist  = (const float*)d_in[3];
    const int*   mask  = (const int*)d_in[4];
    const float* Wq = (const float*)d_in[5];
    const float* bq = (const float*)d_in[6];
    const float* Wk = (const float*)d_in[7];
    const float* bk = (const float*)d_in[8];
    const float* Wv = (const float*)d_in[9];
    const float* bv = (const float*)d_in[10];
    const float* Wo = (const float*)d_in[11];
    const float* bo = (const float*)d_in[12];
    const float* cw1 = (const float*)d_in[13];
    const float* cb1 = (const float*)d_in[14];
    const float* cw2 = (const float*)d_in[15];
    const float* cb2 = (const float*)d_in[16];
    const float* Ws1 = (const float*)d_in[17];
    const float* bs1 = (const float*)d_in[18];
    const float* Ws2 = (const float*)d_in[19];
    const float* bs2 = (const float*)d_in[20];
    float* out = (float*)d_out;

    float *q_p, *k_p, *v_p, *x_p, *h1_p, *wcat_p, *ws2r_p, *bfull_p, *zero_p, *conv_p;
    float *tA_p, *tB_p;
    cudaGetSymbolAddress((void**)&q_p,    g_q);
    cudaGetSymbolAddress((void**)&k_p,    g_k);
    cudaGetSymbolAddress((void**)&v_p,    g_v);
    cudaGetSymbolAddress((void**)&x_p,    g_x);
    cudaGetSymbolAddress((void**)&h1_p,   g_h1);
    cudaGetSymbolAddress((void**)&wcat_p, g_wcat);
    cudaGetSymbolAddress((void**)&ws2r_p, g_ws2r);
    cudaGetSymbolAddress((void**)&bfull_p,g_bfull);
    cudaGetSymbolAddress((void**)&zero_p, g_zero);
    cudaGetSymbolAddress((void**)&conv_p, g_conv);
    cudaGetSymbolAddress((void**)&tA_p,   g_tblA);
    cudaGetSymbolAddress((void**)&tB_p,   g_tblB);

    static cudaStream_t sB = nullptr, sC = nullptr;
    static cudaEvent_t evRoot = nullptr, evB = nullptr, evC = nullptr;
    if (sB == nullptr) {
        cudaStreamCreateWithFlags(&sB, cudaStreamNonBlocking);
        cudaStreamCreateWithFlags(&sC, cudaStreamNonBlocking);
        cudaEventCreateWithFlags(&evRoot, cudaEventDisableTiming);
        cudaEventCreateWithFlags(&evB,   cudaEventDisableTiming);
        cudaEventCreateWithFlags(&evC,   cudaEventDisableTiming);
        cudaFuncSetAttribute(attn_mma,
                             cudaFuncAttributeMaxDynamicSharedMemorySize, ATTN_SMEM);
        cudaFuncSetAttribute(gemm_pl,
                             cudaFuncAttributeMaxDynamicSharedMemorySize, GPL_SMEM);
    }

    const int M = Bq * Nseq;          // 4096
    dim3 blk(256);

    // ---- fork ----
    cudaEventRecord(evRoot, 0);
    cudaStreamWaitEvent(sB, evRoot, 0);
    cudaStreamWaitEvent(sC, evRoot, 0);

    // stream B: conv precompute (inputs only)
    tbl_kernel<<<1, 256, 0, sB>>>(cw1, cb1, cw2, cb2, tA_p, tB_p);
    conv_kernel<<<Bq * Nseq / 4, blk, 0, sB>>>(dist, mask, tA_p, tB_p, conv_p);
    cudaEventRecord(evB, sB);

    // stream C: Wcat (rounded), folded bias, rounded Ws2 (weights only)
    {
        dim3 grid(Edim / 128, Edim / 64, 3);
        gemm_tc<<<grid, blk, 0, sC>>>(Wo, Wo, Wo,
                               Ws1, Ws1 + Edim*Edim, Ws1 + 2*Edim*Edim,
                               zero_p, zero_p, zero_p,
                               wcat_p, wcat_p + Edim*Edim, wcat_p + 2*Edim*Edim,
                               Edim, Edim, Edim, 0, 0, 1);
        bias_fold<<<Edim / 16, 256, 0, sC>>>(bo, Ws1, bs1, bfull_p);
        round_tf32<<<64, 256, 0, sC>>>(Ws2, ws2r_p, Edim * Edim);
    }
    cudaEventRecord(evC, sC);

    // default: QKV projections (tf32-rounded outputs)
    {
        dim3 grid(M / 128, Edim / 64, 3);
        gemm_tc<<<grid, blk>>>(query, key, value,
                               Wq, Wk, Wv,
                               bq, bk, bv,
                               q_p, k_p, v_p,
                               Edim, Edim, 0, 0, 1, 0);
    }

    cudaStreamWaitEvent(0, evB, 0);
    {
        dim3 grid(Nseq / 64, Bq * Hh);
        attn_mma<<<grid, 256, ATTN_SMEM>>>(q_p, k_p, v_p, conv_p, x_p);
    }

    cudaStreamWaitEvent(0, evC, 0);
    // h1 = relu(xcat @ Wcat + bfull), output rounded for the next stage
    {
        dim3 grid(M / 128, Edim / 64);
        gemm_pl<<<grid, blk, GPL_SMEM>>>(x_p, wcat_p, bfull_p, h1_p,
                                         3*Edim, Edim, Edim, 1, 1);
    }
    // out = h1 @ Ws2r + bs2
    {
        dim3 grid(M / 128, Edim / 64);
        gemm_pl<<<grid, blk, GPL_SMEM>>>(h1_p, ws2r_p, bs2, out,
                                         Edim, Edim, Edim, 0, 0);
    }
}

// round 17
// speedup vs baseline: 3.0436x; 1.0149x over previous
#include <cuda_runtime.h>
#include <math.h>

#define Bq   8
#define Nseq 512
#define Edim 256
#define Hh   8
#define DKd  32
#define SCALE 0.17677669529663687f   // 1/sqrt(32)

typedef unsigned long long ull;

// ---------------- scratch (device globals) ------------------------------------
__device__ float g_q[Bq*Hh*Nseq*DKd];
__device__ float g_k[Bq*Hh*Nseq*DKd];
__device__ float g_v[Bq*Hh*Nseq*DKd];
__device__ float g_x[Bq*Nseq*3*Edim];
__device__ float g_h1[Bq*Nseq*Edim];
__device__ float g_wcat[3*Edim*Edim];
__device__ float g_ws2r[Edim*Edim];                // tf32-rounded Ws2
__device__ float g_bfull[Edim];
__device__ float g_zero[Edim];
__device__ float g_conv[(size_t)Bq*Hh*Nseq*Nseq];  // conv*SCALE, code in 2 LSBs, key-permuted
__device__ float g_tblA[Hh*256];
__device__ float g_tblB[Hh*256];

// ---------------- tf32 / cp.async helpers --------------------------------------
__device__ __forceinline__ float tf32_of(float f) {
    unsigned u;
    asm("cvt.rna.tf32.f32 %0, %1;" : "=r"(u) : "f"(f));
    return __uint_as_float(u);
}
__device__ __forceinline__ unsigned tf32_bits(float f) {
    unsigned u;
    asm("cvt.rna.tf32.f32 %0, %1;" : "=r"(u) : "f"(f));
    return u;
}
__device__ __forceinline__ void mma_tf32(float* d, const unsigned* a,
                                         unsigned b0, unsigned b1) {
    asm volatile(
        "mma.sync.aligned.m16n8k8.row.col.f32.tf32.tf32.f32 "
        "{%0,%1,%2,%3}, {%4,%5,%6,%7}, {%8,%9}, {%0,%1,%2,%3};"
        : "+f"(d[0]), "+f"(d[1]), "+f"(d[2]), "+f"(d[3])
        : "r"(a[0]), "r"(a[1]), "r"(a[2]), "r"(a[3]), "r"(b0), "r"(b1));
}
__device__ __forceinline__ float fexp(float x) {
    float e = fmaf(x, 0.041666667f, 0.16666667f);
    e = fmaf(e, x, 0.5f);
    e = fmaf(e, x, 1.0f);
    e = fmaf(e, x, 1.0f);
    if (fabsf(x) > 0.25f) e = __expf(x);
    return e;
}
__device__ __forceinline__ unsigned smaddr(const void* p) {
    unsigned a;
    asm("{ .reg .u64 t; cvta.to.shared.u64 t, %1; cvt.u32.u64 %0, t; }"
        : "=r"(a) : "l"(p));
    return a;
}
#define CP16(dst, src)  asm volatile("cp.async.ca.shared.global [%0], [%1], 16;" :: "r"(dst), "l"(src))
#define CPCOMMIT()      asm volatile("cp.async.commit_group;")
#define CPWAIT0()       asm volatile("cp.async.wait_group 0;" ::: "memory")
#define CPWAIT2()       asm volatile("cp.async.wait_group 2;" ::: "memory")

// ---------------- lerp table build ---------------------------------------------
__global__ void tbl_kernel(const float* __restrict__ cw1, const float* __restrict__ cb1,
                           const float* __restrict__ cw2, const float* __restrict__ cb2,
                           float* __restrict__ tblA, float* __restrict__ tblB)
{
    const int i = threadIdx.x;
    const float d0 = i * (1.0f/256.0f);
    const float d1 = (i+1) * (1.0f/256.0f);
    #pragma unroll
    for (int h = 0; h < 8; h++) {
        float f0 = cb2[h], f1 = cb2[h];
        #pragma unroll
        for (int t = 0; t < 8; t++) {
            float r0 = fmaxf(fmaf(d0, cw1[t], cb1[t]), 0.f);
            float r1 = fmaxf(fmaf(d1, cw1[t], cb1[t]), 0.f);
            f0 = fmaf(cw2[h*8 + t], r0, f0);
            f1 = fmaf(cw2[h*8 + t], r1, f1);
        }
        tblB[h*256 + i] = f0 * SCALE;
        tblA[h*256 + i] = (f1 - f0) * SCALE;
    }
}

// ---------------- round a tensor to tf32 ---------------------------------------
__global__ __launch_bounds__(256) void round_tf32(const float* __restrict__ in,
                                                  float* __restrict__ outp, int n)
{
    for (int i = blockIdx.x * 256 + threadIdx.x; i < n; i += gridDim.x * 256)
        outp[i] = tf32_of(in[i]);
}

// ---------------- conv precompute (key-permuted columns) -----------------------
__global__ __launch_bounds__(256) void conv_kernel(
    const float* __restrict__ dist, const int* __restrict__ mask,
    const float* __restrict__ tblA, const float* __restrict__ tblB,
    float* __restrict__ convp)
{
    __shared__ float sA[8][256], sB[8][256];
    const int tid = threadIdx.x;
    for (int t = tid; t < 2048; t += 256) {
        sA[t >> 8][t & 255] = tblA[t];
        sB[t >> 8][t & 255] = tblB[t];
    }
    __syncthreads();

    const int bi4 = blockIdx.x;
    const int b  = bi4 >> 7;
    const int i0 = (bi4 & 127) << 2;

    #pragma unroll
    for (int ri = 0; ri < 4; ri++) {
        const int i = i0 + ri;
        const float* drow = dist + ((size_t)b * Nseq + i) * Nseq;
        const int*   mrow = mask + ((size_t)b * Nseq + i) * Nseq;
        for (int j = tid; j < Nseq; j += 256) {
            float d = drow[j];
            int   m = mrow[j];
            unsigned code = (m == 0) ? 3u
                          : (i == 0 || j == 0) ? 0u
                          : (d < 0.3f) ? 0u : (d < 0.7f) ? 1u : 2u;
            float df = d * 256.0f;
            int idx = (int)df; idx = idx > 255 ? 255 : (idx < 0 ? 0 : idx);
            float frac = df - (float)idx;
            const int jp = (j & ~7) | (((j & 3) << 1) | ((j >> 2) & 1));
            #pragma unroll
            for (int h = 0; h < 8; h++) {
                float c = fmaf(frac, sA[h][idx], sB[h][idx]);
                unsigned u = (__float_as_uint(c) & ~3u) | code;
                convp[(((size_t)(b*Hh + h) * Nseq + i) * Nseq) + jp] = __uint_as_float(u);
            }
        }
    }
}

// ---------------- register-staged tf32 GEMM (Wcat in stream C) -----------------
__global__ __launch_bounds__(256, 3) void gemm_tc(
    const float* __restrict__ A0, const float* __restrict__ A1, const float* __restrict__ A2,
    const float* __restrict__ W0, const float* __restrict__ W1, const float* __restrict__ W2,
    const float* __restrict__ bias0, const float* __restrict__ bias1, const float* __restrict__ bias2,
    float* __restrict__ C0, float* __restrict__ C1, float* __restrict__ C2,
    int Kd, int ldw, int ldc, int do_relu, int headsplit, int roundC)
{
    const int z = blockIdx.z;
    const float* A    = (z == 0) ? A0 : (z == 1) ? A1 : A2;
    const float* W    = (z == 0) ? W0 : (z == 1) ? W1 : W2;
    const float* bias = (z == 0) ? bias0 : (z == 1) ? bias1 : bias2;
    float*       C    = (z == 0) ? C0 : (z == 1) ? C1 : C2;

    __shared__ float As[2][16][136];
    __shared__ float Ws[2][16][72];

    const int m0 = blockIdx.x << 7;
    const int n0 = blockIdx.y << 6;
    const int tid = threadIdx.x;
    const int warp = tid >> 5, lane = tid & 31;
    const int g = lane >> 2, r4 = lane & 3;
    const int mb = (warp & 3) << 5;
    const int nb = (warp >> 2) << 5;

    const int ar = tid >> 1;
    const int ac = (tid & 1) << 3;
    const int wr = tid >> 4;
    const int wc = (tid & 15) << 2;

    const float* Aptr = A + (size_t)(m0 + ar) * Kd + ac;
    const float* Wptr = W + (size_t)wr * ldw + n0 + wc;

    float4 a0p = *(const float4*)(Aptr);
    float4 a1p = *(const float4*)(Aptr + 4);
    float4 wp  = *(const float4*)(Wptr);

    float c[2][4][4] = {};

    As[0][ac+0][ar] = tf32_of(a0p.x); As[0][ac+1][ar] = tf32_of(a0p.y);
    As[0][ac+2][ar] = tf32_of(a0p.z); As[0][ac+3][ar] = tf32_of(a0p.w);
    As[0][ac+4][ar] = tf32_of(a1p.x); As[0][ac+5][ar] = tf32_of(a1p.y);
    As[0][ac+6][ar] = tf32_of(a1p.z); As[0][ac+7][ar] = tf32_of(a1p.w);
    Ws[0][wr][wc+0] = tf32_of(wp.x);  Ws[0][wr][wc+1] = tf32_of(wp.y);
    Ws[0][wr][wc+2] = tf32_of(wp.z);  Ws[0][wr][wc+3] = tf32_of(wp.w);
    __syncthreads();

    const int nk = Kd >> 4;
    for (int kt = 0; kt < nk; kt++) {
        const int cur = kt & 1, nxt = cur ^ 1;
        if (kt + 1 < nk) {
            a0p = *(const float4*)(Aptr + (kt+1)*16);
            a1p = *(const float4*)(Aptr + (kt+1)*16 + 4);
            wp  = *(const float4*)(Wptr + (size_t)(kt+1)*16*ldw);
        }
        #pragma unroll
        for (int ks = 0; ks < 2; ks++) {
            unsigned af[2][4], bf[4][2];
            #pragma unroll
            for (int mt = 0; mt < 2; mt++) {
                const int row = mb + mt*16 + g;
                af[mt][0] = __float_as_uint(As[cur][ks*8 + r4    ][row    ]);
                af[mt][1] = __float_as_uint(As[cur][ks*8 + r4    ][row + 8]);
                af[mt][2] = __float_as_uint(As[cur][ks*8 + r4 + 4][row    ]);
                af[mt][3] = __float_as_uint(As[cur][ks*8 + r4 + 4][row + 8]);
            }
            #pragma unroll
            for (int nt = 0; nt < 4; nt++) {
                const int col = nb + nt*8 + g;
                bf[nt][0] = __float_as_uint(Ws[cur][ks*8 + r4    ][col]);
                bf[nt][1] = __float_as_uint(Ws[cur][ks*8 + r4 + 4][col]);
            }
            #pragma unroll
            for (int mt = 0; mt < 2; mt++)
                #pragma unroll
                for (int nt = 0; nt < 4; nt++)
                    mma_tf32(c[mt][nt], af[mt], bf[nt][0], bf[nt][1]);
        }
        if (kt + 1 < nk) {
            As[nxt][ac+0][ar] = tf32_of(a0p.x); As[nxt][ac+1][ar] = tf32_of(a0p.y);
            As[nxt][ac+2][ar] = tf32_of(a0p.z); As[nxt][ac+3][ar] = tf32_of(a0p.w);
            As[nxt][ac+4][ar] = tf32_of(a1p.x); As[nxt][ac+5][ar] = tf32_of(a1p.y);
            As[nxt][ac+6][ar] = tf32_of(a1p.z); As[nxt][ac+7][ar] = tf32_of(a1p.w);
            Ws[nxt][wr][wc+0] = tf32_of(wp.x);  Ws[nxt][wr][wc+1] = tf32_of(wp.y);
            Ws[nxt][wr][wc+2] = tf32_of(wp.z);  Ws[nxt][wr][wc+3] = tf32_of(wp.w);
        }
        __syncthreads();
    }

    #pragma unroll
    for (int nt = 0; nt < 4; nt++) {
        const int col0 = n0 + nb + nt*8 + 2*r4;
        const float2 bb = *(const float2*)&bias[col0];
        #pragma unroll
        for (int mt = 0; mt < 2; mt++) {
            const int row0 = m0 + mb + mt*16 + g;
            float2 v0 = make_float2(c[mt][nt][0] + bb.x, c[mt][nt][1] + bb.y);
            float2 v1 = make_float2(c[mt][nt][2] + bb.x, c[mt][nt][3] + bb.y);
            if (do_relu) {
                v0.x = fmaxf(v0.x, 0.f); v0.y = fmaxf(v0.y, 0.f);
                v1.x = fmaxf(v1.x, 0.f); v1.y = fmaxf(v1.y, 0.f);
            }
            if (roundC) {
                v0.x = tf32_of(v0.x); v0.y = tf32_of(v0.y);
                v1.x = tf32_of(v1.x); v1.y = tf32_of(v1.y);
            }
            if (headsplit) {
                v0.x = tf32_of(v0.x); v0.y = tf32_of(v0.y);
                v1.x = tf32_of(v1.x); v1.y = tf32_of(v1.y);
                const int h = col0 >> 5, d = col0 & 31;
                int b = row0 >> 9, n = row0 & 511;
                *(float2*)&C[(((size_t)(b*Hh + h))*Nseq + n)*DKd + d] = v0;
                b = (row0+8) >> 9; n = (row0+8) & 511;
                *(float2*)&C[(((size_t)(b*Hh + h))*Nseq + n)*DKd + d] = v1;
            } else {
                *(float2*)&C[(size_t)row0 * ldc + col0] = v0;
                *(float2*)&C[(size_t)(row0+8) * ldc + col0] = v1;
            }
        }
    }
}

// ---------------- 4-stage cp.async pipelined GEMM (pre-rounded operands) -------
// smem: As[4][128][20] @0 (10240 fl), Ws[4][16][72] @10240 (4608 fl) = 59392 B
#define GPL_SMEM 59392

__global__ __launch_bounds__(256, 2) void gemm_pl(
    const float* __restrict__ A, const float* __restrict__ W,
    const float* __restrict__ bias, float* __restrict__ C,
    int Kd, int ldw, int ldc, int do_relu, int roundC)
{
    extern __shared__ float sm[];
#define APL(st,m,k) sm[(st)*2560 + (m)*20 + (k)]
#define WPL(st,k,n) sm[10240 + (st)*1152 + (k)*72 + (n)]

    const int m0 = blockIdx.x << 7;
    const int n0 = blockIdx.y << 6;
    const int tid = threadIdx.x;
    const int warp = tid >> 5, lane = tid & 31;
    const int g = lane >> 2, r4 = lane & 3;
    const int mb = (warp & 3) << 5;
    const int nb = (warp >> 2) << 5;

    const int ar = tid >> 1;
    const int ac = (tid & 1) << 3;
    const int wr = tid >> 4;
    const int wc = (tid & 15) << 2;

    const float* Abase = A + (size_t)(m0 + ar) * Kd + ac;
    const float* Wbase = W + (size_t)wr * ldw + n0 + wc;

    const int nk = Kd >> 4;

    #pragma unroll
    for (int st = 0; st < 3; st++) {
        if (st < nk) {
            CP16(smaddr(&APL(st, ar, ac)),     Abase + st*16);
            CP16(smaddr(&APL(st, ar, ac + 4)), Abase + st*16 + 4);
            CP16(smaddr(&WPL(st, wr, wc)),     Wbase + (size_t)st*16*ldw);
        }
        CPCOMMIT();
    }

    float c[2][4][4] = {};

    for (int kt = 0; kt < nk; kt++) {
        CPWAIT2();
        __syncthreads();

        if (kt + 3 < nk) {
            const int st = (kt + 3) & 3;
            CP16(smaddr(&APL(st, ar, ac)),     Abase + (kt+3)*16);
            CP16(smaddr(&APL(st, ar, ac + 4)), Abase + (kt+3)*16 + 4);
            CP16(smaddr(&WPL(st, wr, wc)),     Wbase + (size_t)(kt+3)*16*ldw);
        }
        CPCOMMIT();

        const int cur = kt & 3;
        #pragma unroll
        for (int ks = 0; ks < 2; ks++) {
            unsigned af[2][4], bf[4][2];
            #pragma unroll
            for (int mt = 0; mt < 2; mt++) {
                const int row = mb + mt*16 + g;
                af[mt][0] = __float_as_uint(APL(cur, row,     ks*8 + r4    ));
                af[mt][1] = __float_as_uint(APL(cur, row + 8, ks*8 + r4    ));
                af[mt][2] = __float_as_uint(APL(cur, row,     ks*8 + r4 + 4));
                af[mt][3] = __float_as_uint(APL(cur, row + 8, ks*8 + r4 + 4));
            }
            #pragma unroll
            for (int nt = 0; nt < 4; nt++) {
                const int col = nb + nt*8 + g;
                bf[nt][0] = __float_as_uint(WPL(cur, ks*8 + r4,     col));
                bf[nt][1] = __float_as_uint(WPL(cur, ks*8 + r4 + 4, col));
            }
            #pragma unroll
            for (int mt = 0; mt < 2; mt++)
                #pragma unroll
                for (int nt = 0; nt < 4; nt++)
                    mma_tf32(c[mt][nt], af[mt], bf[nt][0], bf[nt][1]);
        }
    }

    #pragma unroll
    for (int nt = 0; nt < 4; nt++) {
        const int col0 = n0 + nb + nt*8 + 2*r4;
        const float2 bb = *(const float2*)&bias[col0];
        #pragma unroll
        for (int mt = 0; mt < 2; mt++) {
            const int row0 = m0 + mb + mt*16 + g;
            float2 v0 = make_float2(c[mt][nt][0] + bb.x, c[mt][nt][1] + bb.y);
            float2 v1 = make_float2(c[mt][nt][2] + bb.x, c[mt][nt][3] + bb.y);
            if (do_relu) {
                v0.x = fmaxf(v0.x, 0.f); v0.y = fmaxf(v0.y, 0.f);
                v1.x = fmaxf(v1.x, 0.f); v1.y = fmaxf(v1.y, 0.f);
            }
            if (roundC) {
                v0.x = tf32_of(v0.x); v0.y = tf32_of(v0.y);
                v1.x = tf32_of(v1.x); v1.y = tf32_of(v1.y);
            }
            *(float2*)&C[(size_t)row0 * ldc + col0] = v0;
            *(float2*)&C[(size_t)(row0+8) * ldc + col0] = v1;
        }
    }
#undef APL
#undef WPL
}

// ---------------- 4-stage pipelined QKV GEMM: cvt at consume, headsplit --------
__global__ __launch_bounds__(256, 2) void gemm_plc(
    const float* __restrict__ A0, const float* __restrict__ A1, const float* __restrict__ A2,
    const float* __restrict__ W0, const float* __restrict__ W1, const float* __restrict__ W2,
    const float* __restrict__ bias0, const float* __restrict__ bias1, const float* __restrict__ bias2,
    float* __restrict__ C0, float* __restrict__ C1, float* __restrict__ C2,
    int Kd, int ldw)
{
    extern __shared__ float sm[];
#define APL(st,m,k) sm[(st)*2560 + (m)*20 + (k)]
#define WPL(st,k,n) sm[10240 + (st)*1152 + (k)*72 + (n)]

    const int z = blockIdx.z;
    const float* A    = (z == 0) ? A0 : (z == 1) ? A1 : A2;
    const float* W    = (z == 0) ? W0 : (z == 1) ? W1 : W2;
    const float* bias = (z == 0) ? bias0 : (z == 1) ? bias1 : bias2;
    float*       C    = (z == 0) ? C0 : (z == 1) ? C1 : C2;

    const int m0 = blockIdx.x << 7;
    const int n0 = blockIdx.y << 6;
    const int tid = threadIdx.x;
    const int warp = tid >> 5, lane = tid & 31;
    const int g = lane >> 2, r4 = lane & 3;
    const int mb = (warp & 3) << 5;
    const int nb = (warp >> 2) << 5;

    const int ar = tid >> 1;
    const int ac = (tid & 1) << 3;
    const int wr = tid >> 4;
    const int wc = (tid & 15) << 2;

    const float* Abase = A + (size_t)(m0 + ar) * Kd + ac;
    const float* Wbase = W + (size_t)wr * ldw + n0 + wc;

    const int nk = Kd >> 4;

    #pragma unroll
    for (int st = 0; st < 3; st++) {
        if (st < nk) {
            CP16(smaddr(&APL(st, ar, ac)),     Abase + st*16);
            CP16(smaddr(&APL(st, ar, ac + 4)), Abase + st*16 + 4);
            CP16(smaddr(&WPL(st, wr, wc)),     Wbase + (size_t)st*16*ldw);
        }
        CPCOMMIT();
    }

    float c[2][4][4] = {};

    for (int kt = 0; kt < nk; kt++) {
        CPWAIT2();
        __syncthreads();

        if (kt + 3 < nk) {
            const int st = (kt + 3) & 3;
            CP16(smaddr(&APL(st, ar, ac)),     Abase + (kt+3)*16);
            CP16(smaddr(&APL(st, ar, ac + 4)), Abase + (kt+3)*16 + 4);
            CP16(smaddr(&WPL(st, wr, wc)),     Wbase + (size_t)(kt+3)*16*ldw);
        }
        CPCOMMIT();

        const int cur = kt & 3;
        #pragma unroll
        for (int ks = 0; ks < 2; ks++) {
            unsigned af[2][4], bf[4][2];
            #pragma unroll
            for (int mt = 0; mt < 2; mt++) {
                const int row = mb + mt*16 + g;
                af[mt][0] = tf32_bits(APL(cur, row,     ks*8 + r4    ));
                af[mt][1] = tf32_bits(APL(cur, row + 8, ks*8 + r4    ));
                af[mt][2] = tf32_bits(APL(cur, row,     ks*8 + r4 + 4));
                af[mt][3] = tf32_bits(APL(cur, row + 8, ks*8 + r4 + 4));
            }
            #pragma unroll
            for (int nt = 0; nt < 4; nt++) {
                const int col = nb + nt*8 + g;
                bf[nt][0] = tf32_bits(WPL(cur, ks*8 + r4,     col));
                bf[nt][1] = tf32_bits(WPL(cur, ks*8 + r4 + 4, col));
            }
            #pragma unroll
            for (int mt = 0; mt < 2; mt++)
                #pragma unroll
                for (int nt = 0; nt < 4; nt++)
                    mma_tf32(c[mt][nt], af[mt], bf[nt][0], bf[nt][1]);
        }
    }

    // headsplit epilogue, tf32-rounded outputs (matches gemm_tc exactly)
    #pragma unroll
    for (int nt = 0; nt < 4; nt++) {
        const int col0 = n0 + nb + nt*8 + 2*r4;
        const float2 bb = *(const float2*)&bias[col0];
        #pragma unroll
        for (int mt = 0; mt < 2; mt++) {
            const int row0 = m0 + mb + mt*16 + g;
            float2 v0 = make_float2(tf32_of(c[mt][nt][0] + bb.x), tf32_of(c[mt][nt][1] + bb.y));
            float2 v1 = make_float2(tf32_of(c[mt][nt][2] + bb.x), tf32_of(c[mt][nt][3] + bb.y));
            const int h = col0 >> 5, d = col0 & 31;
            int b = row0 >> 9, n = row0 & 511;
            *(float2*)&C[(((size_t)(b*Hh + h))*Nseq + n)*DKd + d] = v0;
            b = (row0+8) >> 9; n = (row0+8) & 511;
            *(float2*)&C[(((size_t)(b*Hh + h))*Nseq + n)*DKd + d] = v1;
        }
    }
#undef APL
#undef WPL
}

// ---------------- bias fold ----------------------------------------------------
__global__ __launch_bounds__(256) void bias_fold(
    const float* __restrict__ bo, const float* __restrict__ Ws1,
    const float* __restrict__ bs1, float* __restrict__ bfull)
{
    __shared__ float red[16][16];
    const int nl = threadIdx.x & 15;
    const int rg = threadIdx.x >> 4;
    const int n  = blockIdx.x * 16 + nl;
    float s = 0.f;
    for (int r = rg; r < 3*Edim; r += 16)
        s = fmaf(bo[r & (Edim-1)], Ws1[(size_t)r * Edim + n], s);
    red[rg][nl] = s;
    __syncthreads();
    if (rg == 0) {
        float t = 0.f;
        #pragma unroll
        for (int k = 0; k < 16; k++) t += red[k][nl];
        bfull[n] = bs1[n] + t;
    }
}

// ---------------- tf32 mma attention: cp.async double-buffered -----------------
#define ATTN_SMEM 49664

__global__ __launch_bounds__(256, 2) void attn_mma(
    const float* __restrict__ Q, const float* __restrict__ K, const float* __restrict__ V,
    const float* __restrict__ convp, float* __restrict__ xcat)
{
    extern __shared__ float sm[];
    float (*Qs)[36] = (float(*)[36])(sm);
    float* KsB  = sm + 2304;
    float* VsB  = sm + 6912;
    float* dump = sm;
    float* lsA  = sm + 12032;
    float* lsB  = sm + 12224;
#define KS(buf,row,col) KsB[(buf)*2304 + (row)*36 + (col)]
#define VS(buf,row,col) VsB[(buf)*2560 + (row)*40 + (col)]

    const int qt = blockIdx.x;
    const int bh = blockIdx.y;
    const int b = bh >> 3, h = bh & 7;
    const int q0 = qt << 6;
    const int tid = threadIdx.x;
    const int warp = tid >> 5, lane = tid & 31;
    const int g = lane >> 2, r4 = lane & 3;
    const int wg = warp >> 2;
    const int mwarp = warp & 3;
    const int mrow = mwarp << 4;
    const int keybase = wg << 5;

    const size_t headbase = (size_t)bh * Nseq * DKd;
    const float* Kb = K + headbase;
    const float* Vb = V + headbase;

    const int srow0 = tid >> 3, sc4 = (tid & 7) << 2;
    const int srow1 = srow0 + 32;
    const int pr0 = (srow0 & ~7) | (((srow0 & 3) << 1) | ((srow0 >> 2) & 1));
    const int pr1 = (srow1 & ~7) | (((srow1 & 3) << 1) | ((srow1 >> 2) & 1));

    const float* Qb = Q + headbase + (size_t)q0 * DKd;
    #pragma unroll
    for (int i = 0; i < 2; i++) {
        int idx = tid + i*256;
        int row = idx >> 3, c4 = (idx & 7) << 2;
        *(float4*)&Qs[row][c4] = *(const float4*)&Qb[row*32 + c4];
    }

    {
        CP16(smaddr(&KS(0, pr0, sc4)),  Kb + srow0*32 + sc4);
        CP16(smaddr(&KS(0, pr1, sc4)),  Kb + srow1*32 + sc4);
        CP16(smaddr(&VS(0, srow0, sc4)), Vb + srow0*32 + sc4);
        CP16(smaddr(&VS(0, srow1, sc4)), Vb + srow1*32 + sc4);
        CPCOMMIT();
    }
    CPWAIT0();
    __syncthreads();

    unsigned qa[4][4];
    #pragma unroll
    for (int ks = 0; ks < 4; ks++) {
        qa[ks][0] = __float_as_uint(Qs[mrow + g    ][ks*8 + r4    ]);
        qa[ks][1] = __float_as_uint(Qs[mrow + g + 8][ks*8 + r4    ]);
        qa[ks][2] = __float_as_uint(Qs[mrow + g    ][ks*8 + r4 + 4]);
        qa[ks][3] = __float_as_uint(Qs[mrow + g + 8][ks*8 + r4 + 4]);
    }

    float o[3][4][4] = {};
    float lsum[3][2] = {};

    const float* cbase = convp + ((size_t)bh * Nseq + q0 + mrow) * Nseq;

    for (int kt = 0; kt < 8; kt++) {
        const int cur = kt & 1;
        const int k0 = kt << 6;

        if (kt < 7) {
            const int nk0 = (kt + 1) << 6;
            const float* Kn = Kb + (size_t)nk0 * DKd;
            const float* Vn = Vb + (size_t)nk0 * DKd;
            const int nxt = cur ^ 1;
            CP16(smaddr(&KS(nxt, pr0, sc4)),  Kn + srow0*32 + sc4);
            CP16(smaddr(&KS(nxt, pr1, sc4)),  Kn + srow1*32 + sc4);
            CP16(smaddr(&VS(nxt, srow0, sc4)), Vn + srow0*32 + sc4);
            CP16(smaddr(&VS(nxt, srow1, sc4)), Vn + srow1*32 + sc4);
            CPCOMMIT();
        }

        float2 cc[4][2];
        #pragma unroll
        for (int nt = 0; nt < 4; nt++)
            #pragma unroll
            for (int rr = 0; rr < 2; rr++)
                cc[nt][rr] = *(const float2*)&cbase[(size_t)(g + rr*8) * Nseq
                                                    + k0 + keybase + nt*8 + 2*r4];

        float s[4][4] = {};
        #pragma unroll
        for (int ks = 0; ks < 4; ks++) {
            #pragma unroll
            for (int nt = 0; nt < 4; nt++) {
                unsigned b0 = __float_as_uint(KS(cur, keybase + nt*8 + g, ks*8 + r4    ));
                unsigned b1 = __float_as_uint(KS(cur, keybase + nt*8 + g, ks*8 + r4 + 4));
                mma_tf32(s[nt], qa[ks], b0, b1);
            }
        }

        #pragma unroll
        for (int nt = 0; nt < 4; nt++) {
            const float2 cR0 = cc[nt][0];
            const float2 cR1 = cc[nt][1];
            unsigned m0 = __float_as_uint(cR0.x) & 3u;
            unsigned m1 = __float_as_uint(cR0.y) & 3u;
            unsigned m2 = __float_as_uint(cR1.x) & 3u;
            unsigned m3 = __float_as_uint(cR1.y) & 3u;
            float e0 = fexp(s[nt][0] * cR0.x);
            float e1 = fexp(s[nt][1] * cR0.y);
            float e2 = fexp(s[nt][2] * cR1.x);
            float e3 = fexp(s[nt][3] * cR1.y);
            e0 = (m0 == 3u) ? 0.f : e0;
            e1 = (m1 == 3u) ? 0.f : e1;
            e2 = (m2 == 3u) ? 0.f : e2;
            e3 = (m3 == 3u) ? 0.f : e3;
            float b10 = (m0 < 2u) ? e0 : 0.f;
            float b11 = (m1 < 2u) ? e1 : 0.f;
            float b12 = (m2 < 2u) ? e2 : 0.f;
            float b13 = (m3 < 2u) ? e3 : 0.f;
            float b00 = (m0 == 0u) ? e0 : 0.f;
            float b01 = (m1 == 0u) ? e1 : 0.f;
            float b02 = (m2 == 0u) ? e2 : 0.f;
            float b03 = (m3 == 0u) ? e3 : 0.f;
            lsum[2][0] += e0 + e1;   lsum[2][1] += e2 + e3;
            lsum[1][0] += b10 + b11; lsum[1][1] += b12 + b13;
            lsum[0][0] += b00 + b01; lsum[0][1] += b02 + b03;
            unsigned a2[4] = {__float_as_uint(e0),  __float_as_uint(e2),
                              __float_as_uint(e1),  __float_as_uint(e3)};
            unsigned a1[4] = {__float_as_uint(b10), __float_as_uint(b12),
                              __float_as_uint(b11), __float_as_uint(b13)};
            unsigned a0[4] = {__float_as_uint(b00), __float_as_uint(b02),
                              __float_as_uint(b01), __float_as_uint(b03)};
            const int kk = keybase + nt*8;
            #pragma unroll
            for (int dnt = 0; dnt < 4; dnt++) {
                unsigned vb0 = __float_as_uint(VS(cur, kk + r4,     dnt*8 + g));
                unsigned vb1 = __float_as_uint(VS(cur, kk + r4 + 4, dnt*8 + g));
                mma_tf32(o[2][dnt], a2, vb0, vb1);
                mma_tf32(o[1][dnt], a1, vb0, vb1);
                mma_tf32(o[0][dnt], a0, vb0, vb1);
            }
        }

        if (kt < 7) {
            CPWAIT0();
            __syncthreads();
        }
    }

    __syncthreads();
    float* lsX = wg ? lsB : lsA;
    #pragma unroll
    for (int bar = 0; bar < 3; bar++)
        #pragma unroll
        for (int rr = 0; rr < 2; rr++) {
            float v = lsum[bar][rr];
            v += __shfl_xor_sync(0xffffffffu, v, 1);
            v += __shfl_xor_sync(0xffffffffu, v, 2);
            if (r4 == 0) lsX[bar*64 + mrow + g + rr*8] = v;
        }

    if (wg == 1) {
        const int idx = tid - 128;
        #pragma unroll
        for (int bar = 0; bar < 3; bar++)
            #pragma unroll
            for (int nt = 0; nt < 4; nt++)
                *(float4*)&dump[(idx*12 + bar*4 + nt)*4] =
                    make_float4(o[bar][nt][0], o[bar][nt][1], o[bar][nt][2], o[bar][nt][3]);
    }
    __syncthreads();

    if (wg == 0) {
        const int idx = tid;
        const int rowA = q0 + mrow + g;
        const int rowB = rowA + 8;
        #pragma unroll
        for (int bar = 0; bar < 3; bar++) {
            const float rlA = 1.f / (lsA[bar*64 + mrow + g    ] + lsB[bar*64 + mrow + g    ]);
            const float rlB = 1.f / (lsA[bar*64 + mrow + g + 8] + lsB[bar*64 + mrow + g + 8]);
            #pragma unroll
            for (int nt = 0; nt < 4; nt++) {
                float4 p = *(const float4*)&dump[(idx*12 + bar*4 + nt)*4];
                const int col = bar*Edim + h*DKd + nt*8 + 2*r4;
                size_t baseA = ((size_t)b*Nseq + rowA) * (3*Edim) + col;
                size_t baseB = ((size_t)b*Nseq + rowB) * (3*Edim) + col;
                *(float2*)&xcat[baseA] = make_float2(tf32_of((o[bar][nt][0] + p.x)*rlA),
                                                     tf32_of((o[bar][nt][1] + p.y)*rlA));
                *(float2*)&xcat[baseB] = make_float2(tf32_of((o[bar][nt][2] + p.z)*rlB),
                                                     tf32_of((o[bar][nt][3] + p.w)*rlB));
            }
        }
    }
#undef KS
#undef VS
}

// ---------------- host launcher: forked streams --------------------------------
extern "C" void kernel_launch(void* const* d_in, const int* in_sizes, int n_in,
                              void* d_out, int out_size)
{
    const float* query = (const float*)d_in[0];
    const float* key   = (const float*)d_in[1];
    const float* value = (const float*)d_in[2];
    const float* dist  = (const float*)d_in[3];
    const int*   mask  = (const int*)d_in[4];
    const float* Wq = (const float*)d_in[5];
    const float* bq = (const float*)d_in[6];
    const float* Wk = (const float*)d_in[7];
    const float* bk = (const float*)d_in[8];
    const float* Wv = (const float*)d_in[9];
    const float* bv = (const float*)d_in[10];
    const float* Wo = (const float*)d_in[11];
    const float* bo = (const float*)d_in[12];
    const float* cw1 = (const float*)d_in[13];
    const float* cb1 = (const float*)d_in[14];
    const float* cw2 = (const float*)d_in[15];
    const float* cb2 = (const float*)d_in[16];
    const float* Ws1 = (const float*)d_in[17];
    const float* bs1 = (const float*)d_in[18];
    const float* Ws2 = (const float*)d_in[19];
    const float* bs2 = (const float*)d_in[20];
    float* out = (float*)d_out;

    float *q_p, *k_p, *v_p, *x_p, *h1_p, *wcat_p, *ws2r_p, *bfull_p, *zero_p, *conv_p;
    float *tA_p, *tB_p;
    cudaGetSymbolAddress((void**)&q_p,    g_q);
    cudaGetSymbolAddress((void**)&k_p,    g_k);
    cudaGetSymbolAddress((void**)&v_p,    g_v);
    cudaGetSymbolAddress((void**)&x_p,    g_x);
    cudaGetSymbolAddress((void**)&h1_p,   g_h1);
    cudaGetSymbolAddress((void**)&wcat_p, g_wcat);
    cudaGetSymbolAddress((void**)&ws2r_p, g_ws2r);
    cudaGetSymbolAddress((void**)&bfull_p,g_bfull);
    cudaGetSymbolAddress((void**)&zero_p, g_zero);
    cudaGetSymbolAddress((void**)&conv_p, g_conv);
    cudaGetSymbolAddress((void**)&tA_p,   g_tblA);
    cudaGetSymbolAddress((void**)&tB_p,   g_tblB);

    static cudaStream_t sB = nullptr, sC = nullptr;
    static cudaEvent_t evRoot = nullptr, evB = nullptr, evC = nullptr;
    if (sB == nullptr) {
        cudaStreamCreateWithFlags(&sB, cudaStreamNonBlocking);
        cudaStreamCreateWithFlags(&sC, cudaStreamNonBlocking);
        cudaEventCreateWithFlags(&evRoot, cudaEventDisableTiming);
        cudaEventCreateWithFlags(&evB,   cudaEventDisableTiming);
        cudaEventCreateWithFlags(&evC,   cudaEventDisableTiming);
        cudaFuncSetAttribute(attn_mma,
                             cudaFuncAttributeMaxDynamicSharedMemorySize, ATTN_SMEM);
        cudaFuncSetAttribute(gemm_pl,
                             cudaFuncAttributeMaxDynamicSharedMemorySize, GPL_SMEM);
        cudaFuncSetAttribute(gemm_plc,
                             cudaFuncAttributeMaxDynamicSharedMemorySize, GPL_SMEM);
    }

    const int M = Bq * Nseq;          // 4096
    dim3 blk(256);

    // ---- fork ----
    cudaEventRecord(evRoot, 0);
    cudaStreamWaitEvent(sB, evRoot, 0);
    cudaStreamWaitEvent(sC, evRoot, 0);

    // stream B: conv precompute (inputs only)
    tbl_kernel<<<1, 256, 0, sB>>>(cw1, cb1, cw2, cb2, tA_p, tB_p);
    conv_kernel<<<Bq * Nseq / 4, blk, 0, sB>>>(dist, mask, tA_p, tB_p, conv_p);
    cudaEventRecord(evB, sB);

    // stream C: Wcat (rounded), folded bias, rounded Ws2 (weights only)
    {
        dim3 grid(Edim / 128, Edim / 64, 3);
        gemm_tc<<<grid, blk, 0, sC>>>(Wo, Wo, Wo,
                               Ws1, Ws1 + Edim*Edim, Ws1 + 2*Edim*Edim,
                               zero_p, zero_p, zero_p,
                               wcat_p, wcat_p + Edim*Edim, wcat_p + 2*Edim*Edim,
                               Edim, Edim, Edim, 0, 0, 1);
        bias_fold<<<Edim / 16, 256, 0, sC>>>(bo, Ws1, bs1, bfull_p);
        round_tf32<<<64, 256, 0, sC>>>(Ws2, ws2r_p, Edim * Edim);
    }
    cudaEventRecord(evC, sC);

    // default: QKV projections, 4-stage pipelined, cvt at consume
    {
        dim3 grid(M / 128, Edim / 64, 3);
        gemm_plc<<<grid, blk, GPL_SMEM>>>(query, key, value,
                                          Wq, Wk, Wv,
                                          bq, bk, bv,
                                          q_p, k_p, v_p,
                                          Edim, Edim);
    }

    cudaStreamWaitEvent(0, evB, 0);
    {
        dim3 grid(Nseq / 64, Bq * Hh);
        attn_mma<<<grid, 256, ATTN_SMEM>>>(q_p, k_p, v_p, conv_p, x_p);
    }

    cudaStreamWaitEvent(0, evC, 0);
    // h1 = relu(xcat @ Wcat + bfull), output rounded for the next stage
    {
        dim3 grid(M / 128, Edim / 64);
        gemm_pl<<<grid, blk, GPL_SMEM>>>(x_p, wcat_p, bfull_p, h1_p,
                                         3*Edim, Edim, Edim, 1, 1);
    }
    // out = h1 @ Ws2r + bs2
    {
        dim3 grid(M / 128, Edim / 64);
        gemm_pl<<<grid, blk, GPL_SMEM>>>(h1_p, ws2r_p, bs2, out,
                                         Edim, Edim, Edim, 0, 0);
    }
}